// round 1
// baseline (speedup 1.0000x reference)
#include <cuda_runtime.h>
#include <math.h>

#define HIDDEN   2048
#define HEADS    16
#define HEAD_DIM 128
#define KV_RANK  256
#define ATTN_DIM 2048
#define BATCH    2
#define SEQ      2048
#define M_ROWS   (BATCH * SEQ)   // 4096

// ---------------- scratch (device globals; allocation-free) ----------------
__device__ float g_q  [M_ROWS * ATTN_DIM];       // 32 MB  [b,l,h,d]
__device__ float g_lat[M_ROWS * KV_RANK];        //  4 MB
__device__ float g_kv [M_ROWS * 2 * ATTN_DIM];   // 64 MB  [b,l, (k|v) h,d]
__device__ float g_ao [M_ROWS * ATTN_DIM];       // 32 MB  [b,l,h,d]

// ---------------- generic 128x128x8 fp32 GEMM: C = A(MxK) @ B(KxN) ---------
// A row-major [M,K], B row-major [K,N], all dims multiples of 128/8.
__global__ __launch_bounds__(256) void gemm_kernel(
    const float* __restrict__ A, const float* __restrict__ Bw,
    float* __restrict__ C, int M, int N, int K)
{
    __shared__ float As[8][128];   // k-major
    __shared__ float Bs[8][128];

    const int tid = threadIdx.x;
    const int bm = blockIdx.y * 128;
    const int bn = blockIdx.x * 128;
    const int ty = tid >> 4;       // 0..15
    const int tx = tid & 15;       // 0..15

    const int a_row = tid >> 1;          // 0..127
    const int a_col = (tid & 1) * 4;     // 0 or 4
    const int b_row = tid >> 5;          // 0..7
    const int b_col = (tid & 31) * 4;    // 0..124

    float acc[8][8];
#pragma unroll
    for (int i = 0; i < 8; i++)
#pragma unroll
        for (int j = 0; j < 8; j++) acc[i][j] = 0.f;

    for (int k0 = 0; k0 < K; k0 += 8) {
        float4 av = *(const float4*)&A[(size_t)(bm + a_row) * K + k0 + a_col];
        float4 bv = *(const float4*)&Bw[(size_t)(k0 + b_row) * N + bn + b_col];
        As[a_col + 0][a_row] = av.x;
        As[a_col + 1][a_row] = av.y;
        As[a_col + 2][a_row] = av.z;
        As[a_col + 3][a_row] = av.w;
        *(float4*)&Bs[b_row][b_col] = bv;
        __syncthreads();

#pragma unroll
        for (int kk = 0; kk < 8; kk++) {
            float4 a0 = *(const float4*)&As[kk][ty * 8];
            float4 a1 = *(const float4*)&As[kk][ty * 8 + 4];
            float4 b0 = *(const float4*)&Bs[kk][tx * 8];
            float4 b1 = *(const float4*)&Bs[kk][tx * 8 + 4];
            float a[8] = {a0.x, a0.y, a0.z, a0.w, a1.x, a1.y, a1.z, a1.w};
            float b[8] = {b0.x, b0.y, b0.z, b0.w, b1.x, b1.y, b1.z, b1.w};
#pragma unroll
            for (int i = 0; i < 8; i++)
#pragma unroll
                for (int j = 0; j < 8; j++) acc[i][j] += a[i] * b[j];
        }
        __syncthreads();
    }

#pragma unroll
    for (int i = 0; i < 8; i++) {
        float* crow = &C[(size_t)(bm + ty * 8 + i) * N + bn + tx * 8];
#pragma unroll
        for (int j = 0; j < 8; j += 4) {
            *(float4*)&crow[j] = make_float4(acc[i][j], acc[i][j + 1],
                                             acc[i][j + 2], acc[i][j + 3]);
        }
    }
}

// ---------------- RMSNorm over last dim (256), in place --------------------
__global__ __launch_bounds__(256) void rmsnorm_kernel(
    float* __restrict__ lat, const float* __restrict__ w)
{
    const int row = blockIdx.x;
    const int tid = threadIdx.x;   // 256 == KV_RANK
    float v = lat[(size_t)row * KV_RANK + tid];

    float ss = v * v;
#pragma unroll
    for (int o = 16; o; o >>= 1) ss += __shfl_xor_sync(0xffffffffu, ss, o);
    __shared__ float red[8];
    if ((tid & 31) == 0) red[tid >> 5] = ss;
    __syncthreads();
    float tot = red[0] + red[1] + red[2] + red[3] +
                red[4] + red[5] + red[6] + red[7];
    float r = rsqrtf(tot * (1.0f / KV_RANK) + 1e-6f);
    lat[(size_t)row * KV_RANK + tid] = w[tid] * v * r;
}

// ---------------- causal flash attention, 64x64 tiles, D=128 ---------------
// Q from g_q [b,l,h,d]; K/V packed in g_kv [b,l, 4096] with k at h*128, v at 2048+h*128.
// Output -> g_ao [b,l,h,d].
__global__ __launch_bounds__(256) void attn_kernel(
    const float* __restrict__ Qg, const float* __restrict__ KVg,
    float* __restrict__ Og)
{
    extern __shared__ float sm[];
    float* sQ  = sm;                  // 64 x 128
    float* sKT = sQ + 64 * 128;       // 128 x 64 (d-major)
    float* sV  = sKT + 128 * 64;      // 64 x 128
    float* sP  = sV + 64 * 128;       // 64 x 64

    const int tid = threadIdx.x;
    const int ty = tid >> 4;          // 0..15 -> 4 query rows each
    const int tx = tid & 15;          // 0..15 -> 4 score cols / 8 out cols
    const int qb = blockIdx.x;        // 0..31
    const int h  = blockIdx.y;
    const int b  = blockIdx.z;
    const int q0 = qb * 64;

    const float scale = 0.08838834764831845f;  // 1/sqrt(128)

    // load Q tile (coalesced float4)
    for (int i = tid; i < 64 * 32; i += 256) {
        int r = i >> 5, c4 = (i & 31) << 2;
        float4 v = *(const float4*)&Qg[(size_t)(b * SEQ + q0 + r) * ATTN_DIM + h * HEAD_DIM + c4];
        *(float4*)&sQ[r * 128 + c4] = v;
    }

    float m_i[4], l_i[4], acc[4][8];
#pragma unroll
    for (int i = 0; i < 4; i++) {
        m_i[i] = -1e30f; l_i[i] = 0.f;
#pragma unroll
        for (int j = 0; j < 8; j++) acc[i][j] = 0.f;
    }

    const int ntiles = qb + 1;
    for (int kt = 0; kt < ntiles; kt++) {
        const int k0 = kt * 64;
        __syncthreads();   // smem reuse fence (also covers first-iter Q load)

        // load K (transposed to d-major) and V
        for (int i = tid; i < 64 * 32; i += 256) {
            int r = i >> 5, c4 = (i & 31) << 2;
            const float* base = &KVg[(size_t)(b * SEQ + k0 + r) * (2 * ATTN_DIM) + h * HEAD_DIM];
            float4 kvv = *(const float4*)&base[c4];
            sKT[(c4 + 0) * 64 + r] = kvv.x;
            sKT[(c4 + 1) * 64 + r] = kvv.y;
            sKT[(c4 + 2) * 64 + r] = kvv.z;
            sKT[(c4 + 3) * 64 + r] = kvv.w;
            float4 vv = *(const float4*)&base[ATTN_DIM + c4];
            *(float4*)&sV[r * 128 + c4] = vv;
        }
        __syncthreads();

        // S = Q K^T (4x4 per thread)
        float s[4][4];
#pragma unroll
        for (int i = 0; i < 4; i++)
#pragma unroll
            for (int j = 0; j < 4; j++) s[i][j] = 0.f;

#pragma unroll 4
        for (int d = 0; d < 128; d++) {
            float4 bv = *(const float4*)&sKT[d * 64 + tx * 4];
            float a0 = sQ[(ty * 4 + 0) * 128 + d];
            float a1 = sQ[(ty * 4 + 1) * 128 + d];
            float a2 = sQ[(ty * 4 + 2) * 128 + d];
            float a3 = sQ[(ty * 4 + 3) * 128 + d];
            s[0][0] += a0 * bv.x; s[0][1] += a0 * bv.y; s[0][2] += a0 * bv.z; s[0][3] += a0 * bv.w;
            s[1][0] += a1 * bv.x; s[1][1] += a1 * bv.y; s[1][2] += a1 * bv.z; s[1][3] += a1 * bv.w;
            s[2][0] += a2 * bv.x; s[2][1] += a2 * bv.y; s[2][2] += a2 * bv.z; s[2][3] += a2 * bv.w;
            s[3][0] += a3 * bv.x; s[3][1] += a3 * bv.y; s[3][2] += a3 * bv.z; s[3][3] += a3 * bv.w;
        }

        // mask + online softmax
#pragma unroll
        for (int i = 0; i < 4; i++) {
            const int qi = q0 + ty * 4 + i;
#pragma unroll
            for (int j = 0; j < 4; j++) {
                const int kj = k0 + tx * 4 + j;
                s[i][j] = (kj <= qi) ? s[i][j] * scale : -1e30f;
            }
            float mx = fmaxf(fmaxf(s[i][0], s[i][1]), fmaxf(s[i][2], s[i][3]));
#pragma unroll
            for (int o = 8; o; o >>= 1) mx = fmaxf(mx, __shfl_xor_sync(0xffffffffu, mx, o));
            const float m_new = fmaxf(m_i[i], mx);
            float p0 = __expf(s[i][0] - m_new);
            float p1 = __expf(s[i][1] - m_new);
            float p2 = __expf(s[i][2] - m_new);
            float p3 = __expf(s[i][3] - m_new);
            float rs = p0 + p1 + p2 + p3;
#pragma unroll
            for (int o = 8; o; o >>= 1) rs += __shfl_xor_sync(0xffffffffu, rs, o);
            const float corr = __expf(m_i[i] - m_new);
            l_i[i] = l_i[i] * corr + rs;
            m_i[i] = m_new;
#pragma unroll
            for (int j = 0; j < 8; j++) acc[i][j] *= corr;
            float* prow = &sP[(ty * 4 + i) * 64 + tx * 4];
            prow[0] = p0; prow[1] = p1; prow[2] = p2; prow[3] = p3;
        }
        __syncthreads();

        // acc += P @ V
#pragma unroll 2
        for (int j = 0; j < 64; j++) {
            float p0 = sP[(ty * 4 + 0) * 64 + j];
            float p1 = sP[(ty * 4 + 1) * 64 + j];
            float p2 = sP[(ty * 4 + 2) * 64 + j];
            float p3 = sP[(ty * 4 + 3) * 64 + j];
            float4 v0 = *(const float4*)&sV[j * 128 + tx * 8];
            float4 v1 = *(const float4*)&sV[j * 128 + tx * 8 + 4];
            float vv[8] = {v0.x, v0.y, v0.z, v0.w, v1.x, v1.y, v1.z, v1.w};
#pragma unroll
            for (int c = 0; c < 8; c++) {
                acc[0][c] += p0 * vv[c];
                acc[1][c] += p1 * vv[c];
                acc[2][c] += p2 * vv[c];
                acc[3][c] += p3 * vv[c];
            }
        }
    }

    // epilogue
#pragma unroll
    for (int i = 0; i < 4; i++) {
        const float inv = 1.0f / l_i[i];
        const int row = q0 + ty * 4 + i;
        float* dst = &Og[(size_t)(b * SEQ + row) * ATTN_DIM + h * HEAD_DIM + tx * 8];
        *(float4*)&dst[0] = make_float4(acc[i][0] * inv, acc[i][1] * inv,
                                        acc[i][2] * inv, acc[i][3] * inv);
        *(float4*)&dst[4] = make_float4(acc[i][4] * inv, acc[i][5] * inv,
                                        acc[i][6] * inv, acc[i][7] * inv);
    }
}

// ---------------------------------------------------------------------------
extern "C" void kernel_launch(void* const* d_in, const int* in_sizes, int n_in,
                              void* d_out, int out_size)
{
    const float* x     = (const float*)d_in[0];
    const float* Wq    = (const float*)d_in[1];
    const float* Wkvd  = (const float*)d_in[2];
    const float* knw   = (const float*)d_in[3];
    const float* Wkvu  = (const float*)d_in[4];
    const float* Wo    = (const float*)d_in[5];
    float* out = (float*)d_out;

    float *q, *lat, *kv, *ao;
    cudaGetSymbolAddress((void**)&q,   g_q);
    cudaGetSymbolAddress((void**)&lat, g_lat);
    cudaGetSymbolAddress((void**)&kv,  g_kv);
    cudaGetSymbolAddress((void**)&ao,  g_ao);

    const int attn_smem = (64 * 128 + 128 * 64 + 64 * 128 + 64 * 64) * (int)sizeof(float); // 114688
    cudaFuncSetAttribute(attn_kernel, cudaFuncAttributeMaxDynamicSharedMemorySize, attn_smem);

    dim3 blk(256);

    // 1) q = x @ Wq   [4096,2048]x[2048,2048]
    gemm_kernel<<<dim3(ATTN_DIM / 128, M_ROWS / 128), blk>>>(x, Wq, q, M_ROWS, ATTN_DIM, HIDDEN);

    // 2) lat = x @ Wkv_down   [4096,2048]x[2048,256]
    gemm_kernel<<<dim3(KV_RANK / 128, M_ROWS / 128), blk>>>(x, Wkvd, lat, M_ROWS, KV_RANK, HIDDEN);

    // 3) rmsnorm(lat) in place
    rmsnorm_kernel<<<M_ROWS, KV_RANK>>>(lat, knw);

    // 4) kv = lat @ Wkv_up   [4096,256]x[256,4096]
    gemm_kernel<<<dim3(2 * ATTN_DIM / 128, M_ROWS / 128), blk>>>(lat, Wkvu, kv, M_ROWS, 2 * ATTN_DIM, KV_RANK);

    // 5) causal attention per (qtile, head, batch)
    attn_kernel<<<dim3(SEQ / 64, HEADS, BATCH), blk, attn_smem>>>(q, kv, ao);

    // 6) out = ao @ Wo   [4096,2048]x[2048,2048]
    gemm_kernel<<<dim3(HIDDEN / 128, M_ROWS / 128), blk>>>(ao, Wo, out, M_ROWS, HIDDEN, ATTN_DIM);
}

// round 5
// speedup vs baseline: 1.4640x; 1.4640x over previous
#include <cuda_runtime.h>
#include <cuda_bf16.h>
#include <cstdint>
#include <math.h>

#define HIDDEN   2048
#define HEADS    16
#define HEAD_DIM 128
#define KV_RANK  256
#define ATTN_DIM 2048
#define BATCH    2
#define SEQ      2048
#define M_ROWS   (BATCH * SEQ)   // 4096

// ---------------- scratch (device globals; allocation-free) ----------------
__device__ float g_q  [M_ROWS * ATTN_DIM];
__device__ float g_lat[M_ROWS * KV_RANK];
__device__ float g_kv [M_ROWS * 2 * ATTN_DIM];
__device__ float g_ao [M_ROWS * ATTN_DIM];

// bf16 split buffers (hi/lo)
__device__ __nv_bfloat16 g_xh [M_ROWS * HIDDEN],   g_xl [M_ROWS * HIDDEN];
__device__ __nv_bfloat16 g_lath[M_ROWS * KV_RANK], g_latl[M_ROWS * KV_RANK];
__device__ __nv_bfloat16 g_aoh[M_ROWS * ATTN_DIM], g_aol[M_ROWS * ATTN_DIM];
// weights transposed to [N,K] K-major
__device__ __nv_bfloat16 g_WqTh [ATTN_DIM * HIDDEN],     g_WqTl [ATTN_DIM * HIDDEN];
__device__ __nv_bfloat16 g_WkdTh[KV_RANK * HIDDEN],      g_WkdTl[KV_RANK * HIDDEN];
__device__ __nv_bfloat16 g_WkuTh[2 * ATTN_DIM * KV_RANK],g_WkuTl[2 * ATTN_DIM * KV_RANK];
__device__ __nv_bfloat16 g_WoTh [HIDDEN * ATTN_DIM],     g_WoTl [HIDDEN * ATTN_DIM];

// ======================= PTX helpers (baseline ISA, no 'a' features) =======
__device__ __forceinline__ uint32_t smem_u32(const void* p) {
    uint32_t a;
    asm("{ .reg .u64 t; cvta.to.shared.u64 t, %1; cvt.u32.u64 %0, t; }" : "=r"(a) : "l"(p));
    return a;
}
#define CP_ASYNC16(dst, src) \
    asm volatile("cp.async.cg.shared.global [%0], [%1], 16;" :: "r"(dst), "l"(src) : "memory")
#define CP_COMMIT() asm volatile("cp.async.commit_group;" ::: "memory")
#define CP_WAIT(n)  asm volatile("cp.async.wait_group %0;" :: "n"(n) : "memory")

__device__ __forceinline__ void mma16816(float* c, const uint32_t* a, const uint32_t* b) {
    asm volatile("mma.sync.aligned.m16n8k16.row.col.f32.bf16.bf16.f32 "
        "{%0,%1,%2,%3}, {%4,%5,%6,%7}, {%8,%9}, {%0,%1,%2,%3};"
        : "+f"(c[0]), "+f"(c[1]), "+f"(c[2]), "+f"(c[3])
        : "r"(a[0]), "r"(a[1]), "r"(a[2]), "r"(a[3]), "r"(b[0]), "r"(b[1]));
}

// ======================= conversion kernels ================================
__global__ __launch_bounds__(256) void conv_act(const float4* __restrict__ in,
                                                __nv_bfloat16* __restrict__ h,
                                                __nv_bfloat16* __restrict__ l, int n4)
{
    int i = blockIdx.x * blockDim.x + threadIdx.x;
    if (i >= n4) return;
    float4 x = in[i];
    __nv_bfloat162 h0 = __floats2bfloat162_rn(x.x, x.y);
    __nv_bfloat162 h1 = __floats2bfloat162_rn(x.z, x.w);
    __nv_bfloat162 l0 = __floats2bfloat162_rn(x.x - __bfloat162float(h0.x),
                                              x.y - __bfloat162float(h0.y));
    __nv_bfloat162 l1 = __floats2bfloat162_rn(x.z - __bfloat162float(h1.x),
                                              x.w - __bfloat162float(h1.y));
    ((__nv_bfloat162*)h)[i * 2 + 0] = h0;
    ((__nv_bfloat162*)h)[i * 2 + 1] = h1;
    ((__nv_bfloat162*)l)[i * 2 + 0] = l0;
    ((__nv_bfloat162*)l)[i * 2 + 1] = l1;
}

// W [K,N] fp32 -> T hi/lo [N,K] bf16 (K-major)
__global__ __launch_bounds__(256) void conv_wt_T(const float* __restrict__ W,
                                                 __nv_bfloat16* __restrict__ Th,
                                                 __nv_bfloat16* __restrict__ Tl,
                                                 int K, int N)
{
    __shared__ float t[32][33];
    const int n0 = blockIdx.x * 32, k0 = blockIdx.y * 32;
    const int tid = threadIdx.x;
    for (int i = tid; i < 1024; i += 256) {
        int kk = i >> 5, nn = i & 31;
        t[kk][nn] = W[(size_t)(k0 + kk) * N + n0 + nn];
    }
    __syncthreads();
    for (int i = tid; i < 512; i += 256) {
        int nn = i >> 4, kp = (i & 15) * 2;
        float a = t[kp][nn], b = t[kp + 1][nn];
        __nv_bfloat162 h = __floats2bfloat162_rn(a, b);
        __nv_bfloat162 lo = __floats2bfloat162_rn(a - __bfloat162float(h.x),
                                                  b - __bfloat162float(h.y));
        *(__nv_bfloat162*)&Th[(size_t)(n0 + nn) * K + k0 + kp] = h;
        *(__nv_bfloat162*)&Tl[(size_t)(n0 + nn) * K + k0 + kp] = lo;
    }
}

// ======================= mma.sync bf16 GEMM ================================
// C[M,N] fp32 = A[M,K] @ B[N,K]^T, 3-term hi/lo split.
// CTA tile 128x128, BK=32, double-buffered cp.async.
// smem stage layout (stride 80B/row, 128 rows per matrix = 10240B):
//   Ah @0, Al @10240, Bh @20480, Bl @30720; stage size 40960; 2 stages.
#define GEMM_SMEM (2 * 40960)
__global__ __launch_bounds__(256, 1) void gemm_mma(
    const __nv_bfloat16* __restrict__ Ah, const __nv_bfloat16* __restrict__ Al,
    const __nv_bfloat16* __restrict__ Bh, const __nv_bfloat16* __restrict__ Bl,
    float* __restrict__ C, int M, int N, int K)
{
    extern __shared__ char smem[];
    const uint32_t sbase = smem_u32(smem);
    const int tid  = threadIdx.x;
    const int lane = tid & 31;
    const int w    = tid >> 5;
    const int bm = blockIdx.y * 128;
    const int bn = blockIdx.x * 128;
    const int wm = (w & 3) * 32;          // warp m offset (4 warps in m)
    const int wn = (w >> 2) * 64;         // warp n offset (2 warps in n)
    const int qr = lane >> 2;             // 0..7
    const int qc = lane & 3;              // 0..3

    const __nv_bfloat16* srcs[4] = { Ah, Al, Bh, Bl };
    const int rowoff[4] = { bm, bm, bn, bn };

    float acc[2][8][4];
#pragma unroll
    for (int mf = 0; mf < 2; ++mf)
#pragma unroll
        for (int nf = 0; nf < 8; ++nf)
#pragma unroll
            for (int e = 0; e < 4; ++e) acc[mf][nf][e] = 0.f;

    const int NC = K >> 5;

    // ---- async load of one K-chunk into stage (c&1) ----
    auto issue = [&](int c) {
        const uint32_t st = sbase + (c & 1) * 40960;
        const int k0 = c << 5;
#pragma unroll
        for (int i = 0; i < 8; ++i) {
            const int mat = i >> 1;
            const int sub = ((i & 1) << 8) + tid;   // 0..511
            const int r = sub >> 2, v = sub & 3;
            const void* g = srcs[mat] + (size_t)(rowoff[mat] + r) * K + k0 + v * 8;
            CP_ASYNC16(st + mat * 10240 + r * 80 + v * 16, g);
        }
        CP_COMMIT();
    };

    issue(0);

    for (int c = 0; c < NC; ++c) {
        if (c + 1 < NC) { issue(c + 1); CP_WAIT(1); }
        else            { CP_WAIT(0); }
        __syncthreads();

        const char* base = smem + (c & 1) * 40960;
        const char* pAh = base;
        const char* pAl = base + 10240;
        const char* pBh = base + 20480;
        const char* pBl = base + 30720;

#pragma unroll
        for (int ks = 0; ks < 2; ++ks) {
            const int cK = ((ks << 4) + qc * 2) * 2;   // byte offset of k within row
            uint32_t ah[2][4], al[2][4], bh[8][2], bl[8][2];
#pragma unroll
            for (int mf = 0; mf < 2; ++mf) {
                const int r = wm + mf * 16 + qr;
                ah[mf][0] = *(const uint32_t*)(pAh + r * 80 + cK);
                ah[mf][1] = *(const uint32_t*)(pAh + (r + 8) * 80 + cK);
                ah[mf][2] = *(const uint32_t*)(pAh + r * 80 + cK + 16);
                ah[mf][3] = *(const uint32_t*)(pAh + (r + 8) * 80 + cK + 16);
                al[mf][0] = *(const uint32_t*)(pAl + r * 80 + cK);
                al[mf][1] = *(const uint32_t*)(pAl + (r + 8) * 80 + cK);
                al[mf][2] = *(const uint32_t*)(pAl + r * 80 + cK + 16);
                al[mf][3] = *(const uint32_t*)(pAl + (r + 8) * 80 + cK + 16);
            }
#pragma unroll
            for (int nf = 0; nf < 8; ++nf) {
                const int n = wn + nf * 8 + qr;
                bh[nf][0] = *(const uint32_t*)(pBh + n * 80 + cK);
                bh[nf][1] = *(const uint32_t*)(pBh + n * 80 + cK + 16);
                bl[nf][0] = *(const uint32_t*)(pBl + n * 80 + cK);
                bl[nf][1] = *(const uint32_t*)(pBl + n * 80 + cK + 16);
            }
#pragma unroll
            for (int mf = 0; mf < 2; ++mf)
#pragma unroll
                for (int nf = 0; nf < 8; ++nf) {
                    mma16816(acc[mf][nf], ah[mf], bh[nf]);
                    mma16816(acc[mf][nf], ah[mf], bl[nf]);
                    mma16816(acc[mf][nf], al[mf], bh[nf]);
                }
        }
        __syncthreads();
    }

    // ---- epilogue ----
#pragma unroll
    for (int mf = 0; mf < 2; ++mf) {
        const int r0 = bm + wm + mf * 16 + qr;
#pragma unroll
        for (int nf = 0; nf < 8; ++nf) {
            const int col = bn + wn + nf * 8 + qc * 2;
            *(float2*)&C[(size_t)r0 * N + col] =
                make_float2(acc[mf][nf][0], acc[mf][nf][1]);
            *(float2*)&C[(size_t)(r0 + 8) * N + col] =
                make_float2(acc[mf][nf][2], acc[mf][nf][3]);
        }
    }
}

// ---------------- RMSNorm over last dim (256), in place --------------------
__global__ __launch_bounds__(256) void rmsnorm_kernel(
    float* __restrict__ lat, const float* __restrict__ w)
{
    const int row = blockIdx.x;
    const int tid = threadIdx.x;
    float v = lat[(size_t)row * KV_RANK + tid];
    float ss = v * v;
#pragma unroll
    for (int o = 16; o; o >>= 1) ss += __shfl_xor_sync(0xffffffffu, ss, o);
    __shared__ float red[8];
    if ((tid & 31) == 0) red[tid >> 5] = ss;
    __syncthreads();
    float tot = red[0] + red[1] + red[2] + red[3] + red[4] + red[5] + red[6] + red[7];
    float r = rsqrtf(tot * (1.0f / KV_RANK) + 1e-6f);
    lat[(size_t)row * KV_RANK + tid] = w[tid] * v * r;
}

// ---------------- causal flash attention, 64x64 tiles, D=128 ---------------
__global__ __launch_bounds__(256) void attn_kernel(
    const float* __restrict__ Qg, const float* __restrict__ KVg,
    float* __restrict__ Og)
{
    extern __shared__ float sm[];
    float* sQ  = sm;
    float* sKT = sQ + 64 * 128;
    float* sV  = sKT + 128 * 64;
    float* sP  = sV + 64 * 128;

    const int tid = threadIdx.x;
    const int ty = tid >> 4;
    const int tx = tid & 15;
    const int qb = blockIdx.x;
    const int h  = blockIdx.y;
    const int b  = blockIdx.z;
    const int q0 = qb * 64;
    const float scale = 0.08838834764831845f;

    for (int i = tid; i < 64 * 32; i += 256) {
        int r = i >> 5, c4 = (i & 31) << 2;
        float4 v = *(const float4*)&Qg[(size_t)(b * SEQ + q0 + r) * ATTN_DIM + h * HEAD_DIM + c4];
        *(float4*)&sQ[r * 128 + c4] = v;
    }

    float m_i[4], l_i[4], acc[4][8];
#pragma unroll
    for (int i = 0; i < 4; i++) {
        m_i[i] = -1e30f; l_i[i] = 0.f;
#pragma unroll
        for (int j = 0; j < 8; j++) acc[i][j] = 0.f;
    }

    const int ntiles = qb + 1;
    for (int kt = 0; kt < ntiles; kt++) {
        const int k0 = kt * 64;
        __syncthreads();
        for (int i = tid; i < 64 * 32; i += 256) {
            int r = i >> 5, c4 = (i & 31) << 2;
            const float* base = &KVg[(size_t)(b * SEQ + k0 + r) * (2 * ATTN_DIM) + h * HEAD_DIM];
            float4 kvv = *(const float4*)&base[c4];
            sKT[(c4 + 0) * 64 + r] = kvv.x;
            sKT[(c4 + 1) * 64 + r] = kvv.y;
            sKT[(c4 + 2) * 64 + r] = kvv.z;
            sKT[(c4 + 3) * 64 + r] = kvv.w;
            float4 vv = *(const float4*)&base[ATTN_DIM + c4];
            *(float4*)&sV[r * 128 + c4] = vv;
        }
        __syncthreads();

        float s[4][4];
#pragma unroll
        for (int i = 0; i < 4; i++)
#pragma unroll
            for (int j = 0; j < 4; j++) s[i][j] = 0.f;

#pragma unroll 4
        for (int d = 0; d < 128; d++) {
            float4 bv = *(const float4*)&sKT[d * 64 + tx * 4];
            float a0 = sQ[(ty * 4 + 0) * 128 + d];
            float a1 = sQ[(ty * 4 + 1) * 128 + d];
            float a2 = sQ[(ty * 4 + 2) * 128 + d];
            float a3 = sQ[(ty * 4 + 3) * 128 + d];
            s[0][0] += a0 * bv.x; s[0][1] += a0 * bv.y; s[0][2] += a0 * bv.z; s[0][3] += a0 * bv.w;
            s[1][0] += a1 * bv.x; s[1][1] += a1 * bv.y; s[1][2] += a1 * bv.z; s[1][3] += a1 * bv.w;
            s[2][0] += a2 * bv.x; s[2][1] += a2 * bv.y; s[2][2] += a2 * bv.z; s[2][3] += a2 * bv.w;
            s[3][0] += a3 * bv.x; s[3][1] += a3 * bv.y; s[3][2] += a3 * bv.z; s[3][3] += a3 * bv.w;
        }

#pragma unroll
        for (int i = 0; i < 4; i++) {
            const int qi = q0 + ty * 4 + i;
#pragma unroll
            for (int j = 0; j < 4; j++) {
                const int kj = k0 + tx * 4 + j;
                s[i][j] = (kj <= qi) ? s[i][j] * scale : -1e30f;
            }
            float mx = fmaxf(fmaxf(s[i][0], s[i][1]), fmaxf(s[i][2], s[i][3]));
#pragma unroll
            for (int o = 8; o; o >>= 1) mx = fmaxf(mx, __shfl_xor_sync(0xffffffffu, mx, o));
            const float m_new = fmaxf(m_i[i], mx);
            float p0 = __expf(s[i][0] - m_new);
            float p1 = __expf(s[i][1] - m_new);
            float p2 = __expf(s[i][2] - m_new);
            float p3 = __expf(s[i][3] - m_new);
            float rs = p0 + p1 + p2 + p3;
#pragma unroll
            for (int o = 8; o; o >>= 1) rs += __shfl_xor_sync(0xffffffffu, rs, o);
            const float corr = __expf(m_i[i] - m_new);
            l_i[i] = l_i[i] * corr + rs;
            m_i[i] = m_new;
#pragma unroll
            for (int j = 0; j < 8; j++) acc[i][j] *= corr;
            float* prow = &sP[(ty * 4 + i) * 64 + tx * 4];
            prow[0] = p0; prow[1] = p1; prow[2] = p2; prow[3] = p3;
        }
        __syncthreads();

#pragma unroll 2
        for (int j = 0; j < 64; j++) {
            float p0 = sP[(ty * 4 + 0) * 64 + j];
            float p1 = sP[(ty * 4 + 1) * 64 + j];
            float p2 = sP[(ty * 4 + 2) * 64 + j];
            float p3 = sP[(ty * 4 + 3) * 64 + j];
            float4 v0 = *(const float4*)&sV[j * 128 + tx * 8];
            float4 v1 = *(const float4*)&sV[j * 128 + tx * 8 + 4];
            float vv[8] = {v0.x, v0.y, v0.z, v0.w, v1.x, v1.y, v1.z, v1.w};
#pragma unroll
            for (int c = 0; c < 8; c++) {
                acc[0][c] += p0 * vv[c];
                acc[1][c] += p1 * vv[c];
                acc[2][c] += p2 * vv[c];
                acc[3][c] += p3 * vv[c];
            }
        }
    }

#pragma unroll
    for (int i = 0; i < 4; i++) {
        const float inv = 1.0f / l_i[i];
        const int row = q0 + ty * 4 + i;
        float* dst = &Og[(size_t)(b * SEQ + row) * ATTN_DIM + h * HEAD_DIM + tx * 8];
        *(float4*)&dst[0] = make_float4(acc[i][0] * inv, acc[i][1] * inv,
                                        acc[i][2] * inv, acc[i][3] * inv);
        *(float4*)&dst[4] = make_float4(acc[i][4] * inv, acc[i][5] * inv,
                                        acc[i][6] * inv, acc[i][7] * inv);
    }
}

// ---------------------------------------------------------------------------
extern "C" void kernel_launch(void* const* d_in, const int* in_sizes, int n_in,
                              void* d_out, int out_size)
{
    const float* x    = (const float*)d_in[0];
    const float* Wq   = (const float*)d_in[1];
    const float* Wkvd = (const float*)d_in[2];
    const float* knw  = (const float*)d_in[3];
    const float* Wkvu = (const float*)d_in[4];
    const float* Wo   = (const float*)d_in[5];
    float* out = (float*)d_out;

    float *q, *lat, *kv, *ao;
    cudaGetSymbolAddress((void**)&q,   g_q);
    cudaGetSymbolAddress((void**)&lat, g_lat);
    cudaGetSymbolAddress((void**)&kv,  g_kv);
    cudaGetSymbolAddress((void**)&ao,  g_ao);
    __nv_bfloat16 *xh,*xl,*lath,*latl,*aoh,*aol;
    __nv_bfloat16 *WqTh,*WqTl,*WkdTh,*WkdTl,*WkuTh,*WkuTl,*WoTh,*WoTl;
    cudaGetSymbolAddress((void**)&xh, g_xh);     cudaGetSymbolAddress((void**)&xl, g_xl);
    cudaGetSymbolAddress((void**)&lath, g_lath); cudaGetSymbolAddress((void**)&latl, g_latl);
    cudaGetSymbolAddress((void**)&aoh, g_aoh);   cudaGetSymbolAddress((void**)&aol, g_aol);
    cudaGetSymbolAddress((void**)&WqTh, g_WqTh); cudaGetSymbolAddress((void**)&WqTl, g_WqTl);
    cudaGetSymbolAddress((void**)&WkdTh, g_WkdTh); cudaGetSymbolAddress((void**)&WkdTl, g_WkdTl);
    cudaGetSymbolAddress((void**)&WkuTh, g_WkuTh); cudaGetSymbolAddress((void**)&WkuTl, g_WkuTl);
    cudaGetSymbolAddress((void**)&WoTh, g_WoTh); cudaGetSymbolAddress((void**)&WoTl, g_WoTl);

    const int attn_smem = (64 * 128 + 128 * 64 + 64 * 128 + 64 * 64) * (int)sizeof(float);
    cudaFuncSetAttribute(attn_kernel, cudaFuncAttributeMaxDynamicSharedMemorySize, attn_smem);
    cudaFuncSetAttribute(gemm_mma, cudaFuncAttributeMaxDynamicSharedMemorySize, GEMM_SMEM);

    // weight conversions (transpose to [N,K] bf16 hi/lo)
    conv_wt_T<<<dim3(ATTN_DIM / 32, HIDDEN / 32), 256>>>(Wq,   WqTh,  WqTl,  HIDDEN, ATTN_DIM);
    conv_wt_T<<<dim3(KV_RANK / 32, HIDDEN / 32), 256>>>(Wkvd, WkdTh, WkdTl, HIDDEN, KV_RANK);
    conv_wt_T<<<dim3(2 * ATTN_DIM / 32, KV_RANK / 32), 256>>>(Wkvu, WkuTh, WkuTl, KV_RANK, 2 * ATTN_DIM);
    conv_wt_T<<<dim3(HIDDEN / 32, ATTN_DIM / 32), 256>>>(Wo,   WoTh,  WoTl,  ATTN_DIM, HIDDEN);

    // x -> bf16 hi/lo
    {
        int n4 = M_ROWS * HIDDEN / 4;
        conv_act<<<(n4 + 255) / 256, 256>>>((const float4*)x, xh, xl, n4);
    }

    // q = x @ Wq
    gemm_mma<<<dim3(ATTN_DIM / 128, M_ROWS / 128), 256, GEMM_SMEM>>>(
        xh, xl, WqTh, WqTl, q, M_ROWS, ATTN_DIM, HIDDEN);
    // lat = x @ Wkv_down
    gemm_mma<<<dim3(KV_RANK / 128, M_ROWS / 128), 256, GEMM_SMEM>>>(
        xh, xl, WkdTh, WkdTl, lat, M_ROWS, KV_RANK, HIDDEN);
    // rmsnorm in place
    rmsnorm_kernel<<<M_ROWS, KV_RANK>>>(lat, knw);
    // lat -> bf16 hi/lo
    {
        int n4 = M_ROWS * KV_RANK / 4;
        conv_act<<<(n4 + 255) / 256, 256>>>((const float4*)lat, lath, latl, n4);
    }
    // kv = lat @ Wkv_up
    gemm_mma<<<dim3(2 * ATTN_DIM / 128, M_ROWS / 128), 256, GEMM_SMEM>>>(
        lath, latl, WkuTh, WkuTl, kv, M_ROWS, 2 * ATTN_DIM, KV_RANK);
    // attention
    attn_kernel<<<dim3(SEQ / 64, HEADS, BATCH), 256, attn_smem>>>(q, kv, ao);
    // ao -> bf16 hi/lo
    {
        int n4 = M_ROWS * ATTN_DIM / 4;
        conv_act<<<(n4 + 255) / 256, 256>>>((const float4*)ao, aoh, aol, n4);
    }
    // out = ao @ Wo
    gemm_mma<<<dim3(HIDDEN / 128, M_ROWS / 128), 256, GEMM_SMEM>>>(
        aoh, aol, WoTh, WoTl, out, M_ROWS, HIDDEN, ATTN_DIM);
}

// round 6
// speedup vs baseline: 1.9426x; 1.3270x over previous
#include <cuda_runtime.h>
#include <cuda_bf16.h>
#include <cstdint>
#include <math.h>

#define HIDDEN   2048
#define HEADS    16
#define HEAD_DIM 128
#define KV_RANK  256
#define ATTN_DIM 2048
#define BATCH    2
#define SEQ      2048
#define M_ROWS   (BATCH * SEQ)   // 4096

// ---------------- scratch (device globals; allocation-free) ----------------
__device__ float g_q  [M_ROWS * ATTN_DIM];
__device__ float g_lat[M_ROWS * KV_RANK];
__device__ float g_kv [M_ROWS * 2 * ATTN_DIM];
__device__ float g_ao [M_ROWS * ATTN_DIM];

// bf16 split buffers (hi/lo)
__device__ __nv_bfloat16 g_xh [M_ROWS * HIDDEN],   g_xl [M_ROWS * HIDDEN];
__device__ __nv_bfloat16 g_lath[M_ROWS * KV_RANK], g_latl[M_ROWS * KV_RANK];
__device__ __nv_bfloat16 g_aoh[M_ROWS * ATTN_DIM], g_aol[M_ROWS * ATTN_DIM];
// attention operands
__device__ __nv_bfloat16 g_qh [M_ROWS * ATTN_DIM], g_ql [M_ROWS * ATTN_DIM];
__device__ __nv_bfloat16 g_kh [M_ROWS * ATTN_DIM], g_kl [M_ROWS * ATTN_DIM];
__device__ __nv_bfloat16 g_vth[BATCH * HEADS * HEAD_DIM * SEQ];
__device__ __nv_bfloat16 g_vtl[BATCH * HEADS * HEAD_DIM * SEQ];
// weights transposed to [N,K] K-major
__device__ __nv_bfloat16 g_WqTh [ATTN_DIM * HIDDEN],     g_WqTl [ATTN_DIM * HIDDEN];
__device__ __nv_bfloat16 g_WkdTh[KV_RANK * HIDDEN],      g_WkdTl[KV_RANK * HIDDEN];
__device__ __nv_bfloat16 g_WkuTh[2 * ATTN_DIM * KV_RANK],g_WkuTl[2 * ATTN_DIM * KV_RANK];
__device__ __nv_bfloat16 g_WoTh [HIDDEN * ATTN_DIM],     g_WoTl [HIDDEN * ATTN_DIM];

// ======================= PTX helpers (baseline ISA) ========================
__device__ __forceinline__ uint32_t smem_u32(const void* p) {
    uint32_t a;
    asm("{ .reg .u64 t; cvta.to.shared.u64 t, %1; cvt.u32.u64 %0, t; }" : "=r"(a) : "l"(p));
    return a;
}
#define CP_ASYNC16(dst, src) \
    asm volatile("cp.async.cg.shared.global [%0], [%1], 16;" :: "r"(dst), "l"(src) : "memory")
#define CP_COMMIT() asm volatile("cp.async.commit_group;" ::: "memory")
#define CP_WAIT(n)  asm volatile("cp.async.wait_group %0;" :: "n"(n) : "memory")

__device__ __forceinline__ void mma16816(float* c, const uint32_t* a, const uint32_t* b) {
    asm volatile("mma.sync.aligned.m16n8k16.row.col.f32.bf16.bf16.f32 "
        "{%0,%1,%2,%3}, {%4,%5,%6,%7}, {%8,%9}, {%0,%1,%2,%3};"
        : "+f"(c[0]), "+f"(c[1]), "+f"(c[2]), "+f"(c[3])
        : "r"(a[0]), "r"(a[1]), "r"(a[2]), "r"(a[3]), "r"(b[0]), "r"(b[1]));
}
__device__ __forceinline__ uint32_t pack_bf2(float a, float b) {
    __nv_bfloat162 t = __floats2bfloat162_rn(a, b);
    return *(uint32_t*)&t;
}

// ======================= conversion kernels ================================
__global__ __launch_bounds__(256) void conv_act(const float4* __restrict__ in,
                                                __nv_bfloat16* __restrict__ h,
                                                __nv_bfloat16* __restrict__ l, int n4)
{
    int i = blockIdx.x * blockDim.x + threadIdx.x;
    if (i >= n4) return;
    float4 x = in[i];
    __nv_bfloat162 h0 = __floats2bfloat162_rn(x.x, x.y);
    __nv_bfloat162 h1 = __floats2bfloat162_rn(x.z, x.w);
    __nv_bfloat162 l0 = __floats2bfloat162_rn(x.x - __bfloat162float(h0.x),
                                              x.y - __bfloat162float(h0.y));
    __nv_bfloat162 l1 = __floats2bfloat162_rn(x.z - __bfloat162float(h1.x),
                                              x.w - __bfloat162float(h1.y));
    ((__nv_bfloat162*)h)[i * 2 + 0] = h0;
    ((__nv_bfloat162*)h)[i * 2 + 1] = h1;
    ((__nv_bfloat162*)l)[i * 2 + 0] = l0;
    ((__nv_bfloat162*)l)[i * 2 + 1] = l1;
}

// K half of g_kv (first 2048 cols of 4096-col rows) -> compact bf16 hi/lo
__global__ __launch_bounds__(256) void conv_k(const float* __restrict__ KV,
                                              __nv_bfloat16* __restrict__ h,
                                              __nv_bfloat16* __restrict__ l)
{
    int i = blockIdx.x * blockDim.x + threadIdx.x;   // over 4096*512
    if (i >= M_ROWS * 512) return;
    int row = i >> 9, c = (i & 511) * 4;
    float4 x = *(const float4*)&KV[(size_t)row * 4096 + c];
    __nv_bfloat162 h0 = __floats2bfloat162_rn(x.x, x.y);
    __nv_bfloat162 h1 = __floats2bfloat162_rn(x.z, x.w);
    __nv_bfloat162 l0 = __floats2bfloat162_rn(x.x - __bfloat162float(h0.x),
                                              x.y - __bfloat162float(h0.y));
    __nv_bfloat162 l1 = __floats2bfloat162_rn(x.z - __bfloat162float(h1.x),
                                              x.w - __bfloat162float(h1.y));
    size_t o = (size_t)row * 2048 + c;
    *(__nv_bfloat162*)&h[o]     = h0;
    *(__nv_bfloat162*)&h[o + 2] = h1;
    *(__nv_bfloat162*)&l[o]     = l0;
    *(__nv_bfloat162*)&l[o + 2] = l1;
}

// V half of g_kv -> transposed bf16 hi/lo: VT[(b*2048 + h*128 + d) * 2048 + s]
__global__ __launch_bounds__(256) void conv_vt(const float* __restrict__ KV,
                                               __nv_bfloat16* __restrict__ Th,
                                               __nv_bfloat16* __restrict__ Tl)
{
    __shared__ float t[32][33];
    const int s0  = blockIdx.x * 32;
    const int hd0 = blockIdx.y * 32;
    const int b   = blockIdx.z;
    const int tid = threadIdx.x;
    for (int i = tid; i < 1024; i += 256) {
        int ss = i >> 5, dd = i & 31;
        t[ss][dd] = KV[(size_t)(b * SEQ + s0 + ss) * 4096 + 2048 + hd0 + dd];
    }
    __syncthreads();
    for (int i = tid; i < 512; i += 256) {
        int dd = i >> 4, sp = (i & 15) * 2;
        float a = t[sp][dd], c = t[sp + 1][dd];
        __nv_bfloat162 hh = __floats2bfloat162_rn(a, c);
        __nv_bfloat162 ll = __floats2bfloat162_rn(a - __bfloat162float(hh.x),
                                                  c - __bfloat162float(hh.y));
        size_t o = (size_t)(b * 2048 + hd0 + dd) * 2048 + s0 + sp;
        *(__nv_bfloat162*)&Th[o] = hh;
        *(__nv_bfloat162*)&Tl[o] = ll;
    }
}

// W [K,N] fp32 -> T hi/lo [N,K] bf16 (K-major)
__global__ __launch_bounds__(256) void conv_wt_T(const float* __restrict__ W,
                                                 __nv_bfloat16* __restrict__ Th,
                                                 __nv_bfloat16* __restrict__ Tl,
                                                 int K, int N)
{
    __shared__ float t[32][33];
    const int n0 = blockIdx.x * 32, k0 = blockIdx.y * 32;
    const int tid = threadIdx.x;
    for (int i = tid; i < 1024; i += 256) {
        int kk = i >> 5, nn = i & 31;
        t[kk][nn] = W[(size_t)(k0 + kk) * N + n0 + nn];
    }
    __syncthreads();
    for (int i = tid; i < 512; i += 256) {
        int nn = i >> 4, kp = (i & 15) * 2;
        float a = t[kp][nn], b = t[kp + 1][nn];
        __nv_bfloat162 h = __floats2bfloat162_rn(a, b);
        __nv_bfloat162 lo = __floats2bfloat162_rn(a - __bfloat162float(h.x),
                                                  b - __bfloat162float(h.y));
        *(__nv_bfloat162*)&Th[(size_t)(n0 + nn) * K + k0 + kp] = h;
        *(__nv_bfloat162*)&Tl[(size_t)(n0 + nn) * K + k0 + kp] = lo;
    }
}

// ======================= mma.sync bf16 GEMM (unchanged) ====================
#define GEMM_SMEM (2 * 40960)
__global__ __launch_bounds__(256, 1) void gemm_mma(
    const __nv_bfloat16* __restrict__ Ah, const __nv_bfloat16* __restrict__ Al,
    const __nv_bfloat16* __restrict__ Bh, const __nv_bfloat16* __restrict__ Bl,
    float* __restrict__ C, int M, int N, int K)
{
    extern __shared__ char smem[];
    const uint32_t sbase = smem_u32(smem);
    const int tid  = threadIdx.x;
    const int lane = tid & 31;
    const int w    = tid >> 5;
    const int bm = blockIdx.y * 128;
    const int bn = blockIdx.x * 128;
    const int wm = (w & 3) * 32;
    const int wn = (w >> 2) * 64;
    const int qr = lane >> 2;
    const int qc = lane & 3;

    const __nv_bfloat16* srcs[4] = { Ah, Al, Bh, Bl };
    const int rowoff[4] = { bm, bm, bn, bn };

    float acc[2][8][4];
#pragma unroll
    for (int mf = 0; mf < 2; ++mf)
#pragma unroll
        for (int nf = 0; nf < 8; ++nf)
#pragma unroll
            for (int e = 0; e < 4; ++e) acc[mf][nf][e] = 0.f;

    const int NC = K >> 5;

    auto issue = [&](int c) {
        const uint32_t st = sbase + (c & 1) * 40960;
        const int k0 = c << 5;
#pragma unroll
        for (int i = 0; i < 8; ++i) {
            const int mat = i >> 1;
            const int sub = ((i & 1) << 8) + tid;
            const int r = sub >> 2, v = sub & 3;
            const void* g = srcs[mat] + (size_t)(rowoff[mat] + r) * K + k0 + v * 8;
            CP_ASYNC16(st + mat * 10240 + r * 80 + v * 16, g);
        }
        CP_COMMIT();
    };

    issue(0);

    for (int c = 0; c < NC; ++c) {
        if (c + 1 < NC) { issue(c + 1); CP_WAIT(1); }
        else            { CP_WAIT(0); }
        __syncthreads();

        const char* base = smem + (c & 1) * 40960;
        const char* pAh = base;
        const char* pAl = base + 10240;
        const char* pBh = base + 20480;
        const char* pBl = base + 30720;

#pragma unroll
        for (int ks = 0; ks < 2; ++ks) {
            const int cK = ((ks << 4) + qc * 2) * 2;
            uint32_t ah[2][4], al[2][4], bh[8][2], bl[8][2];
#pragma unroll
            for (int mf = 0; mf < 2; ++mf) {
                const int r = wm + mf * 16 + qr;
                ah[mf][0] = *(const uint32_t*)(pAh + r * 80 + cK);
                ah[mf][1] = *(const uint32_t*)(pAh + (r + 8) * 80 + cK);
                ah[mf][2] = *(const uint32_t*)(pAh + r * 80 + cK + 16);
                ah[mf][3] = *(const uint32_t*)(pAh + (r + 8) * 80 + cK + 16);
                al[mf][0] = *(const uint32_t*)(pAl + r * 80 + cK);
                al[mf][1] = *(const uint32_t*)(pAl + (r + 8) * 80 + cK);
                al[mf][2] = *(const uint32_t*)(pAl + r * 80 + cK + 16);
                al[mf][3] = *(const uint32_t*)(pAl + (r + 8) * 80 + cK + 16);
            }
#pragma unroll
            for (int nf = 0; nf < 8; ++nf) {
                const int n = wn + nf * 8 + qr;
                bh[nf][0] = *(const uint32_t*)(pBh + n * 80 + cK);
                bh[nf][1] = *(const uint32_t*)(pBh + n * 80 + cK + 16);
                bl[nf][0] = *(const uint32_t*)(pBl + n * 80 + cK);
                bl[nf][1] = *(const uint32_t*)(pBl + n * 80 + cK + 16);
            }
#pragma unroll
            for (int mf = 0; mf < 2; ++mf)
#pragma unroll
                for (int nf = 0; nf < 8; ++nf) {
                    mma16816(acc[mf][nf], ah[mf], bh[nf]);
                    mma16816(acc[mf][nf], ah[mf], bl[nf]);
                    mma16816(acc[mf][nf], al[mf], bh[nf]);
                }
        }
        __syncthreads();
    }

#pragma unroll
    for (int mf = 0; mf < 2; ++mf) {
        const int r0 = bm + wm + mf * 16 + qr;
#pragma unroll
        for (int nf = 0; nf < 8; ++nf) {
            const int col = bn + wn + nf * 8 + qc * 2;
            *(float2*)&C[(size_t)r0 * N + col] =
                make_float2(acc[mf][nf][0], acc[mf][nf][1]);
            *(float2*)&C[(size_t)(r0 + 8) * N + col] =
                make_float2(acc[mf][nf][2], acc[mf][nf][3]);
        }
    }
}

// ---------------- RMSNorm over last dim (256), in place --------------------
__global__ __launch_bounds__(256) void rmsnorm_kernel(
    float* __restrict__ lat, const float* __restrict__ w)
{
    const int row = blockIdx.x;
    const int tid = threadIdx.x;
    float v = lat[(size_t)row * KV_RANK + tid];
    float ss = v * v;
#pragma unroll
    for (int o = 16; o; o >>= 1) ss += __shfl_xor_sync(0xffffffffu, ss, o);
    __shared__ float red[8];
    if ((tid & 31) == 0) red[tid >> 5] = ss;
    __syncthreads();
    float tot = red[0] + red[1] + red[2] + red[3] + red[4] + red[5] + red[6] + red[7];
    float r = rsqrtf(tot * (1.0f / KV_RANK) + 1e-6f);
    lat[(size_t)row * KV_RANK + tid] = w[tid] * v * r;
}

// ============ tensor-core flash attention (bf16 3-term splits) =============
// Q tile 128, K tile 64, 8 warps (warp w: q rows w*16..w*16+15, full n=64).
// smem: Qh@0 Ql@34816 (272B rows), 2 stages @69632/+71680:
//   {Kh(17408) Kl(17408) VTh(18432) VTl(18432)}; K rows 272B, VT rows 144B.
#define ATT_SMEM 212992
__global__ __launch_bounds__(256, 1) void attn_mma(
    const __nv_bfloat16* __restrict__ Qh, const __nv_bfloat16* __restrict__ Ql,
    const __nv_bfloat16* __restrict__ Kh, const __nv_bfloat16* __restrict__ Kl,
    const __nv_bfloat16* __restrict__ VTh, const __nv_bfloat16* __restrict__ VTl,
    float* __restrict__ Og)
{
    extern __shared__ char smA[];
    const uint32_t sb = smem_u32(smA);
    const int tid = threadIdx.x;
    const int w = tid >> 5, lane = tid & 31;
    const int qr = lane >> 2, qc = lane & 3;
    const int qb = blockIdx.x, h = blockIdx.y, b = blockIdx.z;
    const int q0 = qb * 128;
    const float scale = 0.08838834764831845f;

    const uint32_t oQl = 34816, oStage = 69632, stSz = 71680;

    // ---- Q tile load (hi/lo) ----
#pragma unroll
    for (int i = 0; i < 16; ++i) {
        int idx = tid + i * 256;
        int mat = idx >> 11, r = (idx >> 4) & 127, v = idx & 15;
        const __nv_bfloat16* g = (mat ? Ql : Qh) +
            (size_t)(b * SEQ + q0 + r) * 2048 + h * HEAD_DIM + v * 8;
        CP_ASYNC16(sb + (mat ? oQl : 0u) + r * 272 + v * 16, g);
    }
    CP_COMMIT();

    auto issue = [&](int kt) {
        const int k0 = kt * 64;
        const uint32_t st = sb + oStage + (kt & 1) * stSz;
#pragma unroll
        for (int i = 0; i < 8; ++i) {
            int idx = tid + i * 256;
            int mat = idx >> 10, r = (idx >> 4) & 63, v = idx & 15;
            const __nv_bfloat16* g = (mat ? Kl : Kh) +
                (size_t)(b * SEQ + k0 + r) * 2048 + h * HEAD_DIM + v * 8;
            CP_ASYNC16(st + mat * 17408 + r * 272 + v * 16, g);
        }
#pragma unroll
        for (int i = 0; i < 8; ++i) {
            int idx = tid + i * 256;
            int mat = idx >> 10, d = (idx >> 3) & 127, v = idx & 7;
            const __nv_bfloat16* g = (mat ? VTl : VTh) +
                (size_t)((b * HEADS + h) * HEAD_DIM + d) * 2048 + k0 + v * 8;
            CP_ASYNC16(st + 34816 + mat * 18432 + d * 144 + v * 16, g);
        }
        CP_COMMIT();
    };

    float m0 = -1e30f, m1 = -1e30f, l0 = 0.f, l1 = 0.f;
    float acc[16][4];
#pragma unroll
    for (int nt = 0; nt < 16; ++nt)
#pragma unroll
        for (int e = 0; e < 4; ++e) acc[nt][e] = 0.f;

    const int ntk = 2 * (qb + 1);
    issue(0);

    for (int kt = 0; kt < ntk; ++kt) {
        if (kt + 1 < ntk) { issue(kt + 1); CP_WAIT(1); }
        else              { CP_WAIT(0); }
        __syncthreads();

        const char* st  = smA + oStage + (kt & 1) * stSz;
        const char* pKh = st;
        const char* pKl = st + 17408;
        const char* pVh = st + 34816;
        const char* pVl = st + 34816 + 18432;
        const char* pQh = smA;
        const char* pQl = smA + oQl;

        // ---- S = Q K^T (3 terms) ----
        float sfr[8][4];
#pragma unroll
        for (int nt = 0; nt < 8; ++nt)
#pragma unroll
            for (int e = 0; e < 4; ++e) sfr[nt][e] = 0.f;

#pragma unroll
        for (int ks = 0; ks < 8; ++ks) {
            const int kb = ks * 32 + qc * 4;
            const int r = w * 16 + qr;
            uint32_t ah[4], al[4];
            ah[0] = *(const uint32_t*)(pQh + r * 272 + kb);
            ah[1] = *(const uint32_t*)(pQh + (r + 8) * 272 + kb);
            ah[2] = *(const uint32_t*)(pQh + r * 272 + kb + 16);
            ah[3] = *(const uint32_t*)(pQh + (r + 8) * 272 + kb + 16);
            al[0] = *(const uint32_t*)(pQl + r * 272 + kb);
            al[1] = *(const uint32_t*)(pQl + (r + 8) * 272 + kb);
            al[2] = *(const uint32_t*)(pQl + r * 272 + kb + 16);
            al[3] = *(const uint32_t*)(pQl + (r + 8) * 272 + kb + 16);
#pragma unroll
            for (int nt = 0; nt < 8; ++nt) {
                const int n = nt * 8 + qr;
                uint32_t bh[2], bl[2];
                bh[0] = *(const uint32_t*)(pKh + n * 272 + kb);
                bh[1] = *(const uint32_t*)(pKh + n * 272 + kb + 16);
                bl[0] = *(const uint32_t*)(pKl + n * 272 + kb);
                bl[1] = *(const uint32_t*)(pKl + n * 272 + kb + 16);
                mma16816(sfr[nt], ah, bh);
                mma16816(sfr[nt], ah, bl);
                mma16816(sfr[nt], al, bh);
            }
        }

        // ---- mask + online softmax ----
        const int i0 = q0 + w * 16 + qr;
        const int i1 = i0 + 8;
        const int k0 = kt * 64;
#pragma unroll
        for (int nt = 0; nt < 8; ++nt) {
            const int j = k0 + nt * 8 + 2 * qc;
            sfr[nt][0] = (j     <= i0) ? sfr[nt][0] * scale : -1e30f;
            sfr[nt][1] = (j + 1 <= i0) ? sfr[nt][1] * scale : -1e30f;
            sfr[nt][2] = (j     <= i1) ? sfr[nt][2] * scale : -1e30f;
            sfr[nt][3] = (j + 1 <= i1) ? sfr[nt][3] * scale : -1e30f;
        }
        float mx0 = -1e30f, mx1 = -1e30f;
#pragma unroll
        for (int nt = 0; nt < 8; ++nt) {
            mx0 = fmaxf(mx0, fmaxf(sfr[nt][0], sfr[nt][1]));
            mx1 = fmaxf(mx1, fmaxf(sfr[nt][2], sfr[nt][3]));
        }
        mx0 = fmaxf(mx0, __shfl_xor_sync(0xffffffffu, mx0, 1));
        mx0 = fmaxf(mx0, __shfl_xor_sync(0xffffffffu, mx0, 2));
        mx1 = fmaxf(mx1, __shfl_xor_sync(0xffffffffu, mx1, 1));
        mx1 = fmaxf(mx1, __shfl_xor_sync(0xffffffffu, mx1, 2));
        const float mn0 = fmaxf(m0, mx0), mn1 = fmaxf(m1, mx1);
        const float c0 = __expf(m0 - mn0), c1 = __expf(m1 - mn1);
        m0 = mn0; m1 = mn1;
        l0 *= c0;  l1 *= c1;

        uint32_t pa[4][4], pl[4][4];
        float rs0 = 0.f, rs1 = 0.f;
#pragma unroll
        for (int nt = 0; nt < 8; ++nt) {
            float p0 = __expf(sfr[nt][0] - mn0);
            float p1 = __expf(sfr[nt][1] - mn0);
            float p2 = __expf(sfr[nt][2] - mn1);
            float p3 = __expf(sfr[nt][3] - mn1);
            rs0 += p0 + p1; rs1 += p2 + p3;
            uint32_t h01 = pack_bf2(p0, p1);
            uint32_t h23 = pack_bf2(p2, p3);
            __nv_bfloat162 hb01 = *(__nv_bfloat162*)&h01;
            __nv_bfloat162 hb23 = *(__nv_bfloat162*)&h23;
            uint32_t r01 = pack_bf2(p0 - __bfloat162float(hb01.x),
                                    p1 - __bfloat162float(hb01.y));
            uint32_t r23 = pack_bf2(p2 - __bfloat162float(hb23.x),
                                    p3 - __bfloat162float(hb23.y));
            const int ks = nt >> 1, half = nt & 1;
            if (half == 0) { pa[ks][0] = h01; pa[ks][1] = h23; pl[ks][0] = r01; pl[ks][1] = r23; }
            else           { pa[ks][2] = h01; pa[ks][3] = h23; pl[ks][2] = r01; pl[ks][3] = r23; }
        }
        rs0 += __shfl_xor_sync(0xffffffffu, rs0, 1);
        rs0 += __shfl_xor_sync(0xffffffffu, rs0, 2);
        rs1 += __shfl_xor_sync(0xffffffffu, rs1, 1);
        rs1 += __shfl_xor_sync(0xffffffffu, rs1, 2);
        l0 += rs0; l1 += rs1;

#pragma unroll
        for (int nt = 0; nt < 16; ++nt) {
            acc[nt][0] *= c0; acc[nt][1] *= c0;
            acc[nt][2] *= c1; acc[nt][3] *= c1;
        }

        // ---- O += P V (3 terms), B operand from VT (d-rows, s-major) ----
#pragma unroll
        for (int ks = 0; ks < 4; ++ks) {
            const int kb = ks * 32 + qc * 4;
#pragma unroll
            for (int nt = 0; nt < 16; ++nt) {
                const int d = nt * 8 + qr;
                uint32_t bh[2], bl[2];
                bh[0] = *(const uint32_t*)(pVh + d * 144 + kb);
                bh[1] = *(const uint32_t*)(pVh + d * 144 + kb + 16);
                bl[0] = *(const uint32_t*)(pVl + d * 144 + kb);
                bl[1] = *(const uint32_t*)(pVl + d * 144 + kb + 16);
                mma16816(acc[nt], pa[ks], bh);
                mma16816(acc[nt], pa[ks], bl);
                mma16816(acc[nt], pl[ks], bh);
            }
        }
        __syncthreads();
    }

    // ---- epilogue ----
    const float inv0 = 1.0f / l0, inv1 = 1.0f / l1;
    const size_t r0 = (size_t)(b * SEQ + q0 + w * 16 + qr);
#pragma unroll
    for (int nt = 0; nt < 16; ++nt) {
        const int col = h * HEAD_DIM + nt * 8 + 2 * qc;
        *(float2*)&Og[r0 * 2048 + col] =
            make_float2(acc[nt][0] * inv0, acc[nt][1] * inv0);
        *(float2*)&Og[(r0 + 8) * 2048 + col] =
            make_float2(acc[nt][2] * inv1, acc[nt][3] * inv1);
    }
}

// ---------------------------------------------------------------------------
extern "C" void kernel_launch(void* const* d_in, const int* in_sizes, int n_in,
                              void* d_out, int out_size)
{
    const float* x    = (const float*)d_in[0];
    const float* Wq   = (const float*)d_in[1];
    const float* Wkvd = (const float*)d_in[2];
    const float* knw  = (const float*)d_in[3];
    const float* Wkvu = (const float*)d_in[4];
    const float* Wo   = (const float*)d_in[5];
    float* out = (float*)d_out;

    float *q, *lat, *kv, *ao;
    cudaGetSymbolAddress((void**)&q,   g_q);
    cudaGetSymbolAddress((void**)&lat, g_lat);
    cudaGetSymbolAddress((void**)&kv,  g_kv);
    cudaGetSymbolAddress((void**)&ao,  g_ao);
    __nv_bfloat16 *xh,*xl,*lath,*latl,*aoh,*aol,*qh,*ql,*kh,*kl,*vth,*vtl;
    __nv_bfloat16 *WqTh,*WqTl,*WkdTh,*WkdTl,*WkuTh,*WkuTl,*WoTh,*WoTl;
    cudaGetSymbolAddress((void**)&xh, g_xh);     cudaGetSymbolAddress((void**)&xl, g_xl);
    cudaGetSymbolAddress((void**)&lath, g_lath); cudaGetSymbolAddress((void**)&latl, g_latl);
    cudaGetSymbolAddress((void**)&aoh, g_aoh);   cudaGetSymbolAddress((void**)&aol, g_aol);
    cudaGetSymbolAddress((void**)&qh, g_qh);     cudaGetSymbolAddress((void**)&ql, g_ql);
    cudaGetSymbolAddress((void**)&kh, g_kh);     cudaGetSymbolAddress((void**)&kl, g_kl);
    cudaGetSymbolAddress((void**)&vth, g_vth);   cudaGetSymbolAddress((void**)&vtl, g_vtl);
    cudaGetSymbolAddress((void**)&WqTh, g_WqTh); cudaGetSymbolAddress((void**)&WqTl, g_WqTl);
    cudaGetSymbolAddress((void**)&WkdTh, g_WkdTh); cudaGetSymbolAddress((void**)&WkdTl, g_WkdTl);
    cudaGetSymbolAddress((void**)&WkuTh, g_WkuTh); cudaGetSymbolAddress((void**)&WkuTl, g_WkuTl);
    cudaGetSymbolAddress((void**)&WoTh, g_WoTh); cudaGetSymbolAddress((void**)&WoTl, g_WoTl);

    cudaFuncSetAttribute(gemm_mma, cudaFuncAttributeMaxDynamicSharedMemorySize, GEMM_SMEM);
    cudaFuncSetAttribute(attn_mma, cudaFuncAttributeMaxDynamicSharedMemorySize, ATT_SMEM);

    // weight conversions
    conv_wt_T<<<dim3(ATTN_DIM / 32, HIDDEN / 32), 256>>>(Wq,   WqTh,  WqTl,  HIDDEN, ATTN_DIM);
    conv_wt_T<<<dim3(KV_RANK / 32, HIDDEN / 32), 256>>>(Wkvd, WkdTh, WkdTl, HIDDEN, KV_RANK);
    conv_wt_T<<<dim3(2 * ATTN_DIM / 32, KV_RANK / 32), 256>>>(Wkvu, WkuTh, WkuTl, KV_RANK, 2 * ATTN_DIM);
    conv_wt_T<<<dim3(HIDDEN / 32, ATTN_DIM / 32), 256>>>(Wo,   WoTh,  WoTl,  ATTN_DIM, HIDDEN);

    // x -> bf16 hi/lo
    {
        int n4 = M_ROWS * HIDDEN / 4;
        conv_act<<<(n4 + 255) / 256, 256>>>((const float4*)x, xh, xl, n4);
    }

    // q = x @ Wq ; lat = x @ Wkv_down
    gemm_mma<<<dim3(ATTN_DIM / 128, M_ROWS / 128), 256, GEMM_SMEM>>>(
        xh, xl, WqTh, WqTl, q, M_ROWS, ATTN_DIM, HIDDEN);
    gemm_mma<<<dim3(KV_RANK / 128, M_ROWS / 128), 256, GEMM_SMEM>>>(
        xh, xl, WkdTh, WkdTl, lat, M_ROWS, KV_RANK, HIDDEN);
    rmsnorm_kernel<<<M_ROWS, KV_RANK>>>(lat, knw);
    {
        int n4 = M_ROWS * KV_RANK / 4;
        conv_act<<<(n4 + 255) / 256, 256>>>((const float4*)lat, lath, latl, n4);
    }
    // kv = lat @ Wkv_up
    gemm_mma<<<dim3(2 * ATTN_DIM / 128, M_ROWS / 128), 256, GEMM_SMEM>>>(
        lath, latl, WkuTh, WkuTl, kv, M_ROWS, 2 * ATTN_DIM, KV_RANK);

    // attention operand preparation
    {
        int n4 = M_ROWS * ATTN_DIM / 4;
        conv_act<<<(n4 + 255) / 256, 256>>>((const float4*)q, qh, ql, n4);
    }
    conv_k<<<(M_ROWS * 512 + 255) / 256, 256>>>(kv, kh, kl);
    conv_vt<<<dim3(SEQ / 32, (HEADS * HEAD_DIM) / 32, BATCH), 256>>>(kv, vth, vtl);

    // tensor-core attention
    attn_mma<<<dim3(SEQ / 128, HEADS, BATCH), 256, ATT_SMEM>>>(
        qh, ql, kh, kl, vth, vtl, ao);

    // out = ao @ Wo
    {
        int n4 = M_ROWS * ATTN_DIM / 4;
        conv_act<<<(n4 + 255) / 256, 256>>>((const float4*)ao, aoh, aol, n4);
    }
    gemm_mma<<<dim3(HIDDEN / 128, M_ROWS / 128), 256, GEMM_SMEM>>>(
        aoh, aol, WoTh, WoTl, out, M_ROWS, HIDDEN, ATTN_DIM);
}

// round 7
// speedup vs baseline: 2.8936x; 1.4895x over previous
#include <cuda_runtime.h>
#include <cuda_bf16.h>
#include <cstdint>
#include <math.h>

#define HIDDEN   2048
#define HEADS    16
#define HEAD_DIM 128
#define KV_RANK  256
#define ATTN_DIM 2048
#define BATCH    2
#define SEQ      2048
#define M_ROWS   (BATCH * SEQ)   // 4096

// ---------------- scratch (device globals; allocation-free) ----------------
__device__ float g_q  [M_ROWS * ATTN_DIM];
__device__ float g_lat[M_ROWS * KV_RANK];
__device__ float g_kv [M_ROWS * 2 * ATTN_DIM];
__device__ float g_ao [M_ROWS * ATTN_DIM];

// bf16 split buffers (hi/lo)
__device__ __nv_bfloat16 g_xh [M_ROWS * HIDDEN],   g_xl [M_ROWS * HIDDEN];
__device__ __nv_bfloat16 g_lath[M_ROWS * KV_RANK], g_latl[M_ROWS * KV_RANK];
__device__ __nv_bfloat16 g_aoh[M_ROWS * ATTN_DIM], g_aol[M_ROWS * ATTN_DIM];
// attention operands
__device__ __nv_bfloat16 g_qh [M_ROWS * ATTN_DIM], g_ql [M_ROWS * ATTN_DIM];
__device__ __nv_bfloat16 g_kh [M_ROWS * ATTN_DIM], g_kl [M_ROWS * ATTN_DIM];
__device__ __nv_bfloat16 g_vth[BATCH * HEADS * HEAD_DIM * SEQ];
__device__ __nv_bfloat16 g_vtl[BATCH * HEADS * HEAD_DIM * SEQ];
// weights transposed to [N,K] K-major
__device__ __nv_bfloat16 g_WqTh [ATTN_DIM * HIDDEN],     g_WqTl [ATTN_DIM * HIDDEN];
__device__ __nv_bfloat16 g_WkdTh[KV_RANK * HIDDEN],      g_WkdTl[KV_RANK * HIDDEN];
__device__ __nv_bfloat16 g_WkuTh[2 * ATTN_DIM * KV_RANK],g_WkuTl[2 * ATTN_DIM * KV_RANK];
__device__ __nv_bfloat16 g_WoTh [HIDDEN * ATTN_DIM],     g_WoTl [HIDDEN * ATTN_DIM];

// ======================= PTX helpers (baseline ISA) ========================
__device__ __forceinline__ uint32_t smem_u32(const void* p) {
    uint32_t a;
    asm("{ .reg .u64 t; cvta.to.shared.u64 t, %1; cvt.u32.u64 %0, t; }" : "=r"(a) : "l"(p));
    return a;
}
#define CP_ASYNC16(dst, src) \
    asm volatile("cp.async.cg.shared.global [%0], [%1], 16;" :: "r"(dst), "l"(src) : "memory")
#define CP_COMMIT() asm volatile("cp.async.commit_group;" ::: "memory")
#define CP_WAIT(n)  asm volatile("cp.async.wait_group %0;" :: "n"(n) : "memory")

#define LDSM4(r0, r1, r2, r3, a) \
    asm volatile("ldmatrix.sync.aligned.m8n8.x4.shared.b16 {%0,%1,%2,%3}, [%4];" \
        : "=r"(r0), "=r"(r1), "=r"(r2), "=r"(r3) : "r"(a))

__device__ __forceinline__ void mma16816(float* c, const uint32_t* a, const uint32_t* b) {
    asm volatile("mma.sync.aligned.m16n8k16.row.col.f32.bf16.bf16.f32 "
        "{%0,%1,%2,%3}, {%4,%5,%6,%7}, {%8,%9}, {%0,%1,%2,%3};"
        : "+f"(c[0]), "+f"(c[1]), "+f"(c[2]), "+f"(c[3])
        : "r"(a[0]), "r"(a[1]), "r"(a[2]), "r"(a[3]), "r"(b[0]), "r"(b[1]));
}
__device__ __forceinline__ uint32_t pack_bf2(float a, float b) {
    __nv_bfloat162 t = __floats2bfloat162_rn(a, b);
    return *(uint32_t*)&t;
}

// ======================= conversion kernels ================================
__global__ __launch_bounds__(256) void conv_act(const float4* __restrict__ in,
                                                __nv_bfloat16* __restrict__ h,
                                                __nv_bfloat16* __restrict__ l, int n4)
{
    int i = blockIdx.x * blockDim.x + threadIdx.x;
    if (i >= n4) return;
    float4 x = in[i];
    __nv_bfloat162 h0 = __floats2bfloat162_rn(x.x, x.y);
    __nv_bfloat162 h1 = __floats2bfloat162_rn(x.z, x.w);
    __nv_bfloat162 l0 = __floats2bfloat162_rn(x.x - __bfloat162float(h0.x),
                                              x.y - __bfloat162float(h0.y));
    __nv_bfloat162 l1 = __floats2bfloat162_rn(x.z - __bfloat162float(h1.x),
                                              x.w - __bfloat162float(h1.y));
    ((__nv_bfloat162*)h)[i * 2 + 0] = h0;
    ((__nv_bfloat162*)h)[i * 2 + 1] = h1;
    ((__nv_bfloat162*)l)[i * 2 + 0] = l0;
    ((__nv_bfloat162*)l)[i * 2 + 1] = l1;
}

// scaled variant (for Q: pre-multiplied by 1/sqrt(HEAD_DIM))
__global__ __launch_bounds__(256) void conv_act_s(const float4* __restrict__ in,
                                                  __nv_bfloat16* __restrict__ h,
                                                  __nv_bfloat16* __restrict__ l,
                                                  int n4, float s)
{
    int i = blockIdx.x * blockDim.x + threadIdx.x;
    if (i >= n4) return;
    float4 x = in[i];
    x.x *= s; x.y *= s; x.z *= s; x.w *= s;
    __nv_bfloat162 h0 = __floats2bfloat162_rn(x.x, x.y);
    __nv_bfloat162 h1 = __floats2bfloat162_rn(x.z, x.w);
    __nv_bfloat162 l0 = __floats2bfloat162_rn(x.x - __bfloat162float(h0.x),
                                              x.y - __bfloat162float(h0.y));
    __nv_bfloat162 l1 = __floats2bfloat162_rn(x.z - __bfloat162float(h1.x),
                                              x.w - __bfloat162float(h1.y));
    ((__nv_bfloat162*)h)[i * 2 + 0] = h0;
    ((__nv_bfloat162*)h)[i * 2 + 1] = h1;
    ((__nv_bfloat162*)l)[i * 2 + 0] = l0;
    ((__nv_bfloat162*)l)[i * 2 + 1] = l1;
}

// K half of g_kv (first 2048 cols of 4096-col rows) -> compact bf16 hi/lo
__global__ __launch_bounds__(256) void conv_k(const float* __restrict__ KV,
                                              __nv_bfloat16* __restrict__ h,
                                              __nv_bfloat16* __restrict__ l)
{
    int i = blockIdx.x * blockDim.x + threadIdx.x;
    if (i >= M_ROWS * 512) return;
    int row = i >> 9, c = (i & 511) * 4;
    float4 x = *(const float4*)&KV[(size_t)row * 4096 + c];
    __nv_bfloat162 h0 = __floats2bfloat162_rn(x.x, x.y);
    __nv_bfloat162 h1 = __floats2bfloat162_rn(x.z, x.w);
    __nv_bfloat162 l0 = __floats2bfloat162_rn(x.x - __bfloat162float(h0.x),
                                              x.y - __bfloat162float(h0.y));
    __nv_bfloat162 l1 = __floats2bfloat162_rn(x.z - __bfloat162float(h1.x),
                                              x.w - __bfloat162float(h1.y));
    size_t o = (size_t)row * 2048 + c;
    *(__nv_bfloat162*)&h[o]     = h0;
    *(__nv_bfloat162*)&h[o + 2] = h1;
    *(__nv_bfloat162*)&l[o]     = l0;
    *(__nv_bfloat162*)&l[o + 2] = l1;
}

// V half of g_kv -> transposed bf16 hi/lo: VT[(b*2048 + h*128 + d) * 2048 + s]
__global__ __launch_bounds__(256) void conv_vt(const float* __restrict__ KV,
                                               __nv_bfloat16* __restrict__ Th,
                                               __nv_bfloat16* __restrict__ Tl)
{
    __shared__ float t[32][33];
    const int s0  = blockIdx.x * 32;
    const int hd0 = blockIdx.y * 32;
    const int b   = blockIdx.z;
    const int tid = threadIdx.x;
    for (int i = tid; i < 1024; i += 256) {
        int ss = i >> 5, dd = i & 31;
        t[ss][dd] = KV[(size_t)(b * SEQ + s0 + ss) * 4096 + 2048 + hd0 + dd];
    }
    __syncthreads();
    for (int i = tid; i < 512; i += 256) {
        int dd = i >> 4, sp = (i & 15) * 2;
        float a = t[sp][dd], c = t[sp + 1][dd];
        __nv_bfloat162 hh = __floats2bfloat162_rn(a, c);
        __nv_bfloat162 ll = __floats2bfloat162_rn(a - __bfloat162float(hh.x),
                                                  c - __bfloat162float(hh.y));
        size_t o = (size_t)(b * 2048 + hd0 + dd) * 2048 + s0 + sp;
        *(__nv_bfloat162*)&Th[o] = hh;
        *(__nv_bfloat162*)&Tl[o] = ll;
    }
}

// W [K,N] fp32 -> T hi/lo [N,K] bf16 (K-major)
__global__ __launch_bounds__(256) void conv_wt_T(const float* __restrict__ W,
                                                 __nv_bfloat16* __restrict__ Th,
                                                 __nv_bfloat16* __restrict__ Tl,
                                                 int K, int N)
{
    __shared__ float t[32][33];
    const int n0 = blockIdx.x * 32, k0 = blockIdx.y * 32;
    const int tid = threadIdx.x;
    for (int i = tid; i < 1024; i += 256) {
        int kk = i >> 5, nn = i & 31;
        t[kk][nn] = W[(size_t)(k0 + kk) * N + n0 + nn];
    }
    __syncthreads();
    for (int i = tid; i < 512; i += 256) {
        int nn = i >> 4, kp = (i & 15) * 2;
        float a = t[kp][nn], b = t[kp + 1][nn];
        __nv_bfloat162 h = __floats2bfloat162_rn(a, b);
        __nv_bfloat162 lo = __floats2bfloat162_rn(a - __bfloat162float(h.x),
                                                  b - __bfloat162float(h.y));
        *(__nv_bfloat162*)&Th[(size_t)(n0 + nn) * K + k0 + kp] = h;
        *(__nv_bfloat162*)&Tl[(size_t)(n0 + nn) * K + k0 + kp] = lo;
    }
}

// ======================= mma.sync bf16 GEMM (unchanged; at HW floor) =======
#define GEMM_SMEM (2 * 40960)
__global__ __launch_bounds__(256, 1) void gemm_mma(
    const __nv_bfloat16* __restrict__ Ah, const __nv_bfloat16* __restrict__ Al,
    const __nv_bfloat16* __restrict__ Bh, const __nv_bfloat16* __restrict__ Bl,
    float* __restrict__ C, int M, int N, int K)
{
    extern __shared__ char smem[];
    const uint32_t sbase = smem_u32(smem);
    const int tid  = threadIdx.x;
    const int lane = tid & 31;
    const int w    = tid >> 5;
    const int bm = blockIdx.y * 128;
    const int bn = blockIdx.x * 128;
    const int wm = (w & 3) * 32;
    const int wn = (w >> 2) * 64;
    const int qr = lane >> 2;
    const int qc = lane & 3;

    const __nv_bfloat16* srcs[4] = { Ah, Al, Bh, Bl };
    const int rowoff[4] = { bm, bm, bn, bn };

    float acc[2][8][4];
#pragma unroll
    for (int mf = 0; mf < 2; ++mf)
#pragma unroll
        for (int nf = 0; nf < 8; ++nf)
#pragma unroll
            for (int e = 0; e < 4; ++e) acc[mf][nf][e] = 0.f;

    const int NC = K >> 5;

    auto issue = [&](int c) {
        const uint32_t st = sbase + (c & 1) * 40960;
        const int k0 = c << 5;
#pragma unroll
        for (int i = 0; i < 8; ++i) {
            const int mat = i >> 1;
            const int sub = ((i & 1) << 8) + tid;
            const int r = sub >> 2, v = sub & 3;
            const void* g = srcs[mat] + (size_t)(rowoff[mat] + r) * K + k0 + v * 8;
            CP_ASYNC16(st + mat * 10240 + r * 80 + v * 16, g);
        }
        CP_COMMIT();
    };

    issue(0);

    for (int c = 0; c < NC; ++c) {
        if (c + 1 < NC) { issue(c + 1); CP_WAIT(1); }
        else            { CP_WAIT(0); }
        __syncthreads();

        const char* base = smem + (c & 1) * 40960;
        const char* pAh = base;
        const char* pAl = base + 10240;
        const char* pBh = base + 20480;
        const char* pBl = base + 30720;

#pragma unroll
        for (int ks = 0; ks < 2; ++ks) {
            const int cK = ((ks << 4) + qc * 2) * 2;
            uint32_t ah[2][4], al[2][4], bh[8][2], bl[8][2];
#pragma unroll
            for (int mf = 0; mf < 2; ++mf) {
                const int r = wm + mf * 16 + qr;
                ah[mf][0] = *(const uint32_t*)(pAh + r * 80 + cK);
                ah[mf][1] = *(const uint32_t*)(pAh + (r + 8) * 80 + cK);
                ah[mf][2] = *(const uint32_t*)(pAh + r * 80 + cK + 16);
                ah[mf][3] = *(const uint32_t*)(pAh + (r + 8) * 80 + cK + 16);
                al[mf][0] = *(const uint32_t*)(pAl + r * 80 + cK);
                al[mf][1] = *(const uint32_t*)(pAl + (r + 8) * 80 + cK);
                al[mf][2] = *(const uint32_t*)(pAl + r * 80 + cK + 16);
                al[mf][3] = *(const uint32_t*)(pAl + (r + 8) * 80 + cK + 16);
            }
#pragma unroll
            for (int nf = 0; nf < 8; ++nf) {
                const int n = wn + nf * 8 + qr;
                bh[nf][0] = *(const uint32_t*)(pBh + n * 80 + cK);
                bh[nf][1] = *(const uint32_t*)(pBh + n * 80 + cK + 16);
                bl[nf][0] = *(const uint32_t*)(pBl + n * 80 + cK);
                bl[nf][1] = *(const uint32_t*)(pBl + n * 80 + cK + 16);
            }
#pragma unroll
            for (int mf = 0; mf < 2; ++mf)
#pragma unroll
                for (int nf = 0; nf < 8; ++nf) {
                    mma16816(acc[mf][nf], ah[mf], bh[nf]);
                    mma16816(acc[mf][nf], ah[mf], bl[nf]);
                    mma16816(acc[mf][nf], al[mf], bh[nf]);
                }
        }
        __syncthreads();
    }

#pragma unroll
    for (int mf = 0; mf < 2; ++mf) {
        const int r0 = bm + wm + mf * 16 + qr;
#pragma unroll
        for (int nf = 0; nf < 8; ++nf) {
            const int col = bn + wn + nf * 8 + qc * 2;
            *(float2*)&C[(size_t)r0 * N + col] =
                make_float2(acc[mf][nf][0], acc[mf][nf][1]);
            *(float2*)&C[(size_t)(r0 + 8) * N + col] =
                make_float2(acc[mf][nf][2], acc[mf][nf][3]);
        }
    }
}

// ---------------- RMSNorm over last dim (256), in place --------------------
__global__ __launch_bounds__(256) void rmsnorm_kernel(
    float* __restrict__ lat, const float* __restrict__ w)
{
    const int row = blockIdx.x;
    const int tid = threadIdx.x;
    float v = lat[(size_t)row * KV_RANK + tid];
    float ss = v * v;
#pragma unroll
    for (int o = 16; o; o >>= 1) ss += __shfl_xor_sync(0xffffffffu, ss, o);
    __shared__ float red[8];
    if ((tid & 31) == 0) red[tid >> 5] = ss;
    __syncthreads();
    float tot = red[0] + red[1] + red[2] + red[3] + red[4] + red[5] + red[6] + red[7];
    float r = rsqrtf(tot * (1.0f / KV_RANK) + 1e-6f);
    lat[(size_t)row * KV_RANK + tid] = w[tid] * v * r;
}

// ============ tensor-core flash attention (ldmatrix fragment loads) ========
// Q tile 128 (prescaled by 1/sqrt(d)), K tile 64, 8 warps (warp w: rows w*16..+15).
// smem: Qh@0 Ql@34816 (272B rows), 2 stages @69632/+71680:
//   {Kh(17408) Kl(17408) VTh(18432) VTl(18432)}; K rows 272B, VT rows 144B.
#define ATT_SMEM 212992
__global__ __launch_bounds__(256, 1) void attn_mma(
    const __nv_bfloat16* __restrict__ Qh, const __nv_bfloat16* __restrict__ Ql,
    const __nv_bfloat16* __restrict__ Kh, const __nv_bfloat16* __restrict__ Kl,
    const __nv_bfloat16* __restrict__ VTh, const __nv_bfloat16* __restrict__ VTl,
    float* __restrict__ Og)
{
    extern __shared__ char smA[];
    const uint32_t sb = smem_u32(smA);
    const int tid = threadIdx.x;
    const int w = tid >> 5, lane = tid & 31;
    const int qr = lane >> 2, qc = lane & 3;
    const int qb = blockIdx.x, h = blockIdx.y, b = blockIdx.z;
    const int q0 = qb * 128;

    const uint32_t oQl = 34816, oStage = 69632, stSz = 71680;

    // ldmatrix lane address parts: row = (lane&15), col-half = (lane>>4)*16
    const uint32_t lmK = (uint32_t)(lane & 15) * 272 + (uint32_t)(lane >> 4) * 16; // 272B rows
    const uint32_t lmV = (uint32_t)(lane & 15) * 144 + (uint32_t)(lane >> 4) * 16; // 144B rows
    const uint32_t lmQ = (uint32_t)(w * 16) * 272 + lmK;                           // A rows

    // ---- Q tile load (hi/lo) ----
#pragma unroll
    for (int i = 0; i < 16; ++i) {
        int idx = tid + i * 256;
        int mat = idx >> 11, r = (idx >> 4) & 127, v = idx & 15;
        const __nv_bfloat16* g = (mat ? Ql : Qh) +
            (size_t)(b * SEQ + q0 + r) * 2048 + h * HEAD_DIM + v * 8;
        CP_ASYNC16(sb + (mat ? oQl : 0u) + r * 272 + v * 16, g);
    }
    CP_COMMIT();

    auto issue = [&](int kt) {
        const int k0 = kt * 64;
        const uint32_t st = sb + oStage + (kt & 1) * stSz;
#pragma unroll
        for (int i = 0; i < 8; ++i) {
            int idx = tid + i * 256;
            int mat = idx >> 10, r = (idx >> 4) & 63, v = idx & 15;
            const __nv_bfloat16* g = (mat ? Kl : Kh) +
                (size_t)(b * SEQ + k0 + r) * 2048 + h * HEAD_DIM + v * 8;
            CP_ASYNC16(st + mat * 17408 + r * 272 + v * 16, g);
        }
#pragma unroll
        for (int i = 0; i < 8; ++i) {
            int idx = tid + i * 256;
            int mat = idx >> 10, d = (idx >> 3) & 127, v = idx & 7;
            const __nv_bfloat16* g = (mat ? VTl : VTh) +
                (size_t)((b * HEADS + h) * HEAD_DIM + d) * 2048 + k0 + v * 8;
            CP_ASYNC16(st + 34816 + mat * 18432 + d * 144 + v * 16, g);
        }
        CP_COMMIT();
    };

    float m0 = -1e30f, m1 = -1e30f, l0 = 0.f, l1 = 0.f;
    float acc[16][4];
#pragma unroll
    for (int nt = 0; nt < 16; ++nt)
#pragma unroll
        for (int e = 0; e < 4; ++e) acc[nt][e] = 0.f;

    const int ntk = 2 * (qb + 1);
    issue(0);

    for (int kt = 0; kt < ntk; ++kt) {
        if (kt + 1 < ntk) { issue(kt + 1); CP_WAIT(1); }
        else              { CP_WAIT(0); }
        __syncthreads();

        const uint32_t st  = sb + oStage + (kt & 1) * stSz;
        const uint32_t aKh = st + lmK;
        const uint32_t aKl = st + 17408 + lmK;
        const uint32_t aVh = st + 34816 + lmV;
        const uint32_t aVl = st + 34816 + 18432 + lmV;
        const uint32_t aQh = sb + lmQ;
        const uint32_t aQl = sb + oQl + lmQ;

        // ---- S = Q K^T (3 terms), ldmatrix fragments ----
        float sfr[8][4];
#pragma unroll
        for (int nt = 0; nt < 8; ++nt)
#pragma unroll
            for (int e = 0; e < 4; ++e) sfr[nt][e] = 0.f;

#pragma unroll
        for (int ks = 0; ks < 8; ++ks) {
            const uint32_t kb = ks * 32;
            uint32_t ah[4], al[4];
            LDSM4(ah[0], ah[1], ah[2], ah[3], aQh + kb);
            LDSM4(al[0], al[1], al[2], al[3], aQl + kb);
#pragma unroll
            for (int np = 0; np < 4; ++np) {
                const uint32_t ro = (uint32_t)(np * 16) * 272 + kb;
                uint32_t h0, h1, h2, h3, L0, L1, L2, L3;
                LDSM4(h0, h1, h2, h3, aKh + ro);
                LDSM4(L0, L1, L2, L3, aKl + ro);
                uint32_t be[2] = { h0, h2 }, bo[2] = { h1, h3 };
                uint32_t le[2] = { L0, L2 }, lo[2] = { L1, L3 };
                mma16816(sfr[2 * np],     ah, be);
                mma16816(sfr[2 * np],     ah, le);
                mma16816(sfr[2 * np],     al, be);
                mma16816(sfr[2 * np + 1], ah, bo);
                mma16816(sfr[2 * np + 1], ah, lo);
                mma16816(sfr[2 * np + 1], al, bo);
            }
        }

        // ---- mask + online softmax (Q prescaled; mask = select only) ----
        const int i0 = q0 + w * 16 + qr;
        const int i1 = i0 + 8;
        const int k0 = kt * 64;
#pragma unroll
        for (int nt = 0; nt < 8; ++nt) {
            const int j = k0 + nt * 8 + 2 * qc;
            if (j     > i0) sfr[nt][0] = -1e30f;
            if (j + 1 > i0) sfr[nt][1] = -1e30f;
            if (j     > i1) sfr[nt][2] = -1e30f;
            if (j + 1 > i1) sfr[nt][3] = -1e30f;
        }
        float mx0 = -1e30f, mx1 = -1e30f;
#pragma unroll
        for (int nt = 0; nt < 8; ++nt) {
            mx0 = fmaxf(mx0, fmaxf(sfr[nt][0], sfr[nt][1]));
            mx1 = fmaxf(mx1, fmaxf(sfr[nt][2], sfr[nt][3]));
        }
        mx0 = fmaxf(mx0, __shfl_xor_sync(0xffffffffu, mx0, 1));
        mx0 = fmaxf(mx0, __shfl_xor_sync(0xffffffffu, mx0, 2));
        mx1 = fmaxf(mx1, __shfl_xor_sync(0xffffffffu, mx1, 1));
        mx1 = fmaxf(mx1, __shfl_xor_sync(0xffffffffu, mx1, 2));
        const float mn0 = fmaxf(m0, mx0), mn1 = fmaxf(m1, mx1);
        const float c0 = __expf(m0 - mn0), c1 = __expf(m1 - mn1);
        m0 = mn0; m1 = mn1;
        l0 *= c0;  l1 *= c1;

        uint32_t pa[4][4], pl[4][4];
        float rs0 = 0.f, rs1 = 0.f;
#pragma unroll
        for (int nt = 0; nt < 8; ++nt) {
            float p0 = __expf(sfr[nt][0] - mn0);
            float p1 = __expf(sfr[nt][1] - mn0);
            float p2 = __expf(sfr[nt][2] - mn1);
            float p3 = __expf(sfr[nt][3] - mn1);
            rs0 += p0 + p1; rs1 += p2 + p3;
            uint32_t h01 = pack_bf2(p0, p1);
            uint32_t h23 = pack_bf2(p2, p3);
            __nv_bfloat162 hb01 = *(__nv_bfloat162*)&h01;
            __nv_bfloat162 hb23 = *(__nv_bfloat162*)&h23;
            uint32_t r01 = pack_bf2(p0 - __bfloat162float(hb01.x),
                                    p1 - __bfloat162float(hb01.y));
            uint32_t r23 = pack_bf2(p2 - __bfloat162float(hb23.x),
                                    p3 - __bfloat162float(hb23.y));
            const int ks = nt >> 1, half = nt & 1;
            if (half == 0) { pa[ks][0] = h01; pa[ks][1] = h23; pl[ks][0] = r01; pl[ks][1] = r23; }
            else           { pa[ks][2] = h01; pa[ks][3] = h23; pl[ks][2] = r01; pl[ks][3] = r23; }
        }
        rs0 += __shfl_xor_sync(0xffffffffu, rs0, 1);
        rs0 += __shfl_xor_sync(0xffffffffu, rs0, 2);
        rs1 += __shfl_xor_sync(0xffffffffu, rs1, 1);
        rs1 += __shfl_xor_sync(0xffffffffu, rs1, 2);
        l0 += rs0; l1 += rs1;

#pragma unroll
        for (int nt = 0; nt < 16; ++nt) {
            acc[nt][0] *= c0; acc[nt][1] *= c0;
            acc[nt][2] *= c1; acc[nt][3] *= c1;
        }

        // ---- O += P V (3 terms), ldmatrix V fragments ----
#pragma unroll
        for (int ks = 0; ks < 4; ++ks) {
            const uint32_t kb = ks * 32;
#pragma unroll
            for (int dp = 0; dp < 8; ++dp) {
                const uint32_t ro = (uint32_t)(dp * 16) * 144 + kb;
                uint32_t h0, h1, h2, h3, L0, L1, L2, L3;
                LDSM4(h0, h1, h2, h3, aVh + ro);
                LDSM4(L0, L1, L2, L3, aVl + ro);
                uint32_t be[2] = { h0, h2 }, bo[2] = { h1, h3 };
                uint32_t le[2] = { L0, L2 }, lo[2] = { L1, L3 };
                mma16816(acc[2 * dp],     pa[ks], be);
                mma16816(acc[2 * dp],     pa[ks], le);
                mma16816(acc[2 * dp],     pl[ks], be);
                mma16816(acc[2 * dp + 1], pa[ks], bo);
                mma16816(acc[2 * dp + 1], pa[ks], lo);
                mma16816(acc[2 * dp + 1], pl[ks], bo);
            }
        }
        __syncthreads();
    }

    // ---- epilogue ----
    const float inv0 = 1.0f / l0, inv1 = 1.0f / l1;
    const size_t r0 = (size_t)(b * SEQ + q0 + w * 16 + qr);
#pragma unroll
    for (int nt = 0; nt < 16; ++nt) {
        const int col = h * HEAD_DIM + nt * 8 + 2 * qc;
        *(float2*)&Og[r0 * 2048 + col] =
            make_float2(acc[nt][0] * inv0, acc[nt][1] * inv0);
        *(float2*)&Og[(r0 + 8) * 2048 + col] =
            make_float2(acc[nt][2] * inv1, acc[nt][3] * inv1);
    }
}

// ---------------------------------------------------------------------------
extern "C" void kernel_launch(void* const* d_in, const int* in_sizes, int n_in,
                              void* d_out, int out_size)
{
    const float* x    = (const float*)d_in[0];
    const float* Wq   = (const float*)d_in[1];
    const float* Wkvd = (const float*)d_in[2];
    const float* knw  = (const float*)d_in[3];
    const float* Wkvu = (const float*)d_in[4];
    const float* Wo   = (const float*)d_in[5];
    float* out = (float*)d_out;

    float *q, *lat, *kv, *ao;
    cudaGetSymbolAddress((void**)&q,   g_q);
    cudaGetSymbolAddress((void**)&lat, g_lat);
    cudaGetSymbolAddress((void**)&kv,  g_kv);
    cudaGetSymbolAddress((void**)&ao,  g_ao);
    __nv_bfloat16 *xh,*xl,*lath,*latl,*aoh,*aol,*qh,*ql,*kh,*kl,*vth,*vtl;
    __nv_bfloat16 *WqTh,*WqTl,*WkdTh,*WkdTl,*WkuTh,*WkuTl,*WoTh,*WoTl;
    cudaGetSymbolAddress((void**)&xh, g_xh);     cudaGetSymbolAddress((void**)&xl, g_xl);
    cudaGetSymbolAddress((void**)&lath, g_lath); cudaGetSymbolAddress((void**)&latl, g_latl);
    cudaGetSymbolAddress((void**)&aoh, g_aoh);   cudaGetSymbolAddress((void**)&aol, g_aol);
    cudaGetSymbolAddress((void**)&qh, g_qh);     cudaGetSymbolAddress((void**)&ql, g_ql);
    cudaGetSymbolAddress((void**)&kh, g_kh);     cudaGetSymbolAddress((void**)&kl, g_kl);
    cudaGetSymbolAddress((void**)&vth, g_vth);   cudaGetSymbolAddress((void**)&vtl, g_vtl);
    cudaGetSymbolAddress((void**)&WqTh, g_WqTh); cudaGetSymbolAddress((void**)&WqTl, g_WqTl);
    cudaGetSymbolAddress((void**)&WkdTh, g_WkdTh); cudaGetSymbolAddress((void**)&WkdTl, g_WkdTl);
    cudaGetSymbolAddress((void**)&WkuTh, g_WkuTh); cudaGetSymbolAddress((void**)&WkuTl, g_WkuTl);
    cudaGetSymbolAddress((void**)&WoTh, g_WoTh); cudaGetSymbolAddress((void**)&WoTl, g_WoTl);

    cudaFuncSetAttribute(gemm_mma, cudaFuncAttributeMaxDynamicSharedMemorySize, GEMM_SMEM);
    cudaFuncSetAttribute(attn_mma, cudaFuncAttributeMaxDynamicSharedMemorySize, ATT_SMEM);

    // weight conversions
    conv_wt_T<<<dim3(ATTN_DIM / 32, HIDDEN / 32), 256>>>(Wq,   WqTh,  WqTl,  HIDDEN, ATTN_DIM);
    conv_wt_T<<<dim3(KV_RANK / 32, HIDDEN / 32), 256>>>(Wkvd, WkdTh, WkdTl, HIDDEN, KV_RANK);
    conv_wt_T<<<dim3(2 * ATTN_DIM / 32, KV_RANK / 32), 256>>>(Wkvu, WkuTh, WkuTl, KV_RANK, 2 * ATTN_DIM);
    conv_wt_T<<<dim3(HIDDEN / 32, ATTN_DIM / 32), 256>>>(Wo,   WoTh,  WoTl,  ATTN_DIM, HIDDEN);

    // x -> bf16 hi/lo
    {
        int n4 = M_ROWS * HIDDEN / 4;
        conv_act<<<(n4 + 255) / 256, 256>>>((const float4*)x, xh, xl, n4);
    }

    // q = x @ Wq ; lat = x @ Wkv_down
    gemm_mma<<<dim3(ATTN_DIM / 128, M_ROWS / 128), 256, GEMM_SMEM>>>(
        xh, xl, WqTh, WqTl, q, M_ROWS, ATTN_DIM, HIDDEN);
    gemm_mma<<<dim3(KV_RANK / 128, M_ROWS / 128), 256, GEMM_SMEM>>>(
        xh, xl, WkdTh, WkdTl, lat, M_ROWS, KV_RANK, HIDDEN);
    rmsnorm_kernel<<<M_ROWS, KV_RANK>>>(lat, knw);
    {
        int n4 = M_ROWS * KV_RANK / 4;
        conv_act<<<(n4 + 255) / 256, 256>>>((const float4*)lat, lath, latl, n4);
    }
    // kv = lat @ Wkv_up
    gemm_mma<<<dim3(2 * ATTN_DIM / 128, M_ROWS / 128), 256, GEMM_SMEM>>>(
        lath, latl, WkuTh, WkuTl, kv, M_ROWS, 2 * ATTN_DIM, KV_RANK);

    // attention operand preparation (Q prescaled by 1/sqrt(d))
    {
        int n4 = M_ROWS * ATTN_DIM / 4;
        conv_act_s<<<(n4 + 255) / 256, 256>>>((const float4*)q, qh, ql, n4,
                                              0.08838834764831845f);
    }
    conv_k<<<(M_ROWS * 512 + 255) / 256, 256>>>(kv, kh, kl);
    conv_vt<<<dim3(SEQ / 32, (HEADS * HEAD_DIM) / 32, BATCH), 256>>>(kv, vth, vtl);

    // tensor-core attention
    attn_mma<<<dim3(SEQ / 128, HEADS, BATCH), 256, ATT_SMEM>>>(
        qh, ql, kh, kl, vth, vtl, ao);

    // out = ao @ Wo
    {
        int n4 = M_ROWS * ATTN_DIM / 4;
        conv_act<<<(n4 + 255) / 256, 256>>>((const float4*)ao, aoh, aol, n4);
    }
    gemm_mma<<<dim3(HIDDEN / 128, M_ROWS / 128), 256, GEMM_SMEM>>>(
        aoh, aol, WoTh, WoTl, out, M_ROWS, HIDDEN, ATTN_DIM);
}

// round 9
// speedup vs baseline: 4.0871x; 1.4124x over previous
#include <cuda_runtime.h>
#include <cuda_fp16.h>
#include <cstdint>
#include <math.h>

#define HIDDEN   2048
#define HEADS    16
#define HEAD_DIM 128
#define KV_RANK  256
#define ATTN_DIM 2048
#define BATCH    2
#define SEQ      2048
#define M_ROWS   (BATCH * SEQ)   // 4096

// ---------------- scratch (device globals; allocation-free) ----------------
__device__ float g_q  [M_ROWS * ATTN_DIM];
__device__ float g_lat[M_ROWS * KV_RANK];
__device__ float g_kv [M_ROWS * 2 * ATTN_DIM];
__device__ float g_ao [M_ROWS * ATTN_DIM];

// fp16 split buffers (A-side: hi/lo; B-side: single)
__device__ __half g_xh [M_ROWS * HIDDEN],   g_xl [M_ROWS * HIDDEN];
__device__ __half g_lath[M_ROWS * KV_RANK], g_latl[M_ROWS * KV_RANK];
__device__ __half g_aoh[M_ROWS * ATTN_DIM], g_aol[M_ROWS * ATTN_DIM];
__device__ __half g_qh [M_ROWS * ATTN_DIM], g_ql [M_ROWS * ATTN_DIM];
__device__ __half g_k1 [M_ROWS * ATTN_DIM];
__device__ __half g_vt [BATCH * HEADS * HEAD_DIM * SEQ];
// weights transposed to [N,K] K-major, single fp16
__device__ __half g_WqT [ATTN_DIM * HIDDEN];
__device__ __half g_WkdT[KV_RANK * HIDDEN];
__device__ __half g_WkuT[2 * ATTN_DIM * KV_RANK];
__device__ __half g_WoT [HIDDEN * ATTN_DIM];

// ======================= PTX helpers (baseline ISA) ========================
__device__ __forceinline__ uint32_t smem_u32(const void* p) {
    uint32_t a;
    asm("{ .reg .u64 t; cvta.to.shared.u64 t, %1; cvt.u32.u64 %0, t; }" : "=r"(a) : "l"(p));
    return a;
}
#define CP_ASYNC16(dst, src) \
    asm volatile("cp.async.cg.shared.global [%0], [%1], 16;" :: "r"(dst), "l"(src) : "memory")
#define CP_COMMIT() asm volatile("cp.async.commit_group;" ::: "memory")
#define CP_WAIT(n)  asm volatile("cp.async.wait_group %0;" :: "n"(n) : "memory")

#define LDSM4(r0, r1, r2, r3, a) \
    asm volatile("ldmatrix.sync.aligned.m8n8.x4.shared.b16 {%0,%1,%2,%3}, [%4];" \
        : "=r"(r0), "=r"(r1), "=r"(r2), "=r"(r3) : "r"(a))

__device__ __forceinline__ void mma16816(float* c, const uint32_t* a, const uint32_t* b) {
    asm volatile("mma.sync.aligned.m16n8k16.row.col.f32.f16.f16.f32 "
        "{%0,%1,%2,%3}, {%4,%5,%6,%7}, {%8,%9}, {%0,%1,%2,%3};"
        : "+f"(c[0]), "+f"(c[1]), "+f"(c[2]), "+f"(c[3])
        : "r"(a[0]), "r"(a[1]), "r"(a[2]), "r"(a[3]), "r"(b[0]), "r"(b[1]));
}
__device__ __forceinline__ uint32_t pack_hf2(float a, float b) {
    __half2 t = __floats2half2_rn(a, b);
    return *(uint32_t*)&t;
}

// ======================= conversion kernels ================================
// fp32 -> fp16 hi/lo (optionally scaled)
__global__ __launch_bounds__(256) void conv_act(const float4* __restrict__ in,
                                                __half* __restrict__ h,
                                                __half* __restrict__ l,
                                                int n4, float s)
{
    int i = blockIdx.x * blockDim.x + threadIdx.x;
    if (i >= n4) return;
    float4 x = in[i];
    x.x *= s; x.y *= s; x.z *= s; x.w *= s;
    __half hx = __float2half_rn(x.x), hy = __float2half_rn(x.y);
    __half hz = __float2half_rn(x.z), hw = __float2half_rn(x.w);
    ((__half2*)h)[i * 2 + 0] = __halves2half2(hx, hy);
    ((__half2*)h)[i * 2 + 1] = __halves2half2(hz, hw);
    ((__half2*)l)[i * 2 + 0] = __floats2half2_rn(x.x - __half2float(hx),
                                                 x.y - __half2float(hy));
    ((__half2*)l)[i * 2 + 1] = __floats2half2_rn(x.z - __half2float(hz),
                                                 x.w - __half2float(hw));
}

// K half of g_kv (first 2048 cols of 4096-col rows) -> compact single fp16
__global__ __launch_bounds__(256) void conv_k(const float* __restrict__ KV,
                                              __half* __restrict__ h)
{
    int i = blockIdx.x * blockDim.x + threadIdx.x;
    if (i >= M_ROWS * 512) return;
    int row = i >> 9, c = (i & 511) * 4;
    float4 x = *(const float4*)&KV[(size_t)row * 4096 + c];
    size_t o = (size_t)row * 2048 + c;
    *(__half2*)&h[o]     = __floats2half2_rn(x.x, x.y);
    *(__half2*)&h[o + 2] = __floats2half2_rn(x.z, x.w);
}

// V half of g_kv -> transposed single fp16: VT[(b*2048 + h*128 + d) * 2048 + s]
__global__ __launch_bounds__(256) void conv_vt(const float* __restrict__ KV,
                                               __half* __restrict__ T)
{
    __shared__ float t[32][33];
    const int s0  = blockIdx.x * 32;
    const int hd0 = blockIdx.y * 32;
    const int b   = blockIdx.z;
    const int tid = threadIdx.x;
    for (int i = tid; i < 1024; i += 256) {
        int ss = i >> 5, dd = i & 31;
        t[ss][dd] = KV[(size_t)(b * SEQ + s0 + ss) * 4096 + 2048 + hd0 + dd];
    }
    __syncthreads();
    for (int i = tid; i < 512; i += 256) {
        int dd = i >> 4, sp = (i & 15) * 2;
        size_t o = (size_t)(b * 2048 + hd0 + dd) * 2048 + s0 + sp;
        *(__half2*)&T[o] = __floats2half2_rn(t[sp][dd], t[sp + 1][dd]);
    }
}

// W [K,N] fp32 -> T [N,K] single fp16 (K-major)
__global__ __launch_bounds__(256) void conv_wt_T(const float* __restrict__ W,
                                                 __half* __restrict__ Th,
                                                 int K, int N)
{
    __shared__ float t[32][33];
    const int n0 = blockIdx.x * 32, k0 = blockIdx.y * 32;
    const int tid = threadIdx.x;
    for (int i = tid; i < 1024; i += 256) {
        int kk = i >> 5, nn = i & 31;
        t[kk][nn] = W[(size_t)(k0 + kk) * N + n0 + nn];
    }
    __syncthreads();
    for (int i = tid; i < 512; i += 256) {
        int nn = i >> 4, kp = (i & 15) * 2;
        *(__half2*)&Th[(size_t)(n0 + nn) * K + k0 + kp] =
            __floats2half2_rn(t[kp][nn], t[kp + 1][nn]);
    }
}

// ======================= mma.sync fp16 GEMM (2-term, ldmatrix) =============
// C[M,N] fp32 = A[M,K] @ B[N,K]^T, A = Ah + Al (fp16), B single fp16.
// CTA tile 128x128, BK=32, double-buffered cp.async.
// stage (80B rows): Ah@0 (10240), Al@10240, B@20480; stage 30720; 2 stages.
#define GEMM_SMEM (2 * 30720)
__global__ __launch_bounds__(256, 2) void gemm_mma(
    const __half* __restrict__ Ah, const __half* __restrict__ Al,
    const __half* __restrict__ Bw,
    float* __restrict__ C, int M, int N, int K)
{
    extern __shared__ char smem[];
    const uint32_t sbase = smem_u32(smem);
    const int tid  = threadIdx.x;
    const int lane = tid & 31;
    const int w    = tid >> 5;
    const int bm = blockIdx.y * 128;
    const int bn = blockIdx.x * 128;
    const int wm = (w & 3) * 32;
    const int wn = (w >> 2) * 64;
    const int qr = lane >> 2;
    const int qc = lane & 3;

    const __half* srcs[3] = { Ah, Al, Bw };
    const int rowoff[3] = { bm, bm, bn };

    const uint32_t lm = (uint32_t)(lane & 15) * 80 + (uint32_t)(lane >> 4) * 16;

    float acc[2][8][4];
#pragma unroll
    for (int mf = 0; mf < 2; ++mf)
#pragma unroll
        for (int nf = 0; nf < 8; ++nf)
#pragma unroll
            for (int e = 0; e < 4; ++e) acc[mf][nf][e] = 0.f;

    const int NC = K >> 5;

    auto issue = [&](int c) {
        const uint32_t st = sbase + (c & 1) * 30720;
        const int k0 = c << 5;
#pragma unroll
        for (int i = 0; i < 6; ++i) {
            const int mat = i >> 1;
            const int sub = ((i & 1) << 8) + tid;
            const int r = sub >> 2, v = sub & 3;
            const void* g = srcs[mat] + (size_t)(rowoff[mat] + r) * K + k0 + v * 8;
            CP_ASYNC16(st + mat * 10240 + r * 80 + v * 16, g);
        }
        CP_COMMIT();
    };

    issue(0);

    for (int c = 0; c < NC; ++c) {
        if (c + 1 < NC) { issue(c + 1); CP_WAIT(1); }
        else            { CP_WAIT(0); }
        __syncthreads();

        const uint32_t st = sbase + (c & 1) * 30720;
        const uint32_t aAh = st + wm * 80 + lm;
        const uint32_t aAl = st + 10240 + wm * 80 + lm;
        const uint32_t aB  = st + 20480 + wn * 80 + lm;

#pragma unroll
        for (int ks = 0; ks < 2; ++ks) {
            const uint32_t kb = ks * 32;
            uint32_t ah[2][4], al[2][4];
            LDSM4(ah[0][0], ah[0][1], ah[0][2], ah[0][3], aAh + kb);
            LDSM4(ah[1][0], ah[1][1], ah[1][2], ah[1][3], aAh + 16 * 80 + kb);
            LDSM4(al[0][0], al[0][1], al[0][2], al[0][3], aAl + kb);
            LDSM4(al[1][0], al[1][1], al[1][2], al[1][3], aAl + 16 * 80 + kb);
#pragma unroll
            for (int np = 0; np < 4; ++np) {
                uint32_t h0, h1, h2, h3;
                LDSM4(h0, h1, h2, h3, aB + (uint32_t)(np * 16) * 80 + kb);
                uint32_t be[2] = { h0, h2 }, bo[2] = { h1, h3 };
#pragma unroll
                for (int mf = 0; mf < 2; ++mf) {
                    mma16816(acc[mf][2 * np],     ah[mf], be);
                    mma16816(acc[mf][2 * np],     al[mf], be);
                    mma16816(acc[mf][2 * np + 1], ah[mf], bo);
                    mma16816(acc[mf][2 * np + 1], al[mf], bo);
                }
            }
        }
        __syncthreads();
    }

#pragma unroll
    for (int mf = 0; mf < 2; ++mf) {
        const int r0 = bm + wm + mf * 16 + qr;
#pragma unroll
        for (int nf = 0; nf < 8; ++nf) {
            const int col = bn + wn + nf * 8 + qc * 2;
            *(float2*)&C[(size_t)r0 * N + col] =
                make_float2(acc[mf][nf][0], acc[mf][nf][1]);
            *(float2*)&C[(size_t)(r0 + 8) * N + col] =
                make_float2(acc[mf][nf][2], acc[mf][nf][3]);
        }
    }
}

// ---------------- RMSNorm over last dim (256), in place --------------------
__global__ __launch_bounds__(256) void rmsnorm_kernel(
    float* __restrict__ lat, const float* __restrict__ w)
{
    const int row = blockIdx.x;
    const int tid = threadIdx.x;
    float v = lat[(size_t)row * KV_RANK + tid];
    float ss = v * v;
#pragma unroll
    for (int o = 16; o; o >>= 1) ss += __shfl_xor_sync(0xffffffffu, ss, o);
    __shared__ float red[8];
    if ((tid & 31) == 0) red[tid >> 5] = ss;
    __syncthreads();
    float tot = red[0] + red[1] + red[2] + red[3] + red[4] + red[5] + red[6] + red[7];
    float r = rsqrtf(tot * (1.0f / KV_RANK) + 1e-6f);
    lat[(size_t)row * KV_RANK + tid] = w[tid] * v * r;
}

// ============ tensor-core flash attention (fp16 2-term, ldmatrix) ==========
// Q tile 128 (prescaled by 1/sqrt(d), hi/lo), K/V single fp16.
// smem: Qh@0 Ql@34816 (272B rows), 2 stages @69632/+35840:
//   {K(17408, 272B rows), VT(18432, 144B rows)}.
#define ATT_SMEM 141312
__global__ __launch_bounds__(256, 1) void attn_mma(
    const __half* __restrict__ Qh, const __half* __restrict__ Ql,
    const __half* __restrict__ Kg, const __half* __restrict__ VT,
    float* __restrict__ Og)
{
    extern __shared__ char smA[];
    const uint32_t sb = smem_u32(smA);
    const int tid = threadIdx.x;
    const int w = tid >> 5, lane = tid & 31;
    const int qr = lane >> 2, qc = lane & 3;
    const int qb = blockIdx.x, h = blockIdx.y, b = blockIdx.z;
    const int q0 = qb * 128;

    const uint32_t oQl = 34816, oStage = 69632, stSz = 35840;

    const uint32_t lmK = (uint32_t)(lane & 15) * 272 + (uint32_t)(lane >> 4) * 16;
    const uint32_t lmV = (uint32_t)(lane & 15) * 144 + (uint32_t)(lane >> 4) * 16;
    const uint32_t lmQ = (uint32_t)(w * 16) * 272 + lmK;

    // ---- Q tile load (hi/lo) ----
#pragma unroll
    for (int i = 0; i < 16; ++i) {
        int idx = tid + i * 256;
        int mat = idx >> 11, r = (idx >> 4) & 127, v = idx & 15;
        const __half* g = (mat ? Ql : Qh) +
            (size_t)(b * SEQ + q0 + r) * 2048 + h * HEAD_DIM + v * 8;
        CP_ASYNC16(sb + (mat ? oQl : 0u) + r * 272 + v * 16, g);
    }
    CP_COMMIT();

    auto issue = [&](int kt) {
        const int k0 = kt * 64;
        const uint32_t st = sb + oStage + (kt & 1) * stSz;
#pragma unroll
        for (int i = 0; i < 4; ++i) {
            int idx = tid + i * 256;
            int r = idx >> 4, v = idx & 15;
            const __half* g = Kg + (size_t)(b * SEQ + k0 + r) * 2048 + h * HEAD_DIM + v * 8;
            CP_ASYNC16(st + r * 272 + v * 16, g);
        }
#pragma unroll
        for (int i = 0; i < 4; ++i) {
            int idx = tid + i * 256;
            int d = idx >> 3, v = idx & 7;
            const __half* g = VT + (size_t)((b * HEADS + h) * HEAD_DIM + d) * 2048 + k0 + v * 8;
            CP_ASYNC16(st + 17408 + d * 144 + v * 16, g);
        }
        CP_COMMIT();
    };

    float m0 = -1e30f, m1 = -1e30f, l0 = 0.f, l1 = 0.f;
    float acc[16][4];
#pragma unroll
    for (int nt = 0; nt < 16; ++nt)
#pragma unroll
        for (int e = 0; e < 4; ++e) acc[nt][e] = 0.f;

    const int ntk = 2 * (qb + 1);
    issue(0);

    for (int kt = 0; kt < ntk; ++kt) {
        if (kt + 1 < ntk) { issue(kt + 1); CP_WAIT(1); }
        else              { CP_WAIT(0); }
        __syncthreads();

        const uint32_t st  = sb + oStage + (kt & 1) * stSz;
        const uint32_t aK  = st + lmK;
        const uint32_t aV  = st + 17408 + lmV;
        const uint32_t aQh = sb + lmQ;
        const uint32_t aQl = sb + oQl + lmQ;

        // ---- S = Q K^T (2 terms) ----
        float sfr[8][4];
#pragma unroll
        for (int nt = 0; nt < 8; ++nt)
#pragma unroll
            for (int e = 0; e < 4; ++e) sfr[nt][e] = 0.f;

#pragma unroll
        for (int ks = 0; ks < 8; ++ks) {
            const uint32_t kb = ks * 32;
            uint32_t ah[4], al[4];
            LDSM4(ah[0], ah[1], ah[2], ah[3], aQh + kb);
            LDSM4(al[0], al[1], al[2], al[3], aQl + kb);
#pragma unroll
            for (int np = 0; np < 4; ++np) {
                uint32_t h0, h1, h2, h3;
                LDSM4(h0, h1, h2, h3, aK + (uint32_t)(np * 16) * 272 + kb);
                uint32_t be[2] = { h0, h2 }, bo[2] = { h1, h3 };
                mma16816(sfr[2 * np],     ah, be);
                mma16816(sfr[2 * np],     al, be);
                mma16816(sfr[2 * np + 1], ah, bo);
                mma16816(sfr[2 * np + 1], al, bo);
            }
        }

        // ---- mask + online softmax ----
        const int i0 = q0 + w * 16 + qr;
        const int i1 = i0 + 8;
        const int k0 = kt * 64;
#pragma unroll
        for (int nt = 0; nt < 8; ++nt) {
            const int j = k0 + nt * 8 + 2 * qc;
            if (j     > i0) sfr[nt][0] = -1e30f;
            if (j + 1 > i0) sfr[nt][1] = -1e30f;
            if (j     > i1) sfr[nt][2] = -1e30f;
            if (j + 1 > i1) sfr[nt][3] = -1e30f;
        }
        float mx0 = -1e30f, mx1 = -1e30f;
#pragma unroll
        for (int nt = 0; nt < 8; ++nt) {
            mx0 = fmaxf(mx0, fmaxf(sfr[nt][0], sfr[nt][1]));
            mx1 = fmaxf(mx1, fmaxf(sfr[nt][2], sfr[nt][3]));
        }
        mx0 = fmaxf(mx0, __shfl_xor_sync(0xffffffffu, mx0, 1));
        mx0 = fmaxf(mx0, __shfl_xor_sync(0xffffffffu, mx0, 2));
        mx1 = fmaxf(mx1, __shfl_xor_sync(0xffffffffu, mx1, 1));
        mx1 = fmaxf(mx1, __shfl_xor_sync(0xffffffffu, mx1, 2));
        const float mn0 = fmaxf(m0, mx0), mn1 = fmaxf(m1, mx1);
        const float c0 = __expf(m0 - mn0), c1 = __expf(m1 - mn1);
        m0 = mn0; m1 = mn1;
        l0 *= c0;  l1 *= c1;

        uint32_t pa[4][4], pl[4][4];
        float rs0 = 0.f, rs1 = 0.f;
#pragma unroll
        for (int nt = 0; nt < 8; ++nt) {
            float p0 = __expf(sfr[nt][0] - mn0);
            float p1 = __expf(sfr[nt][1] - mn0);
            float p2 = __expf(sfr[nt][2] - mn1);
            float p3 = __expf(sfr[nt][3] - mn1);
            rs0 += p0 + p1; rs1 += p2 + p3;
            uint32_t h01 = pack_hf2(p0, p1);
            uint32_t h23 = pack_hf2(p2, p3);
            __half2 hb01 = *(__half2*)&h01;
            __half2 hb23 = *(__half2*)&h23;
            uint32_t r01 = pack_hf2(p0 - __half2float(__low2half(hb01)),
                                    p1 - __half2float(__high2half(hb01)));
            uint32_t r23 = pack_hf2(p2 - __half2float(__low2half(hb23)),
                                    p3 - __half2float(__high2half(hb23)));
            const int ks = nt >> 1, half = nt & 1;
            if (half == 0) { pa[ks][0] = h01; pa[ks][1] = h23; pl[ks][0] = r01; pl[ks][1] = r23; }
            else           { pa[ks][2] = h01; pa[ks][3] = h23; pl[ks][2] = r01; pl[ks][3] = r23; }
        }
        rs0 += __shfl_xor_sync(0xffffffffu, rs0, 1);
        rs0 += __shfl_xor_sync(0xffffffffu, rs0, 2);
        rs1 += __shfl_xor_sync(0xffffffffu, rs1, 1);
        rs1 += __shfl_xor_sync(0xffffffffu, rs1, 2);
        l0 += rs0; l1 += rs1;

#pragma unroll
        for (int nt = 0; nt < 16; ++nt) {
            acc[nt][0] *= c0; acc[nt][1] *= c0;
            acc[nt][2] *= c1; acc[nt][3] *= c1;
        }

        // ---- O += P V (2 terms) ----
#pragma unroll
        for (int ks = 0; ks < 4; ++ks) {
            const uint32_t kb = ks * 32;
#pragma unroll
            for (int dp = 0; dp < 8; ++dp) {
                uint32_t h0, h1, h2, h3;
                LDSM4(h0, h1, h2, h3, aV + (uint32_t)(dp * 16) * 144 + kb);
                uint32_t be[2] = { h0, h2 }, bo[2] = { h1, h3 };
                mma16816(acc[2 * dp],     pa[ks], be);
                mma16816(acc[2 * dp],     pl[ks], be);
                mma16816(acc[2 * dp + 1], pa[ks], bo);
                mma16816(acc[2 * dp + 1], pl[ks], bo);
            }
        }
        __syncthreads();
    }

    // ---- epilogue ----
    const float inv0 = 1.0f / l0, inv1 = 1.0f / l1;
    const size_t r0 = (size_t)(b * SEQ + q0 + w * 16 + qr);
#pragma unroll
    for (int nt = 0; nt < 16; ++nt) {
        const int col = h * HEAD_DIM + nt * 8 + 2 * qc;
        *(float2*)&Og[r0 * 2048 + col] =
            make_float2(acc[nt][0] * inv0, acc[nt][1] * inv0);
        *(float2*)&Og[(r0 + 8) * 2048 + col] =
            make_float2(acc[nt][2] * inv1, acc[nt][3] * inv1);
    }
}

// ---------------------------------------------------------------------------
extern "C" void kernel_launch(void* const* d_in, const int* in_sizes, int n_in,
                              void* d_out, int out_size)
{
    const float* x    = (const float*)d_in[0];
    const float* Wq   = (const float*)d_in[1];
    const float* Wkvd = (const float*)d_in[2];
    const float* knw  = (const float*)d_in[3];
    const float* Wkvu = (const float*)d_in[4];
    const float* Wo   = (const float*)d_in[5];
    float* out = (float*)d_out;

    float *q, *lat, *kv, *ao;
    cudaGetSymbolAddress((void**)&q,   g_q);
    cudaGetSymbolAddress((void**)&lat, g_lat);
    cudaGetSymbolAddress((void**)&kv,  g_kv);
    cudaGetSymbolAddress((void**)&ao,  g_ao);
    __half *xh,*xl,*lath,*latl,*aoh,*aol,*qh,*ql,*k1,*vt;
    __half *WqT,*WkdT,*WkuT,*WoT;
    cudaGetSymbolAddress((void**)&xh, g_xh);     cudaGetSymbolAddress((void**)&xl, g_xl);
    cudaGetSymbolAddress((void**)&lath, g_lath); cudaGetSymbolAddress((void**)&latl, g_latl);
    cudaGetSymbolAddress((void**)&aoh, g_aoh);   cudaGetSymbolAddress((void**)&aol, g_aol);
    cudaGetSymbolAddress((void**)&qh, g_qh);     cudaGetSymbolAddress((void**)&ql, g_ql);
    cudaGetSymbolAddress((void**)&k1, g_k1);     cudaGetSymbolAddress((void**)&vt, g_vt);
    cudaGetSymbolAddress((void**)&WqT, g_WqT);   cudaGetSymbolAddress((void**)&WkdT, g_WkdT);
    cudaGetSymbolAddress((void**)&WkuT, g_WkuT); cudaGetSymbolAddress((void**)&WoT, g_WoT);

    cudaFuncSetAttribute(gemm_mma, cudaFuncAttributeMaxDynamicSharedMemorySize, GEMM_SMEM);
    cudaFuncSetAttribute(attn_mma, cudaFuncAttributeMaxDynamicSharedMemorySize, ATT_SMEM);

    // weight conversions (transpose to [N,K] single fp16)
    conv_wt_T<<<dim3(ATTN_DIM / 32, HIDDEN / 32), 256>>>(Wq,   WqT,  HIDDEN, ATTN_DIM);
    conv_wt_T<<<dim3(KV_RANK / 32, HIDDEN / 32), 256>>>(Wkvd, WkdT, HIDDEN, KV_RANK);
    conv_wt_T<<<dim3(2 * ATTN_DIM / 32, KV_RANK / 32), 256>>>(Wkvu, WkuT, KV_RANK, 2 * ATTN_DIM);
    conv_wt_T<<<dim3(HIDDEN / 32, ATTN_DIM / 32), 256>>>(Wo,   WoT,  ATTN_DIM, HIDDEN);

    // x -> fp16 hi/lo
    {
        int n4 = M_ROWS * HIDDEN / 4;
        conv_act<<<(n4 + 255) / 256, 256>>>((const float4*)x, xh, xl, n4, 1.0f);
    }

    // q = x @ Wq ; lat = x @ Wkv_down
    gemm_mma<<<dim3(ATTN_DIM / 128, M_ROWS / 128), 256, GEMM_SMEM>>>(
        xh, xl, WqT, q, M_ROWS, ATTN_DIM, HIDDEN);
    gemm_mma<<<dim3(KV_RANK / 128, M_ROWS / 128), 256, GEMM_SMEM>>>(
        xh, xl, WkdT, lat, M_ROWS, KV_RANK, HIDDEN);
    rmsnorm_kernel<<<M_ROWS, KV_RANK>>>(lat, knw);
    {
        int n4 = M_ROWS * KV_RANK / 4;
        conv_act<<<(n4 + 255) / 256, 256>>>((const float4*)lat, lath, latl, n4, 1.0f);
    }
    // kv = lat @ Wkv_up
    gemm_mma<<<dim3(2 * ATTN_DIM / 128, M_ROWS / 128), 256, GEMM_SMEM>>>(
        lath, latl, WkuT, kv, M_ROWS, 2 * ATTN_DIM, KV_RANK);

    // attention operand preparation (Q prescaled by 1/sqrt(d))
    {
        int n4 = M_ROWS * ATTN_DIM / 4;
        conv_act<<<(n4 + 255) / 256, 256>>>((const float4*)q, qh, ql, n4,
                                            0.08838834764831845f);
    }
    conv_k<<<(M_ROWS * 512 + 255) / 256, 256>>>(kv, k1);
    conv_vt<<<dim3(SEQ / 32, (HEADS * HEAD_DIM) / 32, BATCH), 256>>>(kv, vt);

    // tensor-core attention
    attn_mma<<<dim3(SEQ / 128, HEADS, BATCH), 256, ATT_SMEM>>>(
        qh, ql, k1, vt, ao);

    // out = ao @ Wo
    {
        int n4 = M_ROWS * ATTN_DIM / 4;
        conv_act<<<(n4 + 255) / 256, 256>>>((const float4*)ao, aoh, aol, n4, 1.0f);
    }
    gemm_mma<<<dim3(HIDDEN / 128, M_ROWS / 128), 256, GEMM_SMEM>>>(
        aoh, aol, WoT, out, M_ROWS, HIDDEN, ATTN_DIM);
}

// round 10
// speedup vs baseline: 4.5674x; 1.1175x over previous
#include <cuda_runtime.h>
#include <cuda_fp16.h>
#include <cstdint>
#include <math.h>

#define HIDDEN   2048
#define HEADS    16
#define HEAD_DIM 128
#define KV_RANK  256
#define ATTN_DIM 2048
#define BATCH    2
#define SEQ      2048
#define M_ROWS   (BATCH * SEQ)   // 4096

// ---------------- scratch (device globals; allocation-free) ----------------
__device__ float g_lat[M_ROWS * KV_RANK];

__device__ __half g_xh [M_ROWS * HIDDEN],   g_xl [M_ROWS * HIDDEN];
__device__ __half g_lath[M_ROWS * KV_RANK], g_latl[M_ROWS * KV_RANK];
__device__ __half g_aoh[M_ROWS * ATTN_DIM], g_aol[M_ROWS * ATTN_DIM];
__device__ __half g_qh [M_ROWS * ATTN_DIM], g_ql [M_ROWS * ATTN_DIM];
__device__ __half g_k1 [M_ROWS * ATTN_DIM];
__device__ __half g_vrm[M_ROWS * ATTN_DIM];                  // V row-major fp16
__device__ __half g_vt [BATCH * HEADS * HEAD_DIM * SEQ];     // V transposed
// weights transposed to [N,K] K-major, single fp16
__device__ __half g_WT1 [(ATTN_DIM + KV_RANK) * HIDDEN];     // [Wq ; Wkv_down] rows
__device__ __half g_WkuT[2 * ATTN_DIM * KV_RANK];
__device__ __half g_WoT [HIDDEN * ATTN_DIM];

// ======================= PTX helpers (baseline ISA) ========================
__device__ __forceinline__ uint32_t smem_u32(const void* p) {
    uint32_t a;
    asm("{ .reg .u64 t; cvta.to.shared.u64 t, %1; cvt.u32.u64 %0, t; }" : "=r"(a) : "l"(p));
    return a;
}
#define CP_ASYNC16(dst, src) \
    asm volatile("cp.async.cg.shared.global [%0], [%1], 16;" :: "r"(dst), "l"(src) : "memory")
#define CP_COMMIT() asm volatile("cp.async.commit_group;" ::: "memory")
#define CP_WAIT(n)  asm volatile("cp.async.wait_group %0;" :: "n"(n) : "memory")

#define LDSM4(r0, r1, r2, r3, a) \
    asm volatile("ldmatrix.sync.aligned.m8n8.x4.shared.b16 {%0,%1,%2,%3}, [%4];" \
        : "=r"(r0), "=r"(r1), "=r"(r2), "=r"(r3) : "r"(a))

__device__ __forceinline__ void mma16816(float* c, const uint32_t* a, const uint32_t* b) {
    asm volatile("mma.sync.aligned.m16n8k16.row.col.f32.f16.f16.f32 "
        "{%0,%1,%2,%3}, {%4,%5,%6,%7}, {%8,%9}, {%0,%1,%2,%3};"
        : "+f"(c[0]), "+f"(c[1]), "+f"(c[2]), "+f"(c[3])
        : "r"(a[0]), "r"(a[1]), "r"(a[2]), "r"(a[3]), "r"(b[0]), "r"(b[1]));
}
__device__ __forceinline__ uint32_t pack_hf2(float a, float b) {
    __half2 t = __floats2half2_rn(a, b);
    return *(uint32_t*)&t;
}
// split pair: hi halves + residual lo halves
__device__ __forceinline__ void split2(float a, float b, __half2& h, __half2& l) {
    __half ha = __float2half_rn(a), hb = __float2half_rn(b);
    h = __halves2half2(ha, hb);
    l = __floats2half2_rn(a - __half2float(ha), b - __half2float(hb));
}

// ======================= conversion kernels ================================
// fp32 -> fp16 hi/lo
__global__ __launch_bounds__(256) void conv_act(const float4* __restrict__ in,
                                                __half* __restrict__ h,
                                                __half* __restrict__ l, int n4)
{
    int i = blockIdx.x * blockDim.x + threadIdx.x;
    if (i >= n4) return;
    float4 x = in[i];
    __half2 h0, l0, h1, l1;
    split2(x.x, x.y, h0, l0);
    split2(x.z, x.w, h1, l1);
    ((__half2*)h)[i * 2 + 0] = h0;
    ((__half2*)h)[i * 2 + 1] = h1;
    ((__half2*)l)[i * 2 + 0] = l0;
    ((__half2*)l)[i * 2 + 1] = l1;
}

// fp16 V row-major -> transposed: VT[(b*2048 + hd) * 2048 + s]
__global__ __launch_bounds__(256) void conv_vt_h(const __half* __restrict__ V,
                                                 __half* __restrict__ T)
{
    __shared__ __half t[32][40];
    const int s0  = blockIdx.x * 32;
    const int hd0 = blockIdx.y * 32;
    const int b   = blockIdx.z;
    const int tid = threadIdx.x;
    for (int i = tid; i < 1024; i += 256) {
        int ss = i >> 5, dd = i & 31;
        t[ss][dd] = V[(size_t)(b * SEQ + s0 + ss) * 2048 + hd0 + dd];
    }
    __syncthreads();
    for (int i = tid; i < 512; i += 256) {
        int dd = i >> 4, sp = (i & 15) * 2;
        size_t o = (size_t)(b * 2048 + hd0 + dd) * 2048 + s0 + sp;
        *(__half2*)&T[o] = __halves2half2(t[sp][dd], t[sp + 1][dd]);
    }
}

// W [K,N] fp32 -> T [N,K] single fp16 (K-major); T may be an offset pointer
__global__ __launch_bounds__(256) void conv_wt_T(const float* __restrict__ W,
                                                 __half* __restrict__ Th,
                                                 int K, int N)
{
    __shared__ float t[32][33];
    const int n0 = blockIdx.x * 32, k0 = blockIdx.y * 32;
    const int tid = threadIdx.x;
    for (int i = tid; i < 1024; i += 256) {
        int kk = i >> 5, nn = i & 31;
        t[kk][nn] = W[(size_t)(k0 + kk) * N + n0 + nn];
    }
    __syncthreads();
    for (int i = tid; i < 512; i += 256) {
        int nn = i >> 4, kp = (i & 15) * 2;
        *(__half2*)&Th[(size_t)(n0 + nn) * K + k0 + kp] =
            __floats2half2_rn(t[kp][nn], t[kp + 1][nn]);
    }
}

// ======================= mma.sync fp16 GEMM (2-term, ldmatrix) =============
// C = (Ah+Al)[M,K] @ B[N,K]^T. Epilogue by MODE:
//   0: fp32 out Cf (stride N)
//   1: cols<2048 -> fp16 hi/lo (Oh/Ol, stride 2048, scaled by sc); cols>=2048 -> fp32 Cf stride 256
//   2: cols<2048 -> fp16 single Oh (stride 2048); cols>=2048 -> fp16 single O2 (stride 2048)
#define GEMM_SMEM (2 * 30720)
template<int MODE>
__global__ __launch_bounds__(256, 2) void gemm_mma(
    const __half* __restrict__ Ah, const __half* __restrict__ Al,
    const __half* __restrict__ Bw,
    float* __restrict__ Cf, __half* __restrict__ Oh, __half* __restrict__ Ol,
    __half* __restrict__ O2,
    int M, int N, int K, float sc)
{
    extern __shared__ char smem[];
    const uint32_t sbase = smem_u32(smem);
    const int tid  = threadIdx.x;
    const int lane = tid & 31;
    const int w    = tid >> 5;
    const int bm = blockIdx.y * 128;
    const int bn = blockIdx.x * 128;
    const int wm = (w & 3) * 32;
    const int wn = (w >> 2) * 64;
    const int qr = lane >> 2;
    const int qc = lane & 3;

    const __half* srcs[3] = { Ah, Al, Bw };
    const int rowoff[3] = { bm, bm, bn };

    const uint32_t lm = (uint32_t)(lane & 15) * 80 + (uint32_t)(lane >> 4) * 16;

    float acc[2][8][4];
#pragma unroll
    for (int mf = 0; mf < 2; ++mf)
#pragma unroll
        for (int nf = 0; nf < 8; ++nf)
#pragma unroll
            for (int e = 0; e < 4; ++e) acc[mf][nf][e] = 0.f;

    const int NC = K >> 5;

    auto issue = [&](int c) {
        const uint32_t st = sbase + (c & 1) * 30720;
        const int k0 = c << 5;
#pragma unroll
        for (int i = 0; i < 6; ++i) {
            const int mat = i >> 1;
            const int sub = ((i & 1) << 8) + tid;
            const int r = sub >> 2, v = sub & 3;
            const void* g = srcs[mat] + (size_t)(rowoff[mat] + r) * K + k0 + v * 8;
            CP_ASYNC16(st + mat * 10240 + r * 80 + v * 16, g);
        }
        CP_COMMIT();
    };

    issue(0);

    for (int c = 0; c < NC; ++c) {
        if (c + 1 < NC) { issue(c + 1); CP_WAIT(1); }
        else            { CP_WAIT(0); }
        __syncthreads();

        const uint32_t st = sbase + (c & 1) * 30720;
        const uint32_t aAh = st + wm * 80 + lm;
        const uint32_t aAl = st + 10240 + wm * 80 + lm;
        const uint32_t aB  = st + 20480 + wn * 80 + lm;

#pragma unroll
        for (int ks = 0; ks < 2; ++ks) {
            const uint32_t kb = ks * 32;
            uint32_t ah[2][4], al[2][4];
            LDSM4(ah[0][0], ah[0][1], ah[0][2], ah[0][3], aAh + kb);
            LDSM4(ah[1][0], ah[1][1], ah[1][2], ah[1][3], aAh + 16 * 80 + kb);
            LDSM4(al[0][0], al[0][1], al[0][2], al[0][3], aAl + kb);
            LDSM4(al[1][0], al[1][1], al[1][2], al[1][3], aAl + 16 * 80 + kb);
#pragma unroll
            for (int np = 0; np < 4; ++np) {
                uint32_t h0, h1, h2, h3;
                LDSM4(h0, h1, h2, h3, aB + (uint32_t)(np * 16) * 80 + kb);
                uint32_t be[2] = { h0, h2 }, bo[2] = { h1, h3 };
#pragma unroll
                for (int mf = 0; mf < 2; ++mf) {
                    mma16816(acc[mf][2 * np],     ah[mf], be);
                    mma16816(acc[mf][2 * np],     al[mf], be);
                    mma16816(acc[mf][2 * np + 1], ah[mf], bo);
                    mma16816(acc[mf][2 * np + 1], al[mf], bo);
                }
            }
        }
        __syncthreads();
    }

    // ---- epilogue ----
#pragma unroll
    for (int mf = 0; mf < 2; ++mf) {
        const int r0 = bm + wm + mf * 16 + qr;
        const int r1 = r0 + 8;
#pragma unroll
        for (int nf = 0; nf < 8; ++nf) {
            const int col = bn + wn + nf * 8 + qc * 2;
            float a0 = acc[mf][nf][0], a1 = acc[mf][nf][1];
            float a2 = acc[mf][nf][2], a3 = acc[mf][nf][3];
            if (MODE == 0) {
                *(float2*)&Cf[(size_t)r0 * N + col] = make_float2(a0, a1);
                *(float2*)&Cf[(size_t)r1 * N + col] = make_float2(a2, a3);
            } else if (MODE == 1) {
                if (col < 2048) {
                    a0 *= sc; a1 *= sc; a2 *= sc; a3 *= sc;
                    __half2 h, l;
                    split2(a0, a1, h, l);
                    *(__half2*)&Oh[(size_t)r0 * 2048 + col] = h;
                    *(__half2*)&Ol[(size_t)r0 * 2048 + col] = l;
                    split2(a2, a3, h, l);
                    *(__half2*)&Oh[(size_t)r1 * 2048 + col] = h;
                    *(__half2*)&Ol[(size_t)r1 * 2048 + col] = l;
                } else {
                    const int cl = col - 2048;
                    *(float2*)&Cf[(size_t)r0 * KV_RANK + cl] = make_float2(a0, a1);
                    *(float2*)&Cf[(size_t)r1 * KV_RANK + cl] = make_float2(a2, a3);
                }
            } else {   // MODE 2
                if (col < 2048) {
                    *(__half2*)&Oh[(size_t)r0 * 2048 + col] = __floats2half2_rn(a0, a1);
                    *(__half2*)&Oh[(size_t)r1 * 2048 + col] = __floats2half2_rn(a2, a3);
                } else {
                    const int cl = col - 2048;
                    *(__half2*)&O2[(size_t)r0 * 2048 + cl] = __floats2half2_rn(a0, a1);
                    *(__half2*)&O2[(size_t)r1 * 2048 + cl] = __floats2half2_rn(a2, a3);
                }
            }
        }
    }
}

// ---------------- RMSNorm over last dim (256) -> fp16 hi/lo ----------------
__global__ __launch_bounds__(256) void rmsnorm_kernel(
    const float* __restrict__ lat, const float* __restrict__ w,
    __half* __restrict__ lh, __half* __restrict__ ll)
{
    const int row = blockIdx.x;
    const int tid = threadIdx.x;
    float v = lat[(size_t)row * KV_RANK + tid];
    float ss = v * v;
#pragma unroll
    for (int o = 16; o; o >>= 1) ss += __shfl_xor_sync(0xffffffffu, ss, o);
    __shared__ float red[8];
    if ((tid & 31) == 0) red[tid >> 5] = ss;
    __syncthreads();
    float tot = red[0] + red[1] + red[2] + red[3] + red[4] + red[5] + red[6] + red[7];
    float r = rsqrtf(tot * (1.0f / KV_RANK) + 1e-6f);
    float nv = w[tid] * v * r;
    __half h = __float2half_rn(nv);
    lh[(size_t)row * KV_RANK + tid] = h;
    ll[(size_t)row * KV_RANK + tid] = __float2half_rn(nv - __half2float(h));
}

// ============ tensor-core flash attention (fp16 2-term, ldmatrix) ==========
#define ATT_SMEM 141312
__global__ __launch_bounds__(256, 1) void attn_mma(
    const __half* __restrict__ Qh, const __half* __restrict__ Ql,
    const __half* __restrict__ Kg, const __half* __restrict__ VT,
    __half* __restrict__ Ohg, __half* __restrict__ Olg)
{
    extern __shared__ char smA[];
    const uint32_t sb = smem_u32(smA);
    const int tid = threadIdx.x;
    const int w = tid >> 5, lane = tid & 31;
    const int qr = lane >> 2, qc = lane & 3;
    const int qb = blockIdx.x, h = blockIdx.y, b = blockIdx.z;
    const int q0 = qb * 128;

    const uint32_t oQl = 34816, oStage = 69632, stSz = 35840;

    const uint32_t lmK = (uint32_t)(lane & 15) * 272 + (uint32_t)(lane >> 4) * 16;
    const uint32_t lmV = (uint32_t)(lane & 15) * 144 + (uint32_t)(lane >> 4) * 16;
    const uint32_t lmQ = (uint32_t)(w * 16) * 272 + lmK;

    // ---- Q tile load (hi/lo) ----
#pragma unroll
    for (int i = 0; i < 16; ++i) {
        int idx = tid + i * 256;
        int mat = idx >> 11, r = (idx >> 4) & 127, v = idx & 15;
        const __half* g = (mat ? Ql : Qh) +
            (size_t)(b * SEQ + q0 + r) * 2048 + h * HEAD_DIM + v * 8;
        CP_ASYNC16(sb + (mat ? oQl : 0u) + r * 272 + v * 16, g);
    }
    CP_COMMIT();

    auto issue = [&](int kt) {
        const int k0 = kt * 64;
        const uint32_t st = sb + oStage + (kt & 1) * stSz;
#pragma unroll
        for (int i = 0; i < 4; ++i) {
            int idx = tid + i * 256;
            int r = idx >> 4, v = idx & 15;
            const __half* g = Kg + (size_t)(b * SEQ + k0 + r) * 2048 + h * HEAD_DIM + v * 8;
            CP_ASYNC16(st + r * 272 + v * 16, g);
        }
#pragma unroll
        for (int i = 0; i < 4; ++i) {
            int idx = tid + i * 256;
            int d = idx >> 3, v = idx & 7;
            const __half* g = VT + (size_t)((b * HEADS + h) * HEAD_DIM + d) * 2048 + k0 + v * 8;
            CP_ASYNC16(st + 17408 + d * 144 + v * 16, g);
        }
        CP_COMMIT();
    };

    float m0 = -1e30f, m1 = -1e30f, l0 = 0.f, l1 = 0.f;
    float acc[16][4];
#pragma unroll
    for (int nt = 0; nt < 16; ++nt)
#pragma unroll
        for (int e = 0; e < 4; ++e) acc[nt][e] = 0.f;

    const int ntk = 2 * (qb + 1);
    issue(0);

    for (int kt = 0; kt < ntk; ++kt) {
        if (kt + 1 < ntk) { issue(kt + 1); CP_WAIT(1); }
        else              { CP_WAIT(0); }
        __syncthreads();

        const uint32_t st  = sb + oStage + (kt & 1) * stSz;
        const uint32_t aK  = st + lmK;
        const uint32_t aV  = st + 17408 + lmV;
        const uint32_t aQh = sb + lmQ;
        const uint32_t aQl = sb + oQl + lmQ;

        // ---- S = Q K^T (2 terms) ----
        float sfr[8][4];
#pragma unroll
        for (int nt = 0; nt < 8; ++nt)
#pragma unroll
            for (int e = 0; e < 4; ++e) sfr[nt][e] = 0.f;

#pragma unroll
        for (int ks = 0; ks < 8; ++ks) {
            const uint32_t kb = ks * 32;
            uint32_t ah[4], al[4];
            LDSM4(ah[0], ah[1], ah[2], ah[3], aQh + kb);
            LDSM4(al[0], al[1], al[2], al[3], aQl + kb);
#pragma unroll
            for (int np = 0; np < 4; ++np) {
                uint32_t h0, h1, h2, h3;
                LDSM4(h0, h1, h2, h3, aK + (uint32_t)(np * 16) * 272 + kb);
                uint32_t be[2] = { h0, h2 }, bo[2] = { h1, h3 };
                mma16816(sfr[2 * np],     ah, be);
                mma16816(sfr[2 * np],     al, be);
                mma16816(sfr[2 * np + 1], ah, bo);
                mma16816(sfr[2 * np + 1], al, bo);
            }
        }

        // ---- mask + online softmax ----
        const int i0 = q0 + w * 16 + qr;
        const int i1 = i0 + 8;
        const int k0 = kt * 64;
#pragma unroll
        for (int nt = 0; nt < 8; ++nt) {
            const int j = k0 + nt * 8 + 2 * qc;
            if (j     > i0) sfr[nt][0] = -1e30f;
            if (j + 1 > i0) sfr[nt][1] = -1e30f;
            if (j     > i1) sfr[nt][2] = -1e30f;
            if (j + 1 > i1) sfr[nt][3] = -1e30f;
        }
        float mx0 = -1e30f, mx1 = -1e30f;
#pragma unroll
        for (int nt = 0; nt < 8; ++nt) {
            mx0 = fmaxf(mx0, fmaxf(sfr[nt][0], sfr[nt][1]));
            mx1 = fmaxf(mx1, fmaxf(sfr[nt][2], sfr[nt][3]));
        }
        mx0 = fmaxf(mx0, __shfl_xor_sync(0xffffffffu, mx0, 1));
        mx0 = fmaxf(mx0, __shfl_xor_sync(0xffffffffu, mx0, 2));
        mx1 = fmaxf(mx1, __shfl_xor_sync(0xffffffffu, mx1, 1));
        mx1 = fmaxf(mx1, __shfl_xor_sync(0xffffffffu, mx1, 2));
        const float mn0 = fmaxf(m0, mx0), mn1 = fmaxf(m1, mx1);
        const float c0 = __expf(m0 - mn0), c1 = __expf(m1 - mn1);
        m0 = mn0; m1 = mn1;
        l0 *= c0;  l1 *= c1;

        uint32_t pa[4][4], pl[4][4];
        float rs0 = 0.f, rs1 = 0.f;
#pragma unroll
        for (int nt = 0; nt < 8; ++nt) {
            float p0 = __expf(sfr[nt][0] - mn0);
            float p1 = __expf(sfr[nt][1] - mn0);
            float p2 = __expf(sfr[nt][2] - mn1);
            float p3 = __expf(sfr[nt][3] - mn1);
            rs0 += p0 + p1; rs1 += p2 + p3;
            uint32_t h01 = pack_hf2(p0, p1);
            uint32_t h23 = pack_hf2(p2, p3);
            __half2 hb01 = *(__half2*)&h01;
            __half2 hb23 = *(__half2*)&h23;
            uint32_t r01 = pack_hf2(p0 - __half2float(__low2half(hb01)),
                                    p1 - __half2float(__high2half(hb01)));
            uint32_t r23 = pack_hf2(p2 - __half2float(__low2half(hb23)),
                                    p3 - __half2float(__high2half(hb23)));
            const int ks = nt >> 1, half = nt & 1;
            if (half == 0) { pa[ks][0] = h01; pa[ks][1] = h23; pl[ks][0] = r01; pl[ks][1] = r23; }
            else           { pa[ks][2] = h01; pa[ks][3] = h23; pl[ks][2] = r01; pl[ks][3] = r23; }
        }
        rs0 += __shfl_xor_sync(0xffffffffu, rs0, 1);
        rs0 += __shfl_xor_sync(0xffffffffu, rs0, 2);
        rs1 += __shfl_xor_sync(0xffffffffu, rs1, 1);
        rs1 += __shfl_xor_sync(0xffffffffu, rs1, 2);
        l0 += rs0; l1 += rs1;

#pragma unroll
        for (int nt = 0; nt < 16; ++nt) {
            acc[nt][0] *= c0; acc[nt][1] *= c0;
            acc[nt][2] *= c1; acc[nt][3] *= c1;
        }

        // ---- O += P V (2 terms) ----
#pragma unroll
        for (int ks = 0; ks < 4; ++ks) {
            const uint32_t kb = ks * 32;
#pragma unroll
            for (int dp = 0; dp < 8; ++dp) {
                uint32_t h0, h1, h2, h3;
                LDSM4(h0, h1, h2, h3, aV + (uint32_t)(dp * 16) * 144 + kb);
                uint32_t be[2] = { h0, h2 }, bo[2] = { h1, h3 };
                mma16816(acc[2 * dp],     pa[ks], be);
                mma16816(acc[2 * dp],     pl[ks], be);
                mma16816(acc[2 * dp + 1], pa[ks], bo);
                mma16816(acc[2 * dp + 1], pl[ks], bo);
            }
        }
        __syncthreads();
    }

    // ---- epilogue: write fp16 hi/lo directly ----
    const float inv0 = 1.0f / l0, inv1 = 1.0f / l1;
    const size_t r0 = (size_t)(b * SEQ + q0 + w * 16 + qr);
    const size_t r1 = r0 + 8;
#pragma unroll
    for (int nt = 0; nt < 16; ++nt) {
        const int col = h * HEAD_DIM + nt * 8 + 2 * qc;
        __half2 hh, ll;
        split2(acc[nt][0] * inv0, acc[nt][1] * inv0, hh, ll);
        *(__half2*)&Ohg[r0 * 2048 + col] = hh;
        *(__half2*)&Olg[r0 * 2048 + col] = ll;
        split2(acc[nt][2] * inv1, acc[nt][3] * inv1, hh, ll);
        *(__half2*)&Ohg[r1 * 2048 + col] = hh;
        *(__half2*)&Olg[r1 * 2048 + col] = ll;
    }
}

// ---------------------------------------------------------------------------
extern "C" void kernel_launch(void* const* d_in, const int* in_sizes, int n_in,
                              void* d_out, int out_size)
{
    const float* x    = (const float*)d_in[0];
    const float* Wq   = (const float*)d_in[1];
    const float* Wkvd = (const float*)d_in[2];
    const float* knw  = (const float*)d_in[3];
    const float* Wkvu = (const float*)d_in[4];
    const float* Wo   = (const float*)d_in[5];
    float* out = (float*)d_out;

    float* lat;
    cudaGetSymbolAddress((void**)&lat, g_lat);
    __half *xh,*xl,*lath,*latl,*aoh,*aol,*qh,*ql,*k1,*vrm,*vt;
    __half *WT1,*WkuT,*WoT;
    cudaGetSymbolAddress((void**)&xh, g_xh);     cudaGetSymbolAddress((void**)&xl, g_xl);
    cudaGetSymbolAddress((void**)&lath, g_lath); cudaGetSymbolAddress((void**)&latl, g_latl);
    cudaGetSymbolAddress((void**)&aoh, g_aoh);   cudaGetSymbolAddress((void**)&aol, g_aol);
    cudaGetSymbolAddress((void**)&qh, g_qh);     cudaGetSymbolAddress((void**)&ql, g_ql);
    cudaGetSymbolAddress((void**)&k1, g_k1);     cudaGetSymbolAddress((void**)&vrm, g_vrm);
    cudaGetSymbolAddress((void**)&vt, g_vt);
    cudaGetSymbolAddress((void**)&WT1, g_WT1);
    cudaGetSymbolAddress((void**)&WkuT, g_WkuT); cudaGetSymbolAddress((void**)&WoT, g_WoT);

    cudaFuncSetAttribute(gemm_mma<0>, cudaFuncAttributeMaxDynamicSharedMemorySize, GEMM_SMEM);
    cudaFuncSetAttribute(gemm_mma<1>, cudaFuncAttributeMaxDynamicSharedMemorySize, GEMM_SMEM);
    cudaFuncSetAttribute(gemm_mma<2>, cudaFuncAttributeMaxDynamicSharedMemorySize, GEMM_SMEM);
    cudaFuncSetAttribute(attn_mma, cudaFuncAttributeMaxDynamicSharedMemorySize, ATT_SMEM);

    // weight conversions: WT1 = [WqT rows 0..2047 ; WkdT rows 2048..2303]
    conv_wt_T<<<dim3(ATTN_DIM / 32, HIDDEN / 32), 256>>>(Wq, WT1, HIDDEN, ATTN_DIM);
    conv_wt_T<<<dim3(KV_RANK / 32, HIDDEN / 32), 256>>>(
        Wkvd, WT1 + (size_t)ATTN_DIM * HIDDEN, HIDDEN, KV_RANK);
    conv_wt_T<<<dim3(2 * ATTN_DIM / 32, KV_RANK / 32), 256>>>(Wkvu, WkuT, KV_RANK, 2 * ATTN_DIM);
    conv_wt_T<<<dim3(HIDDEN / 32, ATTN_DIM / 32), 256>>>(Wo, WoT, ATTN_DIM, HIDDEN);

    // x -> fp16 hi/lo
    {
        int n4 = M_ROWS * HIDDEN / 4;
        conv_act<<<(n4 + 255) / 256, 256>>>((const float4*)x, xh, xl, n4);
    }

    // fused q+lat GEMM: N=2304; q cols -> qh/ql (scaled), lat cols -> fp32
    gemm_mma<1><<<dim3((ATTN_DIM + KV_RANK) / 128, M_ROWS / 128), 256, GEMM_SMEM>>>(
        xh, xl, WT1, lat, qh, ql, nullptr,
        M_ROWS, ATTN_DIM + KV_RANK, HIDDEN, 0.08838834764831845f);

    // rmsnorm -> fp16 hi/lo directly
    rmsnorm_kernel<<<M_ROWS, KV_RANK>>>(lat, knw, lath, latl);

    // kv GEMM: K half -> k1 fp16, V half -> vrm fp16 (row-major)
    gemm_mma<2><<<dim3(2 * ATTN_DIM / 128, M_ROWS / 128), 256, GEMM_SMEM>>>(
        lath, latl, WkuT, nullptr, k1, nullptr, vrm,
        M_ROWS, 2 * ATTN_DIM, KV_RANK, 1.0f);

    // V transpose (fp16 -> fp16)
    conv_vt_h<<<dim3(SEQ / 32, (HEADS * HEAD_DIM) / 32, BATCH), 256>>>(vrm, vt);

    // tensor-core attention -> aoh/aol fp16 hi/lo directly
    attn_mma<<<dim3(SEQ / 128, HEADS, BATCH), 256, ATT_SMEM>>>(
        qh, ql, k1, vt, aoh, aol);

    // out = ao @ Wo (fp32 out)
    gemm_mma<0><<<dim3(HIDDEN / 128, M_ROWS / 128), 256, GEMM_SMEM>>>(
        aoh, aol, WoT, out, nullptr, nullptr, nullptr,
        M_ROWS, HIDDEN, ATTN_DIM, 1.0f);
}

// round 11
// speedup vs baseline: 5.3492x; 1.1712x over previous
#include <cuda_runtime.h>
#include <cuda_fp16.h>
#include <cstdint>
#include <math.h>

#define HIDDEN   2048
#define HEADS    16
#define HEAD_DIM 128
#define KV_RANK  256
#define ATTN_DIM 2048
#define BATCH    2
#define SEQ      2048
#define M_ROWS   (BATCH * SEQ)   // 4096

// ---------------- scratch (device globals; allocation-free) ----------------
__device__ float g_lat[M_ROWS * KV_RANK];

__device__ __half g_xh [M_ROWS * HIDDEN],   g_xl [M_ROWS * HIDDEN];
__device__ __half g_lath[M_ROWS * KV_RANK], g_latl[M_ROWS * KV_RANK];
__device__ __half g_aoh[M_ROWS * ATTN_DIM], g_aol[M_ROWS * ATTN_DIM];
__device__ __half g_qh [M_ROWS * ATTN_DIM], g_ql [M_ROWS * ATTN_DIM];
__device__ __half g_k1 [M_ROWS * ATTN_DIM];
__device__ __half g_vrm[M_ROWS * ATTN_DIM];                  // V row-major fp16
__device__ __half g_vt [BATCH * HEADS * HEAD_DIM * SEQ];     // V transposed
// weights transposed to [N,K] K-major, single fp16
__device__ __half g_WT1 [(ATTN_DIM + KV_RANK) * HIDDEN];     // [Wq ; Wkv_down] rows
__device__ __half g_WkuT[2 * ATTN_DIM * KV_RANK];
__device__ __half g_WoT [HIDDEN * ATTN_DIM];

// ======================= PTX helpers (baseline ISA) ========================
__device__ __forceinline__ uint32_t smem_u32(const void* p) {
    uint32_t a;
    asm("{ .reg .u64 t; cvta.to.shared.u64 t, %1; cvt.u32.u64 %0, t; }" : "=r"(a) : "l"(p));
    return a;
}
#define CP_ASYNC16(dst, src) \
    asm volatile("cp.async.cg.shared.global [%0], [%1], 16;" :: "r"(dst), "l"(src) : "memory")
#define CP_COMMIT() asm volatile("cp.async.commit_group;" ::: "memory")
#define CP_WAIT(n)  asm volatile("cp.async.wait_group %0;" :: "n"(n) : "memory")

#define LDSM4(r0, r1, r2, r3, a) \
    asm volatile("ldmatrix.sync.aligned.m8n8.x4.shared.b16 {%0,%1,%2,%3}, [%4];" \
        : "=r"(r0), "=r"(r1), "=r"(r2), "=r"(r3) : "r"(a))

__device__ __forceinline__ void mma16816(float* c, const uint32_t* a, const uint32_t* b) {
    asm volatile("mma.sync.aligned.m16n8k16.row.col.f32.f16.f16.f32 "
        "{%0,%1,%2,%3}, {%4,%5,%6,%7}, {%8,%9}, {%0,%1,%2,%3};"
        : "+f"(c[0]), "+f"(c[1]), "+f"(c[2]), "+f"(c[3])
        : "r"(a[0]), "r"(a[1]), "r"(a[2]), "r"(a[3]), "r"(b[0]), "r"(b[1]));
}
__device__ __forceinline__ uint32_t pack_hf2(float a, float b) {
    __half2 t = __floats2half2_rn(a, b);
    return *(uint32_t*)&t;
}
__device__ __forceinline__ void split2(float a, float b, __half2& h, __half2& l) {
    __half ha = __float2half_rn(a), hb = __float2half_rn(b);
    h = __halves2half2(ha, hb);
    l = __floats2half2_rn(a - __half2float(ha), b - __half2float(hb));
}

// ======================= conversion kernels ================================
__global__ __launch_bounds__(256) void conv_act(const float4* __restrict__ in,
                                                __half* __restrict__ h,
                                                __half* __restrict__ l, int n4)
{
    int i = blockIdx.x * blockDim.x + threadIdx.x;
    if (i >= n4) return;
    float4 x = in[i];
    __half2 h0, l0, h1, l1;
    split2(x.x, x.y, h0, l0);
    split2(x.z, x.w, h1, l1);
    ((__half2*)h)[i * 2 + 0] = h0;
    ((__half2*)h)[i * 2 + 1] = h1;
    ((__half2*)l)[i * 2 + 0] = l0;
    ((__half2*)l)[i * 2 + 1] = l1;
}

// fp16 V row-major -> transposed: VT[(b*2048 + hd) * 2048 + s]
__global__ __launch_bounds__(256) void conv_vt_h(const __half* __restrict__ V,
                                                 __half* __restrict__ T)
{
    __shared__ __half t[32][40];
    const int s0  = blockIdx.x * 32;
    const int hd0 = blockIdx.y * 32;
    const int b   = blockIdx.z;
    const int tid = threadIdx.x;
    for (int i = tid; i < 1024; i += 256) {
        int ss = i >> 5, dd = i & 31;
        t[ss][dd] = V[(size_t)(b * SEQ + s0 + ss) * 2048 + hd0 + dd];
    }
    __syncthreads();
    for (int i = tid; i < 512; i += 256) {
        int dd = i >> 4, sp = (i & 15) * 2;
        size_t o = (size_t)(b * 2048 + hd0 + dd) * 2048 + s0 + sp;
        *(__half2*)&T[o] = __halves2half2(t[sp][dd], t[sp + 1][dd]);
    }
}

// W [K,N] fp32 -> T [N,K] single fp16 (K-major). 32k x 128n tiles, vectorized.
__global__ __launch_bounds__(256) void conv_wt_T(const float* __restrict__ W,
                                                 __half* __restrict__ Th,
                                                 int K, int N)
{
    __shared__ float t[32][129];
    const int n0 = blockIdx.x * 128, k0 = blockIdx.y * 32;
    const int tid = threadIdx.x;
#pragma unroll
    for (int i = 0; i < 4; ++i) {
        int idx = tid + i * 256;
        int r = idx >> 5, c4 = (idx & 31) * 4;
        float4 v = *(const float4*)&W[(size_t)(k0 + r) * N + n0 + c4];
        t[r][c4 + 0] = v.x; t[r][c4 + 1] = v.y;
        t[r][c4 + 2] = v.z; t[r][c4 + 3] = v.w;
    }
    __syncthreads();
#pragma unroll
    for (int i = 0; i < 2; ++i) {
        int idx = tid + i * 256;
        int n = idx >> 2, kh = (idx & 3) * 8;
        uint4 u;
        uint32_t* up = (uint32_t*)&u;
#pragma unroll
        for (int j = 0; j < 4; ++j) {
            __half2 o = __floats2half2_rn(t[kh + 2 * j][n], t[kh + 2 * j + 1][n]);
            up[j] = *(uint32_t*)&o;
        }
        *(uint4*)&Th[(size_t)(n0 + n) * K + k0 + kh] = u;
    }
}

// ======================= mma.sync fp16 GEMM (ldmatrix) =====================
// C = A[M,K] @ B[N,K]^T. SPLITA: A = Ah + Al (2 MMA terms) else single Ah.
// MODE 0: fp32 out Cf (stride N)
// MODE 1: cols<2048 -> fp16 hi/lo (Oh/Ol, stride 2048, scaled); else fp32 Cf stride 256
// MODE 2: cols<2048 -> fp16 Oh (stride 2048); else fp16 O2 (stride 2048)
template<int MODE, bool SPLITA>
__global__ __launch_bounds__(256, 2) void gemm_mma(
    const __half* __restrict__ Ah, const __half* __restrict__ Al,
    const __half* __restrict__ Bw,
    float* __restrict__ Cf, __half* __restrict__ Oh, __half* __restrict__ Ol,
    __half* __restrict__ O2,
    int M, int N, int K, float sc)
{
    constexpr int NMAT = SPLITA ? 3 : 2;
    constexpr uint32_t STAGE = NMAT * 10240;

    extern __shared__ char smem[];
    const uint32_t sbase = smem_u32(smem);
    const int tid  = threadIdx.x;
    const int lane = tid & 31;
    const int w    = tid >> 5;
    const int bm = blockIdx.y * 128;
    const int bn = blockIdx.x * 128;
    const int wm = (w & 3) * 32;
    const int wn = (w >> 2) * 64;
    const int qr = lane >> 2;
    const int qc = lane & 3;

    const __half* srcs[3] = { Ah, SPLITA ? Al : Bw, Bw };
    const int rowoff[3] = { bm, SPLITA ? bm : bn, bn };

    const uint32_t lm = (uint32_t)(lane & 15) * 80 + (uint32_t)(lane >> 4) * 16;

    float acc[2][8][4];
#pragma unroll
    for (int mf = 0; mf < 2; ++mf)
#pragma unroll
        for (int nf = 0; nf < 8; ++nf)
#pragma unroll
            for (int e = 0; e < 4; ++e) acc[mf][nf][e] = 0.f;

    const int NC = K >> 5;

    auto issue = [&](int c) {
        const uint32_t st = sbase + (c & 1) * STAGE;
        const int k0 = c << 5;
#pragma unroll
        for (int i = 0; i < 2 * NMAT; ++i) {
            const int mat = i >> 1;
            const int sub = ((i & 1) << 8) + tid;
            const int r = sub >> 2, v = sub & 3;
            const void* g = srcs[mat] + (size_t)(rowoff[mat] + r) * K + k0 + v * 8;
            CP_ASYNC16(st + mat * 10240 + r * 80 + v * 16, g);
        }
        CP_COMMIT();
    };

    issue(0);

    for (int c = 0; c < NC; ++c) {
        if (c + 1 < NC) { issue(c + 1); CP_WAIT(1); }
        else            { CP_WAIT(0); }
        __syncthreads();

        const uint32_t st = sbase + (c & 1) * STAGE;
        const uint32_t aAh = st + wm * 80 + lm;
        const uint32_t aAl = st + 10240 + wm * 80 + lm;
        const uint32_t aB  = st + (NMAT - 1) * 10240 + wn * 80 + lm;

#pragma unroll
        for (int ks = 0; ks < 2; ++ks) {
            const uint32_t kb = ks * 32;
            uint32_t ah[2][4], al[2][4];
            LDSM4(ah[0][0], ah[0][1], ah[0][2], ah[0][3], aAh + kb);
            LDSM4(ah[1][0], ah[1][1], ah[1][2], ah[1][3], aAh + 16 * 80 + kb);
            if (SPLITA) {
                LDSM4(al[0][0], al[0][1], al[0][2], al[0][3], aAl + kb);
                LDSM4(al[1][0], al[1][1], al[1][2], al[1][3], aAl + 16 * 80 + kb);
            }
#pragma unroll
            for (int np = 0; np < 4; ++np) {
                uint32_t h0, h1, h2, h3;
                LDSM4(h0, h1, h2, h3, aB + (uint32_t)(np * 16) * 80 + kb);
                uint32_t be[2] = { h0, h2 }, bo[2] = { h1, h3 };
#pragma unroll
                for (int mf = 0; mf < 2; ++mf) {
                    mma16816(acc[mf][2 * np],     ah[mf], be);
                    mma16816(acc[mf][2 * np + 1], ah[mf], bo);
                    if (SPLITA) {
                        mma16816(acc[mf][2 * np],     al[mf], be);
                        mma16816(acc[mf][2 * np + 1], al[mf], bo);
                    }
                }
            }
        }
        __syncthreads();
    }

    // ---- epilogue ----
#pragma unroll
    for (int mf = 0; mf < 2; ++mf) {
        const int r0 = bm + wm + mf * 16 + qr;
        const int r1 = r0 + 8;
#pragma unroll
        for (int nf = 0; nf < 8; ++nf) {
            const int col = bn + wn + nf * 8 + qc * 2;
            float a0 = acc[mf][nf][0], a1 = acc[mf][nf][1];
            float a2 = acc[mf][nf][2], a3 = acc[mf][nf][3];
            if (MODE == 0) {
                *(float2*)&Cf[(size_t)r0 * N + col] = make_float2(a0, a1);
                *(float2*)&Cf[(size_t)r1 * N + col] = make_float2(a2, a3);
            } else if (MODE == 1) {
                if (col < 2048) {
                    a0 *= sc; a1 *= sc; a2 *= sc; a3 *= sc;
                    __half2 h, l;
                    split2(a0, a1, h, l);
                    *(__half2*)&Oh[(size_t)r0 * 2048 + col] = h;
                    *(__half2*)&Ol[(size_t)r0 * 2048 + col] = l;
                    split2(a2, a3, h, l);
                    *(__half2*)&Oh[(size_t)r1 * 2048 + col] = h;
                    *(__half2*)&Ol[(size_t)r1 * 2048 + col] = l;
                } else {
                    const int cl = col - 2048;
                    *(float2*)&Cf[(size_t)r0 * KV_RANK + cl] = make_float2(a0, a1);
                    *(float2*)&Cf[(size_t)r1 * KV_RANK + cl] = make_float2(a2, a3);
                }
            } else {   // MODE 2
                if (col < 2048) {
                    *(__half2*)&Oh[(size_t)r0 * 2048 + col] = __floats2half2_rn(a0, a1);
                    *(__half2*)&Oh[(size_t)r1 * 2048 + col] = __floats2half2_rn(a2, a3);
                } else {
                    const int cl = col - 2048;
                    *(__half2*)&O2[(size_t)r0 * 2048 + cl] = __floats2half2_rn(a0, a1);
                    *(__half2*)&O2[(size_t)r1 * 2048 + cl] = __floats2half2_rn(a2, a3);
                }
            }
        }
    }
}

// ---------------- RMSNorm over last dim (256) -> fp16 hi/lo ----------------
__global__ __launch_bounds__(256) void rmsnorm_kernel(
    const float* __restrict__ lat, const float* __restrict__ w,
    __half* __restrict__ lh, __half* __restrict__ ll)
{
    const int row = blockIdx.x;
    const int tid = threadIdx.x;
    float v = lat[(size_t)row * KV_RANK + tid];
    float ss = v * v;
#pragma unroll
    for (int o = 16; o; o >>= 1) ss += __shfl_xor_sync(0xffffffffu, ss, o);
    __shared__ float red[8];
    if ((tid & 31) == 0) red[tid >> 5] = ss;
    __syncthreads();
    float tot = red[0] + red[1] + red[2] + red[3] + red[4] + red[5] + red[6] + red[7];
    float r = rsqrtf(tot * (1.0f / KV_RANK) + 1e-6f);
    float nv = w[tid] * v * r;
    __half h = __float2half_rn(nv);
    lh[(size_t)row * KV_RANK + tid] = h;
    ll[(size_t)row * KV_RANK + tid] = __float2half_rn(nv - __half2float(h));
}

// ============ tensor-core flash attention (fp16 2-term, ldmatrix) ==========
#define ATT_SMEM 141312
__global__ __launch_bounds__(256, 1) void attn_mma(
    const __half* __restrict__ Qh, const __half* __restrict__ Ql,
    const __half* __restrict__ Kg, const __half* __restrict__ VT,
    __half* __restrict__ Ohg, __half* __restrict__ Olg)
{
    extern __shared__ char smA[];
    const uint32_t sb = smem_u32(smA);
    const int tid = threadIdx.x;
    const int w = tid >> 5, lane = tid & 31;
    const int qr = lane >> 2, qc = lane & 3;
    // heaviest-first scheduling: high qb = most k-tiles, launch first
    const int qb = (int)gridDim.x - 1 - (int)blockIdx.x;
    const int h = blockIdx.y, b = blockIdx.z;
    const int q0 = qb * 128;

    const uint32_t oQl = 34816, oStage = 69632, stSz = 35840;

    const uint32_t lmK = (uint32_t)(lane & 15) * 272 + (uint32_t)(lane >> 4) * 16;
    const uint32_t lmV = (uint32_t)(lane & 15) * 144 + (uint32_t)(lane >> 4) * 16;
    const uint32_t lmQ = (uint32_t)(w * 16) * 272 + lmK;

    // ---- Q tile load (hi/lo) ----
#pragma unroll
    for (int i = 0; i < 16; ++i) {
        int idx = tid + i * 256;
        int mat = idx >> 11, r = (idx >> 4) & 127, v = idx & 15;
        const __half* g = (mat ? Ql : Qh) +
            (size_t)(b * SEQ + q0 + r) * 2048 + h * HEAD_DIM + v * 8;
        CP_ASYNC16(sb + (mat ? oQl : 0u) + r * 272 + v * 16, g);
    }
    CP_COMMIT();

    auto issue = [&](int kt) {
        const int k0 = kt * 64;
        const uint32_t st = sb + oStage + (kt & 1) * stSz;
#pragma unroll
        for (int i = 0; i < 4; ++i) {
            int idx = tid + i * 256;
            int r = idx >> 4, v = idx & 15;
            const __half* g = Kg + (size_t)(b * SEQ + k0 + r) * 2048 + h * HEAD_DIM + v * 8;
            CP_ASYNC16(st + r * 272 + v * 16, g);
        }
#pragma unroll
        for (int i = 0; i < 4; ++i) {
            int idx = tid + i * 256;
            int d = idx >> 3, v = idx & 7;
            const __half* g = VT + (size_t)((b * HEADS + h) * HEAD_DIM + d) * 2048 + k0 + v * 8;
            CP_ASYNC16(st + 17408 + d * 144 + v * 16, g);
        }
        CP_COMMIT();
    };

    float m0 = -1e30f, m1 = -1e30f, l0 = 0.f, l1 = 0.f;
    float acc[16][4];
#pragma unroll
    for (int nt = 0; nt < 16; ++nt)
#pragma unroll
        for (int e = 0; e < 4; ++e) acc[nt][e] = 0.f;

    const int ntk = 2 * (qb + 1);
    issue(0);

    for (int kt = 0; kt < ntk; ++kt) {
        if (kt + 1 < ntk) { issue(kt + 1); CP_WAIT(1); }
        else              { CP_WAIT(0); }
        __syncthreads();

        const uint32_t st  = sb + oStage + (kt & 1) * stSz;
        const uint32_t aK  = st + lmK;
        const uint32_t aV  = st + 17408 + lmV;
        const uint32_t aQh = sb + lmQ;
        const uint32_t aQl = sb + oQl + lmQ;

        // ---- S = Q K^T (2 terms) ----
        float sfr[8][4];
#pragma unroll
        for (int nt = 0; nt < 8; ++nt)
#pragma unroll
            for (int e = 0; e < 4; ++e) sfr[nt][e] = 0.f;

#pragma unroll
        for (int ks = 0; ks < 8; ++ks) {
            const uint32_t kb = ks * 32;
            uint32_t ah[4], al[4];
            LDSM4(ah[0], ah[1], ah[2], ah[3], aQh + kb);
            LDSM4(al[0], al[1], al[2], al[3], aQl + kb);
#pragma unroll
            for (int np = 0; np < 4; ++np) {
                uint32_t h0, h1, h2, h3;
                LDSM4(h0, h1, h2, h3, aK + (uint32_t)(np * 16) * 272 + kb);
                uint32_t be[2] = { h0, h2 }, bo[2] = { h1, h3 };
                mma16816(sfr[2 * np],     ah, be);
                mma16816(sfr[2 * np],     al, be);
                mma16816(sfr[2 * np + 1], ah, bo);
                mma16816(sfr[2 * np + 1], al, bo);
            }
        }

        // ---- mask + online softmax ----
        const int i0 = q0 + w * 16 + qr;
        const int i1 = i0 + 8;
        const int k0 = kt * 64;
#pragma unroll
        for (int nt = 0; nt < 8; ++nt) {
            const int j = k0 + nt * 8 + 2 * qc;
            if (j     > i0) sfr[nt][0] = -1e30f;
            if (j + 1 > i0) sfr[nt][1] = -1e30f;
            if (j     > i1) sfr[nt][2] = -1e30f;
            if (j + 1 > i1) sfr[nt][3] = -1e30f;
        }
        float mx0 = -1e30f, mx1 = -1e30f;
#pragma unroll
        for (int nt = 0; nt < 8; ++nt) {
            mx0 = fmaxf(mx0, fmaxf(sfr[nt][0], sfr[nt][1]));
            mx1 = fmaxf(mx1, fmaxf(sfr[nt][2], sfr[nt][3]));
        }
        mx0 = fmaxf(mx0, __shfl_xor_sync(0xffffffffu, mx0, 1));
        mx0 = fmaxf(mx0, __shfl_xor_sync(0xffffffffu, mx0, 2));
        mx1 = fmaxf(mx1, __shfl_xor_sync(0xffffffffu, mx1, 1));
        mx1 = fmaxf(mx1, __shfl_xor_sync(0xffffffffu, mx1, 2));
        const float mn0 = fmaxf(m0, mx0), mn1 = fmaxf(m1, mx1);
        const float c0 = __expf(m0 - mn0), c1 = __expf(m1 - mn1);
        m0 = mn0; m1 = mn1;
        l0 *= c0;  l1 *= c1;

        uint32_t pa[4][4], pl[4][4];
        float rs0 = 0.f, rs1 = 0.f;
#pragma unroll
        for (int nt = 0; nt < 8; ++nt) {
            float p0 = __expf(sfr[nt][0] - mn0);
            float p1 = __expf(sfr[nt][1] - mn0);
            float p2 = __expf(sfr[nt][2] - mn1);
            float p3 = __expf(sfr[nt][3] - mn1);
            rs0 += p0 + p1; rs1 += p2 + p3;
            uint32_t h01 = pack_hf2(p0, p1);
            uint32_t h23 = pack_hf2(p2, p3);
            __half2 hb01 = *(__half2*)&h01;
            __half2 hb23 = *(__half2*)&h23;
            uint32_t r01 = pack_hf2(p0 - __half2float(__low2half(hb01)),
                                    p1 - __half2float(__high2half(hb01)));
            uint32_t r23 = pack_hf2(p2 - __half2float(__low2half(hb23)),
                                    p3 - __half2float(__high2half(hb23)));
            const int ks = nt >> 1, half = nt & 1;
            if (half == 0) { pa[ks][0] = h01; pa[ks][1] = h23; pl[ks][0] = r01; pl[ks][1] = r23; }
            else           { pa[ks][2] = h01; pa[ks][3] = h23; pl[ks][2] = r01; pl[ks][3] = r23; }
        }
        rs0 += __shfl_xor_sync(0xffffffffu, rs0, 1);
        rs0 += __shfl_xor_sync(0xffffffffu, rs0, 2);
        rs1 += __shfl_xor_sync(0xffffffffu, rs1, 1);
        rs1 += __shfl_xor_sync(0xffffffffu, rs1, 2);
        l0 += rs0; l1 += rs1;

#pragma unroll
        for (int nt = 0; nt < 16; ++nt) {
            acc[nt][0] *= c0; acc[nt][1] *= c0;
            acc[nt][2] *= c1; acc[nt][3] *= c1;
        }

        // ---- O += P V (2 terms) ----
#pragma unroll
        for (int ks = 0; ks < 4; ++ks) {
            const uint32_t kb = ks * 32;
#pragma unroll
            for (int dp = 0; dp < 8; ++dp) {
                uint32_t h0, h1, h2, h3;
                LDSM4(h0, h1, h2, h3, aV + (uint32_t)(dp * 16) * 144 + kb);
                uint32_t be[2] = { h0, h2 }, bo[2] = { h1, h3 };
                mma16816(acc[2 * dp],     pa[ks], be);
                mma16816(acc[2 * dp],     pl[ks], be);
                mma16816(acc[2 * dp + 1], pa[ks], bo);
                mma16816(acc[2 * dp + 1], pl[ks], bo);
            }
        }
        __syncthreads();
    }

    // ---- epilogue: write fp16 hi/lo directly ----
    const float inv0 = 1.0f / l0, inv1 = 1.0f / l1;
    const size_t r0 = (size_t)(b * SEQ + q0 + w * 16 + qr);
    const size_t r1 = r0 + 8;
#pragma unroll
    for (int nt = 0; nt < 16; ++nt) {
        const int col = h * HEAD_DIM + nt * 8 + 2 * qc;
        __half2 hh, ll;
        split2(acc[nt][0] * inv0, acc[nt][1] * inv0, hh, ll);
        *(__half2*)&Ohg[r0 * 2048 + col] = hh;
        *(__half2*)&Olg[r0 * 2048 + col] = ll;
        split2(acc[nt][2] * inv1, acc[nt][3] * inv1, hh, ll);
        *(__half2*)&Ohg[r1 * 2048 + col] = hh;
        *(__half2*)&Olg[r1 * 2048 + col] = ll;
    }
}

// ---------------------------------------------------------------------------
extern "C" void kernel_launch(void* const* d_in, const int* in_sizes, int n_in,
                              void* d_out, int out_size)
{
    const float* x    = (const float*)d_in[0];
    const float* Wq   = (const float*)d_in[1];
    const float* Wkvd = (const float*)d_in[2];
    const float* knw  = (const float*)d_in[3];
    const float* Wkvu = (const float*)d_in[4];
    const float* Wo   = (const float*)d_in[5];
    float* out = (float*)d_out;

    float* lat;
    cudaGetSymbolAddress((void**)&lat, g_lat);
    __half *xh,*xl,*lath,*latl,*aoh,*aol,*qh,*ql,*k1,*vrm,*vt;
    __half *WT1,*WkuT,*WoT;
    cudaGetSymbolAddress((void**)&xh, g_xh);     cudaGetSymbolAddress((void**)&xl, g_xl);
    cudaGetSymbolAddress((void**)&lath, g_lath); cudaGetSymbolAddress((void**)&latl, g_latl);
    cudaGetSymbolAddress((void**)&aoh, g_aoh);   cudaGetSymbolAddress((void**)&aol, g_aol);
    cudaGetSymbolAddress((void**)&qh, g_qh);     cudaGetSymbolAddress((void**)&ql, g_ql);
    cudaGetSymbolAddress((void**)&k1, g_k1);     cudaGetSymbolAddress((void**)&vrm, g_vrm);
    cudaGetSymbolAddress((void**)&vt, g_vt);
    cudaGetSymbolAddress((void**)&WT1, g_WT1);
    cudaGetSymbolAddress((void**)&WkuT, g_WkuT); cudaGetSymbolAddress((void**)&WoT, g_WoT);

    cudaFuncSetAttribute(gemm_mma<1, true>,  cudaFuncAttributeMaxDynamicSharedMemorySize, 61440);
    cudaFuncSetAttribute(gemm_mma<2, true>,  cudaFuncAttributeMaxDynamicSharedMemorySize, 61440);
    cudaFuncSetAttribute(gemm_mma<0, false>, cudaFuncAttributeMaxDynamicSharedMemorySize, 40960);
    cudaFuncSetAttribute(attn_mma, cudaFuncAttributeMaxDynamicSharedMemorySize, ATT_SMEM);

    // weight conversions: WT1 = [WqT rows 0..2047 ; WkdT rows 2048..2303]
    conv_wt_T<<<dim3(ATTN_DIM / 128, HIDDEN / 32), 256>>>(Wq, WT1, HIDDEN, ATTN_DIM);
    conv_wt_T<<<dim3(KV_RANK / 128, HIDDEN / 32), 256>>>(
        Wkvd, WT1 + (size_t)ATTN_DIM * HIDDEN, HIDDEN, KV_RANK);
    conv_wt_T<<<dim3(2 * ATTN_DIM / 128, KV_RANK / 32), 256>>>(Wkvu, WkuT, KV_RANK, 2 * ATTN_DIM);
    conv_wt_T<<<dim3(HIDDEN / 128, ATTN_DIM / 32), 256>>>(Wo, WoT, ATTN_DIM, HIDDEN);

    // x -> fp16 hi/lo
    {
        int n4 = M_ROWS * HIDDEN / 4;
        conv_act<<<(n4 + 255) / 256, 256>>>((const float4*)x, xh, xl, n4);
    }

    // fused q+lat GEMM: N=2304; q cols -> qh/ql (scaled), lat cols -> fp32
    gemm_mma<1, true><<<dim3((ATTN_DIM + KV_RANK) / 128, M_ROWS / 128), 256, 61440>>>(
        xh, xl, WT1, lat, qh, ql, nullptr,
        M_ROWS, ATTN_DIM + KV_RANK, HIDDEN, 0.08838834764831845f);

    // rmsnorm -> fp16 hi/lo directly
    rmsnorm_kernel<<<M_ROWS, KV_RANK>>>(lat, knw, lath, latl);

    // kv GEMM: K half -> k1 fp16, V half -> vrm fp16 (row-major)
    gemm_mma<2, true><<<dim3(2 * ATTN_DIM / 128, M_ROWS / 128), 256, 61440>>>(
        lath, latl, WkuT, nullptr, k1, nullptr, vrm,
        M_ROWS, 2 * ATTN_DIM, KV_RANK, 1.0f);

    // V transpose (fp16 -> fp16)
    conv_vt_h<<<dim3(SEQ / 32, (HEADS * HEAD_DIM) / 32, BATCH), 256>>>(vrm, vt);

    // tensor-core attention -> aoh/aol fp16 hi/lo directly (heaviest-first)
    attn_mma<<<dim3(SEQ / 128, HEADS, BATCH), 256, ATT_SMEM>>>(
        qh, ql, k1, vt, aoh, aol);

    // out = ao @ Wo (fp32 out, single-A term)
    gemm_mma<0, false><<<dim3(HIDDEN / 128, M_ROWS / 128), 256, 40960>>>(
        aoh, nullptr, WoT, out, nullptr, nullptr, nullptr,
        M_ROWS, HIDDEN, ATTN_DIM, 1.0f);
}

// round 14
// speedup vs baseline: 5.5136x; 1.0307x over previous
#include <cuda_runtime.h>
#include <cuda_fp16.h>
#include <cstdint>
#include <math.h>

#define HIDDEN   2048
#define HEADS    16
#define HEAD_DIM 128
#define KV_RANK  256
#define ATTN_DIM 2048
#define BATCH    2
#define SEQ      2048
#define M_ROWS   (BATCH * SEQ)   // 4096

// ---------------- scratch (device globals; allocation-free) ----------------
__device__ float g_lat[M_ROWS * KV_RANK];

__device__ __half g_xh [M_ROWS * HIDDEN],   g_xl [M_ROWS * HIDDEN];
__device__ __half g_lath[M_ROWS * KV_RANK], g_latl[M_ROWS * KV_RANK];
__device__ __half g_aoh[M_ROWS * ATTN_DIM], g_aol[M_ROWS * ATTN_DIM];
__device__ __half g_qh [M_ROWS * ATTN_DIM], g_ql [M_ROWS * ATTN_DIM];
__device__ __half g_k1 [M_ROWS * ATTN_DIM];
__device__ __half g_vrm[M_ROWS * ATTN_DIM];                  // V row-major fp16
__device__ __half g_vt [BATCH * HEADS * HEAD_DIM * SEQ];     // V transposed
// weights transposed to [N,K] K-major, single fp16
__device__ __half g_WT1 [(ATTN_DIM + KV_RANK) * HIDDEN];     // [Wq ; Wkv_down] rows
__device__ __half g_WkuT[2 * ATTN_DIM * KV_RANK];
__device__ __half g_WoT [HIDDEN * ATTN_DIM];

// ======================= PTX helpers (baseline ISA) ========================
__device__ __forceinline__ uint32_t smem_u32(const void* p) {
    uint32_t a;
    asm("{ .reg .u64 t; cvta.to.shared.u64 t, %1; cvt.u32.u64 %0, t; }" : "=r"(a) : "l"(p));
    return a;
}
#define CP_ASYNC16(dst, src) \
    asm volatile("cp.async.cg.shared.global [%0], [%1], 16;" :: "r"(dst), "l"(src) : "memory")
#define CP_COMMIT() asm volatile("cp.async.commit_group;" ::: "memory")
#define CP_WAIT(n)  asm volatile("cp.async.wait_group %0;" :: "n"(n) : "memory")

#define LDSM4(r0, r1, r2, r3, a) \
    asm volatile("ldmatrix.sync.aligned.m8n8.x4.shared.b16 {%0,%1,%2,%3}, [%4];" \
        : "=r"(r0), "=r"(r1), "=r"(r2), "=r"(r3) : "r"(a))

__device__ __forceinline__ void mma16816(float* c, const uint32_t* a, const uint32_t* b) {
    asm volatile("mma.sync.aligned.m16n8k16.row.col.f32.f16.f16.f32 "
        "{%0,%1,%2,%3}, {%4,%5,%6,%7}, {%8,%9}, {%0,%1,%2,%3};"
        : "+f"(c[0]), "+f"(c[1]), "+f"(c[2]), "+f"(c[3])
        : "r"(a[0]), "r"(a[1]), "r"(a[2]), "r"(a[3]), "r"(b[0]), "r"(b[1]));
}
__device__ __forceinline__ uint32_t pack_hf2(float a, float b) {
    __half2 t = __floats2half2_rn(a, b);
    return *(uint32_t*)&t;
}
__device__ __forceinline__ void split2(float a, float b, __half2& h, __half2& l) {
    __half ha = __float2half_rn(a), hb = __float2half_rn(b);
    h = __halves2half2(ha, hb);
    l = __floats2half2_rn(a - __half2float(ha), b - __half2float(hb));
}

// ======================= conversion kernels ================================
__global__ __launch_bounds__(256) void conv_act(const float4* __restrict__ in,
                                                __half* __restrict__ h,
                                                __half* __restrict__ l, int n4)
{
    int i = blockIdx.x * blockDim.x + threadIdx.x;
    if (i >= n4) return;
    float4 x = in[i];
    __half2 h0, l0, h1, l1;
    split2(x.x, x.y, h0, l0);
    split2(x.z, x.w, h1, l1);
    ((__half2*)h)[i * 2 + 0] = h0;
    ((__half2*)h)[i * 2 + 1] = h1;
    ((__half2*)l)[i * 2 + 0] = l0;
    ((__half2*)l)[i * 2 + 1] = l1;
}

// fp16 V row-major -> transposed: VT[(b*2048 + hd) * 2048 + s]
__global__ __launch_bounds__(256) void conv_vt_h(const __half* __restrict__ V,
                                                 __half* __restrict__ T)
{
    __shared__ __half t[32][40];
    const int s0  = blockIdx.x * 32;
    const int hd0 = blockIdx.y * 32;
    const int b   = blockIdx.z;
    const int tid = threadIdx.x;
    for (int i = tid; i < 1024; i += 256) {
        int ss = i >> 5, dd = i & 31;
        t[ss][dd] = V[(size_t)(b * SEQ + s0 + ss) * 2048 + hd0 + dd];
    }
    __syncthreads();
    for (int i = tid; i < 512; i += 256) {
        int dd = i >> 4, sp = (i & 15) * 2;
        size_t o = (size_t)(b * 2048 + hd0 + dd) * 2048 + s0 + sp;
        *(__half2*)&T[o] = __halves2half2(t[sp][dd], t[sp + 1][dd]);
    }
}

// W [K,N] fp32 -> T [N,K] single fp16 (K-major). 32k x 128n tiles, vectorized.
__global__ __launch_bounds__(256) void conv_wt_T(const float* __restrict__ W,
                                                 __half* __restrict__ Th,
                                                 int K, int N)
{
    __shared__ float t[32][129];
    const int n0 = blockIdx.x * 128, k0 = blockIdx.y * 32;
    const int tid = threadIdx.x;
#pragma unroll
    for (int i = 0; i < 4; ++i) {
        int idx = tid + i * 256;
        int r = idx >> 5, c4 = (idx & 31) * 4;
        float4 v = *(const float4*)&W[(size_t)(k0 + r) * N + n0 + c4];
        t[r][c4 + 0] = v.x; t[r][c4 + 1] = v.y;
        t[r][c4 + 2] = v.z; t[r][c4 + 3] = v.w;
    }
    __syncthreads();
#pragma unroll
    for (int i = 0; i < 2; ++i) {
        int idx = tid + i * 256;
        int n = idx >> 2, kh = (idx & 3) * 8;
        uint4 u;
        uint32_t* up = (uint32_t*)&u;
#pragma unroll
        for (int j = 0; j < 4; ++j) {
            __half2 o = __floats2half2_rn(t[kh + 2 * j][n], t[kh + 2 * j + 1][n]);
            up[j] = *(uint32_t*)&o;
        }
        *(uint4*)&Th[(size_t)(n0 + n) * K + k0 + kh] = u;
    }
}

// ======================= mma.sync fp16 GEMM (ldmatrix) =====================
template<int MODE, bool SPLITA>
__global__ __launch_bounds__(256, 2) void gemm_mma(
    const __half* __restrict__ Ah, const __half* __restrict__ Al,
    const __half* __restrict__ Bw,
    float* __restrict__ Cf, __half* __restrict__ Oh, __half* __restrict__ Ol,
    __half* __restrict__ O2,
    int M, int N, int K, float sc)
{
    constexpr int NMAT = SPLITA ? 3 : 2;
    constexpr uint32_t STAGE = NMAT * 10240;

    extern __shared__ char smem[];
    const uint32_t sbase = smem_u32(smem);
    const int tid  = threadIdx.x;
    const int lane = tid & 31;
    const int w    = tid >> 5;
    const int bm = blockIdx.y * 128;
    const int bn = blockIdx.x * 128;
    const int wm = (w & 3) * 32;
    const int wn = (w >> 2) * 64;
    const int qr = lane >> 2;
    const int qc = lane & 3;

    const __half* srcs[3] = { Ah, SPLITA ? Al : Bw, Bw };
    const int rowoff[3] = { bm, SPLITA ? bm : bn, bn };

    const uint32_t lm = (uint32_t)(lane & 15) * 80 + (uint32_t)(lane >> 4) * 16;

    float acc[2][8][4];
#pragma unroll
    for (int mf = 0; mf < 2; ++mf)
#pragma unroll
        for (int nf = 0; nf < 8; ++nf)
#pragma unroll
            for (int e = 0; e < 4; ++e) acc[mf][nf][e] = 0.f;

    const int NC = K >> 5;

    auto issue = [&](int c) {
        const uint32_t st = sbase + (c & 1) * STAGE;
        const int k0 = c << 5;
#pragma unroll
        for (int i = 0; i < 2 * NMAT; ++i) {
            const int mat = i >> 1;
            const int sub = ((i & 1) << 8) + tid;
            const int r = sub >> 2, v = sub & 3;
            const void* g = srcs[mat] + (size_t)(rowoff[mat] + r) * K + k0 + v * 8;
            CP_ASYNC16(st + mat * 10240 + r * 80 + v * 16, g);
        }
        CP_COMMIT();
    };

    issue(0);

    for (int c = 0; c < NC; ++c) {
        if (c + 1 < NC) { issue(c + 1); CP_WAIT(1); }
        else            { CP_WAIT(0); }
        __syncthreads();

        const uint32_t st = sbase + (c & 1) * STAGE;
        const uint32_t aAh = st + wm * 80 + lm;
        const uint32_t aAl = st + 10240 + wm * 80 + lm;
        const uint32_t aB  = st + (NMAT - 1) * 10240 + wn * 80 + lm;

#pragma unroll
        for (int ks = 0; ks < 2; ++ks) {
            const uint32_t kb = ks * 32;
            uint32_t ah[2][4], al[2][4];
            LDSM4(ah[0][0], ah[0][1], ah[0][2], ah[0][3], aAh + kb);
            LDSM4(ah[1][0], ah[1][1], ah[1][2], ah[1][3], aAh + 16 * 80 + kb);
            if (SPLITA) {
                LDSM4(al[0][0], al[0][1], al[0][2], al[0][3], aAl + kb);
                LDSM4(al[1][0], al[1][1], al[1][2], al[1][3], aAl + 16 * 80 + kb);
            }
#pragma unroll
            for (int np = 0; np < 4; ++np) {
                uint32_t h0, h1, h2, h3;
                LDSM4(h0, h1, h2, h3, aB + (uint32_t)(np * 16) * 80 + kb);
                uint32_t be[2] = { h0, h2 }, bo[2] = { h1, h3 };
#pragma unroll
                for (int mf = 0; mf < 2; ++mf) {
                    mma16816(acc[mf][2 * np],     ah[mf], be);
                    mma16816(acc[mf][2 * np + 1], ah[mf], bo);
                    if (SPLITA) {
                        mma16816(acc[mf][2 * np],     al[mf], be);
                        mma16816(acc[mf][2 * np + 1], al[mf], bo);
                    }
                }
            }
        }
        __syncthreads();
    }

    // ---- epilogue ----
#pragma unroll
    for (int mf = 0; mf < 2; ++mf) {
        const int r0 = bm + wm + mf * 16 + qr;
        const int r1 = r0 + 8;
#pragma unroll
        for (int nf = 0; nf < 8; ++nf) {
            const int col = bn + wn + nf * 8 + qc * 2;
            float a0 = acc[mf][nf][0], a1 = acc[mf][nf][1];
            float a2 = acc[mf][nf][2], a3 = acc[mf][nf][3];
            if (MODE == 0) {
                *(float2*)&Cf[(size_t)r0 * N + col] = make_float2(a0, a1);
                *(float2*)&Cf[(size_t)r1 * N + col] = make_float2(a2, a3);
            } else if (MODE == 1) {
                if (col < 2048) {
                    a0 *= sc; a1 *= sc; a2 *= sc; a3 *= sc;
                    __half2 h, l;
                    split2(a0, a1, h, l);
                    *(__half2*)&Oh[(size_t)r0 * 2048 + col] = h;
                    *(__half2*)&Ol[(size_t)r0 * 2048 + col] = l;
                    split2(a2, a3, h, l);
                    *(__half2*)&Oh[(size_t)r1 * 2048 + col] = h;
                    *(__half2*)&Ol[(size_t)r1 * 2048 + col] = l;
                } else {
                    const int cl = col - 2048;
                    *(float2*)&Cf[(size_t)r0 * KV_RANK + cl] = make_float2(a0, a1);
                    *(float2*)&Cf[(size_t)r1 * KV_RANK + cl] = make_float2(a2, a3);
                }
            } else {   // MODE 2
                if (col < 2048) {
                    *(__half2*)&Oh[(size_t)r0 * 2048 + col] = __floats2half2_rn(a0, a1);
                    *(__half2*)&Oh[(size_t)r1 * 2048 + col] = __floats2half2_rn(a2, a3);
                } else {
                    const int cl = col - 2048;
                    *(__half2*)&O2[(size_t)r0 * 2048 + cl] = __floats2half2_rn(a0, a1);
                    *(__half2*)&O2[(size_t)r1 * 2048 + cl] = __floats2half2_rn(a2, a3);
                }
            }
        }
    }
}

// ---------------- RMSNorm over last dim (256) -> fp16 hi/lo ----------------
__global__ __launch_bounds__(256) void rmsnorm_kernel(
    const float* __restrict__ lat, const float* __restrict__ w,
    __half* __restrict__ lh, __half* __restrict__ ll)
{
    const int row = blockIdx.x;
    const int tid = threadIdx.x;
    float v = lat[(size_t)row * KV_RANK + tid];
    float ss = v * v;
#pragma unroll
    for (int o = 16; o; o >>= 1) ss += __shfl_xor_sync(0xffffffffu, ss, o);
    __shared__ float red[8];
    if ((tid & 31) == 0) red[tid >> 5] = ss;
    __syncthreads();
    float tot = red[0] + red[1] + red[2] + red[3] + red[4] + red[5] + red[6] + red[7];
    float r = rsqrtf(tot * (1.0f / KV_RANK) + 1e-6f);
    float nv = w[tid] * v * r;
    __half h = __float2half_rn(nv);
    lh[(size_t)row * KV_RANK + tid] = h;
    ll[(size_t)row * KV_RANK + tid] = __float2half_rn(nv - __half2float(h));
}

// ============ tensor-core flash attention (Q-tile 64, 2 CTAs/SM) ===========
// 128 threads, 4 warps (warp w: rows w*16..+15). K tile 64.
// smem: Qh@0 Ql@17408 (272B rows, 64 rows), 2 stages @34816/+35840:
//   {K(17408, 272B rows), VT(18432, 144B rows)}.  Total 106496 -> 2 CTAs/SM.
#define ATT_SMEM 106496
__global__ __launch_bounds__(128, 2) void attn_mma(
    const __half* __restrict__ Qh, const __half* __restrict__ Ql,
    const __half* __restrict__ Kg, const __half* __restrict__ VT,
    __half* __restrict__ Ohg, __half* __restrict__ Olg)
{
    extern __shared__ char smA[];
    const uint32_t sb = smem_u32(smA);
    const int tid = threadIdx.x;
    const int w = tid >> 5, lane = tid & 31;
    const int qr = lane >> 2, qc = lane & 3;
    // heaviest-first: high qb = most k-tiles, launch first
    const int qb = (int)gridDim.x - 1 - (int)blockIdx.x;
    const int h = blockIdx.y, b = blockIdx.z;
    const int q0 = qb * 64;

    const uint32_t oQl = 17408, oStage = 34816, stSz = 35840;

    const uint32_t lmK = (uint32_t)(lane & 15) * 272 + (uint32_t)(lane >> 4) * 16;
    const uint32_t lmV = (uint32_t)(lane & 15) * 144 + (uint32_t)(lane >> 4) * 16;
    const uint32_t lmQ = (uint32_t)(w * 16) * 272 + lmK;

    // ---- Q tile load (hi/lo): 64 rows x 16 vecs x 2 mats / 128 thr ----
#pragma unroll
    for (int i = 0; i < 16; ++i) {
        int idx = tid + i * 128;
        int mat = idx >> 10, r = (idx >> 4) & 63, v = idx & 15;
        const __half* g = (mat ? Ql : Qh) +
            (size_t)(b * SEQ + q0 + r) * 2048 + h * HEAD_DIM + v * 8;
        CP_ASYNC16(sb + (mat ? oQl : 0u) + r * 272 + v * 16, g);
    }
    CP_COMMIT();

    auto issue = [&](int kt) {
        const int k0 = kt * 64;
        const uint32_t st = sb + oStage + (kt & 1) * stSz;
#pragma unroll
        for (int i = 0; i < 8; ++i) {
            int idx = tid + i * 128;
            int r = idx >> 4, v = idx & 15;
            const __half* g = Kg + (size_t)(b * SEQ + k0 + r) * 2048 + h * HEAD_DIM + v * 8;
            CP_ASYNC16(st + r * 272 + v * 16, g);
        }
#pragma unroll
        for (int i = 0; i < 8; ++i) {
            int idx = tid + i * 128;
            int d = idx >> 3, v = idx & 7;
            const __half* g = VT + (size_t)((b * HEADS + h) * HEAD_DIM + d) * 2048 + k0 + v * 8;
            CP_ASYNC16(st + 17408 + d * 144 + v * 16, g);
        }
        CP_COMMIT();
    };

    float m0 = -1e30f, m1 = -1e30f, l0 = 0.f, l1 = 0.f;
    float acc[16][4];
#pragma unroll
    for (int nt = 0; nt < 16; ++nt)
#pragma unroll
        for (int e = 0; e < 4; ++e) acc[nt][e] = 0.f;

    const int ntk = qb + 1;
    issue(0);

    for (int kt = 0; kt < ntk; ++kt) {
        if (kt + 1 < ntk) { issue(kt + 1); CP_WAIT(1); }
        else              { CP_WAIT(0); }
        __syncthreads();

        const uint32_t st  = sb + oStage + (kt & 1) * stSz;
        const uint32_t aK  = st + lmK;
        const uint32_t aV  = st + 17408 + lmV;
        const uint32_t aQh = sb + lmQ;
        const uint32_t aQl = sb + oQl + lmQ;

        // ---- S = Q K^T (2 terms) ----
        float sfr[8][4];
#pragma unroll
        for (int nt = 0; nt < 8; ++nt)
#pragma unroll
            for (int e = 0; e < 4; ++e) sfr[nt][e] = 0.f;

#pragma unroll
        for (int ks = 0; ks < 8; ++ks) {
            const uint32_t kb = ks * 32;
            uint32_t ah[4], al[4];
            LDSM4(ah[0], ah[1], ah[2], ah[3], aQh + kb);
            LDSM4(al[0], al[1], al[2], al[3], aQl + kb);
#pragma unroll
            for (int np = 0; np < 4; ++np) {
                uint32_t h0, h1, h2, h3;
                LDSM4(h0, h1, h2, h3, aK + (uint32_t)(np * 16) * 272 + kb);
                uint32_t be[2] = { h0, h2 }, bo[2] = { h1, h3 };
                mma16816(sfr[2 * np],     ah, be);
                mma16816(sfr[2 * np],     al, be);
                mma16816(sfr[2 * np + 1], ah, bo);
                mma16816(sfr[2 * np + 1], al, bo);
            }
        }

        // ---- mask + online softmax ----
        const int i0 = q0 + w * 16 + qr;
        const int i1 = i0 + 8;
        const int k0 = kt * 64;
#pragma unroll
        for (int nt = 0; nt < 8; ++nt) {
            const int j = k0 + nt * 8 + 2 * qc;
            if (j     > i0) sfr[nt][0] = -1e30f;
            if (j + 1 > i0) sfr[nt][1] = -1e30f;
            if (j     > i1) sfr[nt][2] = -1e30f;
            if (j + 1 > i1) sfr[nt][3] = -1e30f;
        }
        float mx0 = -1e30f, mx1 = -1e30f;
#pragma unroll
        for (int nt = 0; nt < 8; ++nt) {
            mx0 = fmaxf(mx0, fmaxf(sfr[nt][0], sfr[nt][1]));
            mx1 = fmaxf(mx1, fmaxf(sfr[nt][2], sfr[nt][3]));
        }
        mx0 = fmaxf(mx0, __shfl_xor_sync(0xffffffffu, mx0, 1));
        mx0 = fmaxf(mx0, __shfl_xor_sync(0xffffffffu, mx0, 2));
        mx1 = fmaxf(mx1, __shfl_xor_sync(0xffffffffu, mx1, 1));
        mx1 = fmaxf(mx1, __shfl_xor_sync(0xffffffffu, mx1, 2));
        const float mn0 = fmaxf(m0, mx0), mn1 = fmaxf(m1, mx1);
        const float c0 = __expf(m0 - mn0), c1 = __expf(m1 - mn1);
        m0 = mn0; m1 = mn1;
        l0 *= c0;  l1 *= c1;

        uint32_t pa[4][4], pl[4][4];
        float rs0 = 0.f, rs1 = 0.f;
#pragma unroll
        for (int nt = 0; nt < 8; ++nt) {
            float p0 = __expf(sfr[nt][0] - mn0);
            float p1 = __expf(sfr[nt][1] - mn0);
            float p2 = __expf(sfr[nt][2] - mn1);
            float p3 = __expf(sfr[nt][3] - mn1);
            rs0 += p0 + p1; rs1 += p2 + p3;
            uint32_t h01 = pack_hf2(p0, p1);
            uint32_t h23 = pack_hf2(p2, p3);
            __half2 hb01 = *(__half2*)&h01;
            __half2 hb23 = *(__half2*)&h23;
            uint32_t r01 = pack_hf2(p0 - __half2float(__low2half(hb01)),
                                    p1 - __half2float(__high2half(hb01)));
            uint32_t r23 = pack_hf2(p2 - __half2float(__low2half(hb23)),
                                    p3 - __half2float(__high2half(hb23)));
            const int ks = nt >> 1, half = nt & 1;
            if (half == 0) { pa[ks][0] = h01; pa[ks][1] = h23; pl[ks][0] = r01; pl[ks][1] = r23; }
            else           { pa[ks][2] = h01; pa[ks][3] = h23; pl[ks][2] = r01; pl[ks][3] = r23; }
        }
        rs0 += __shfl_xor_sync(0xffffffffu, rs0, 1);
        rs0 += __shfl_xor_sync(0xffffffffu, rs0, 2);
        rs1 += __shfl_xor_sync(0xffffffffu, rs1, 1);
        rs1 += __shfl_xor_sync(0xffffffffu, rs1, 2);
        l0 += rs0; l1 += rs1;

#pragma unroll
        for (int nt = 0; nt < 16; ++nt) {
            acc[nt][0] *= c0; acc[nt][1] *= c0;
            acc[nt][2] *= c1; acc[nt][3] *= c1;
        }

        // ---- O += P V (2 terms) ----
#pragma unroll
        for (int ks = 0; ks < 4; ++ks) {
            const uint32_t kb = ks * 32;
#pragma unroll
            for (int dp = 0; dp < 8; ++dp) {
                uint32_t h0, h1, h2, h3;
                LDSM4(h0, h1, h2, h3, aV + (uint32_t)(dp * 16) * 144 + kb);
                uint32_t be[2] = { h0, h2 }, bo[2] = { h1, h3 };
                mma16816(acc[2 * dp],     pa[ks], be);
                mma16816(acc[2 * dp],     pl[ks], be);
                mma16816(acc[2 * dp + 1], pa[ks], bo);
                mma16816(acc[2 * dp + 1], pl[ks], bo);
            }
        }
        __syncthreads();
    }

    // ---- epilogue: write fp16 hi/lo directly ----
    const float inv0 = 1.0f / l0, inv1 = 1.0f / l1;
    const size_t r0 = (size_t)(b * SEQ + q0 + w * 16 + qr);
    const size_t r1 = r0 + 8;
#pragma unroll
    for (int nt = 0; nt < 16; ++nt) {
        const int col = h * HEAD_DIM + nt * 8 + 2 * qc;
        __half2 hh, ll;
        split2(acc[nt][0] * inv0, acc[nt][1] * inv0, hh, ll);
        *(__half2*)&Ohg[r0 * 2048 + col] = hh;
        *(__half2*)&Olg[r0 * 2048 + col] = ll;
        split2(acc[nt][2] * inv1, acc[nt][3] * inv1, hh, ll);
        *(__half2*)&Ohg[r1 * 2048 + col] = hh;
        *(__half2*)&Olg[r1 * 2048 + col] = ll;
    }
}

// ---------------------------------------------------------------------------
extern "C" void kernel_launch(void* const* d_in, const int* in_sizes, int n_in,
                              void* d_out, int out_size)
{
    const float* x    = (const float*)d_in[0];
    const float* Wq   = (const float*)d_in[1];
    const float* Wkvd = (const float*)d_in[2];
    const float* knw  = (const float*)d_in[3];
    const float* Wkvu = (const float*)d_in[4];
    const float* Wo   = (const float*)d_in[5];
    float* out = (float*)d_out;

    float* lat;
    cudaGetSymbolAddress((void**)&lat, g_lat);
    __half *xh,*xl,*lath,*latl,*aoh,*aol,*qh,*ql,*k1,*vrm,*vt;
    __half *WT1,*WkuT,*WoT;
    cudaGetSymbolAddress((void**)&xh, g_xh);     cudaGetSymbolAddress((void**)&xl, g_xl);
    cudaGetSymbolAddress((void**)&lath, g_lath); cudaGetSymbolAddress((void**)&latl, g_latl);
    cudaGetSymbolAddress((void**)&aoh, g_aoh);   cudaGetSymbolAddress((void**)&aol, g_aol);
    cudaGetSymbolAddress((void**)&qh, g_qh);     cudaGetSymbolAddress((void**)&ql, g_ql);
    cudaGetSymbolAddress((void**)&k1, g_k1);     cudaGetSymbolAddress((void**)&vrm, g_vrm);
    cudaGetSymbolAddress((void**)&vt, g_vt);
    cudaGetSymbolAddress((void**)&WT1, g_WT1);
    cudaGetSymbolAddress((void**)&WkuT, g_WkuT); cudaGetSymbolAddress((void**)&WoT, g_WoT);

    cudaFuncSetAttribute(gemm_mma<1, true>,  cudaFuncAttributeMaxDynamicSharedMemorySize, 61440);
    cudaFuncSetAttribute(gemm_mma<2, true>,  cudaFuncAttributeMaxDynamicSharedMemorySize, 61440);
    cudaFuncSetAttribute(gemm_mma<0, false>, cudaFuncAttributeMaxDynamicSharedMemorySize, 40960);
    cudaFuncSetAttribute(attn_mma, cudaFuncAttributeMaxDynamicSharedMemorySize, ATT_SMEM);

    // weight conversions: WT1 = [WqT rows 0..2047 ; WkdT rows 2048..2303]
    conv_wt_T<<<dim3(ATTN_DIM / 128, HIDDEN / 32), 256>>>(Wq, WT1, HIDDEN, ATTN_DIM);
    conv_wt_T<<<dim3(KV_RANK / 128, HIDDEN / 32), 256>>>(
        Wkvd, WT1 + (size_t)ATTN_DIM * HIDDEN, HIDDEN, KV_RANK);
    conv_wt_T<<<dim3(2 * ATTN_DIM / 128, KV_RANK / 32), 256>>>(Wkvu, WkuT, KV_RANK, 2 * ATTN_DIM);
    conv_wt_T<<<dim3(HIDDEN / 128, ATTN_DIM / 32), 256>>>(Wo, WoT, ATTN_DIM, HIDDEN);

    // x -> fp16 hi/lo
    {
        int n4 = M_ROWS * HIDDEN / 4;
        conv_act<<<(n4 + 255) / 256, 256>>>((const float4*)x, xh, xl, n4);
    }

    // fused q+lat GEMM: N=2304; q cols -> qh/ql (scaled), lat cols -> fp32
    gemm_mma<1, true><<<dim3((ATTN_DIM + KV_RANK) / 128, M_ROWS / 128), 256, 61440>>>(
        xh, xl, WT1, lat, qh, ql, nullptr,
        M_ROWS, ATTN_DIM + KV_RANK, HIDDEN, 0.08838834764831845f);

    // rmsnorm -> fp16 hi/lo directly
    rmsnorm_kernel<<<M_ROWS, KV_RANK>>>(lat, knw, lath, latl);

    // kv GEMM: K half -> k1 fp16, V half -> vrm fp16 (row-major)
    gemm_mma<2, true><<<dim3(2 * ATTN_DIM / 128, M_ROWS / 128), 256, 61440>>>(
        lath, latl, WkuT, nullptr, k1, nullptr, vrm,
        M_ROWS, 2 * ATTN_DIM, KV_RANK, 1.0f);

    // V transpose (fp16 -> fp16)
    conv_vt_h<<<dim3(SEQ / 32, (HEADS * HEAD_DIM) / 32, BATCH), 256>>>(vrm, vt);

    // tensor-core attention (Q tile 64, 2 CTAs/SM, heaviest-first)
    attn_mma<<<dim3(SEQ / 64, HEADS, BATCH), 128, ATT_SMEM>>>(
        qh, ql, k1, vt, aoh, aol);

    // out = ao @ Wo (fp32 out, single-A term)
    gemm_mma<0, false><<<dim3(HIDDEN / 128, M_ROWS / 128), 256, 40960>>>(
        aoh, nullptr, WoT, out, nullptr, nullptr, nullptr,
        M_ROWS, HIDDEN, ATTN_DIM, 1.0f);
}

// round 16
// speedup vs baseline: 6.6763x; 1.2109x over previous
#include <cuda_runtime.h>
#include <cuda_fp16.h>
#include <cstdint>
#include <math.h>

#define HIDDEN   2048
#define HEADS    16
#define HEAD_DIM 128
#define KV_RANK  256
#define ATTN_DIM 2048
#define BATCH    2
#define SEQ      2048
#define M_ROWS   (BATCH * SEQ)   // 4096

// ---------------- scratch (device globals; allocation-free) ----------------
__device__ float g_lat[M_ROWS * KV_RANK];

__device__ __half g_xh [M_ROWS * HIDDEN];
__device__ __half g_lath[M_ROWS * KV_RANK];
__device__ __half g_aoh[M_ROWS * ATTN_DIM];
__device__ __half g_qh [M_ROWS * ATTN_DIM], g_ql [M_ROWS * ATTN_DIM];
__device__ __half g_k1 [M_ROWS * ATTN_DIM];
__device__ __half g_vrm[M_ROWS * ATTN_DIM];                  // V row-major fp16
__device__ __half g_vt [BATCH * HEADS * HEAD_DIM * SEQ];     // V transposed
// weights transposed to [N,K] K-major, single fp16
__device__ __half g_WT1 [(ATTN_DIM + KV_RANK) * HIDDEN];     // [Wq ; Wkv_down] rows
__device__ __half g_WkuT[2 * ATTN_DIM * KV_RANK];
__device__ __half g_WoT [HIDDEN * ATTN_DIM];

// ======================= PTX helpers (baseline ISA) ========================
__device__ __forceinline__ uint32_t smem_u32(const void* p) {
    uint32_t a;
    asm("{ .reg .u64 t; cvta.to.shared.u64 t, %1; cvt.u32.u64 %0, t; }" : "=r"(a) : "l"(p));
    return a;
}
#define CP_ASYNC16(dst, src) \
    asm volatile("cp.async.cg.shared.global [%0], [%1], 16;" :: "r"(dst), "l"(src) : "memory")
#define CP_COMMIT() asm volatile("cp.async.commit_group;" ::: "memory")
#define CP_WAIT(n)  asm volatile("cp.async.wait_group %0;" :: "n"(n) : "memory")

#define LDSM4(r0, r1, r2, r3, a) \
    asm volatile("ldmatrix.sync.aligned.m8n8.x4.shared.b16 {%0,%1,%2,%3}, [%4];" \
        : "=r"(r0), "=r"(r1), "=r"(r2), "=r"(r3) : "r"(a))

__device__ __forceinline__ void mma16816(float* c, const uint32_t* a, const uint32_t* b) {
    asm volatile("mma.sync.aligned.m16n8k16.row.col.f32.f16.f16.f32 "
        "{%0,%1,%2,%3}, {%4,%5,%6,%7}, {%8,%9}, {%0,%1,%2,%3};"
        : "+f"(c[0]), "+f"(c[1]), "+f"(c[2]), "+f"(c[3])
        : "r"(a[0]), "r"(a[1]), "r"(a[2]), "r"(a[3]), "r"(b[0]), "r"(b[1]));
}
__device__ __forceinline__ uint32_t pack_hf2(float a, float b) {
    __half2 t = __floats2half2_rn(a, b);
    return *(uint32_t*)&t;
}
__device__ __forceinline__ void split2(float a, float b, __half2& h, __half2& l) {
    __half ha = __float2half_rn(a), hb = __float2half_rn(b);
    h = __halves2half2(ha, hb);
    l = __floats2half2_rn(a - __half2float(ha), b - __half2float(hb));
}

// ======================= conversion kernels ================================
// fp32 -> fp16 single
__global__ __launch_bounds__(256) void conv_h(const float4* __restrict__ in,
                                              __half* __restrict__ h, int n4)
{
    int i = blockIdx.x * blockDim.x + threadIdx.x;
    if (i >= n4) return;
    float4 x = in[i];
    ((__half2*)h)[i * 2 + 0] = __floats2half2_rn(x.x, x.y);
    ((__half2*)h)[i * 2 + 1] = __floats2half2_rn(x.z, x.w);
}

// fp16 V row-major -> transposed: VT[(b*2048 + hd) * 2048 + s]
__global__ __launch_bounds__(256) void conv_vt_h(const __half* __restrict__ V,
                                                 __half* __restrict__ T)
{
    __shared__ __half t[32][40];
    const int s0  = blockIdx.x * 32;
    const int hd0 = blockIdx.y * 32;
    const int b   = blockIdx.z;
    const int tid = threadIdx.x;
    for (int i = tid; i < 1024; i += 256) {
        int ss = i >> 5, dd = i & 31;
        t[ss][dd] = V[(size_t)(b * SEQ + s0 + ss) * 2048 + hd0 + dd];
    }
    __syncthreads();
    for (int i = tid; i < 512; i += 256) {
        int dd = i >> 4, sp = (i & 15) * 2;
        size_t o = (size_t)(b * 2048 + hd0 + dd) * 2048 + s0 + sp;
        *(__half2*)&T[o] = __halves2half2(t[sp][dd], t[sp + 1][dd]);
    }
}

// W [K,N] fp32 -> T [N,K] single fp16 (K-major). 32k x 128n tiles, vectorized.
__global__ __launch_bounds__(256) void conv_wt_T(const float* __restrict__ W,
                                                 __half* __restrict__ Th,
                                                 int K, int N)
{
    __shared__ float t[32][129];
    const int n0 = blockIdx.x * 128, k0 = blockIdx.y * 32;
    const int tid = threadIdx.x;
#pragma unroll
    for (int i = 0; i < 4; ++i) {
        int idx = tid + i * 256;
        int r = idx >> 5, c4 = (idx & 31) * 4;
        float4 v = *(const float4*)&W[(size_t)(k0 + r) * N + n0 + c4];
        t[r][c4 + 0] = v.x; t[r][c4 + 1] = v.y;
        t[r][c4 + 2] = v.z; t[r][c4 + 3] = v.w;
    }
    __syncthreads();
#pragma unroll
    for (int i = 0; i < 2; ++i) {
        int idx = tid + i * 256;
        int n = idx >> 2, kh = (idx & 3) * 8;
        uint4 u;
        uint32_t* up = (uint32_t*)&u;
#pragma unroll
        for (int j = 0; j < 4; ++j) {
            __half2 o = __floats2half2_rn(t[kh + 2 * j][n], t[kh + 2 * j + 1][n]);
            up[j] = *(uint32_t*)&o;
        }
        *(uint4*)&Th[(size_t)(n0 + n) * K + k0 + kh] = u;
    }
}

// ======================= mma.sync fp16 GEMM (ldmatrix) =====================
template<int MODE, bool SPLITA>
__global__ __launch_bounds__(256, 2) void gemm_mma(
    const __half* __restrict__ Ah, const __half* __restrict__ Al,
    const __half* __restrict__ Bw,
    float* __restrict__ Cf, __half* __restrict__ Oh, __half* __restrict__ Ol,
    __half* __restrict__ O2,
    int M, int N, int K, float sc)
{
    constexpr int NMAT = SPLITA ? 3 : 2;
    constexpr uint32_t STAGE = NMAT * 10240;

    extern __shared__ char smem[];
    const uint32_t sbase = smem_u32(smem);
    const int tid  = threadIdx.x;
    const int lane = tid & 31;
    const int w    = tid >> 5;
    const int bm = blockIdx.y * 128;
    const int bn = blockIdx.x * 128;
    const int wm = (w & 3) * 32;
    const int wn = (w >> 2) * 64;
    const int qr = lane >> 2;
    const int qc = lane & 3;

    const __half* srcs[3] = { Ah, SPLITA ? Al : Bw, Bw };
    const int rowoff[3] = { bm, SPLITA ? bm : bn, bn };

    const uint32_t lm = (uint32_t)(lane & 15) * 80 + (uint32_t)(lane >> 4) * 16;

    float acc[2][8][4];
#pragma unroll
    for (int mf = 0; mf < 2; ++mf)
#pragma unroll
        for (int nf = 0; nf < 8; ++nf)
#pragma unroll
            for (int e = 0; e < 4; ++e) acc[mf][nf][e] = 0.f;

    const int NC = K >> 5;

    auto issue = [&](int c) {
        const uint32_t st = sbase + (c & 1) * STAGE;
        const int k0 = c << 5;
#pragma unroll
        for (int i = 0; i < 2 * NMAT; ++i) {
            const int mat = i >> 1;
            const int sub = ((i & 1) << 8) + tid;
            const int r = sub >> 2, v = sub & 3;
            const void* g = srcs[mat] + (size_t)(rowoff[mat] + r) * K + k0 + v * 8;
            CP_ASYNC16(st + mat * 10240 + r * 80 + v * 16, g);
        }
        CP_COMMIT();
    };

    issue(0);

    for (int c = 0; c < NC; ++c) {
        if (c + 1 < NC) { issue(c + 1); CP_WAIT(1); }
        else            { CP_WAIT(0); }
        __syncthreads();

        const uint32_t st = sbase + (c & 1) * STAGE;
        const uint32_t aAh = st + wm * 80 + lm;
        const uint32_t aAl = st + 10240 + wm * 80 + lm;
        const uint32_t aB  = st + (NMAT - 1) * 10240 + wn * 80 + lm;

#pragma unroll
        for (int ks = 0; ks < 2; ++ks) {
            const uint32_t kb = ks * 32;
            uint32_t ah[2][4], al[2][4];
            LDSM4(ah[0][0], ah[0][1], ah[0][2], ah[0][3], aAh + kb);
            LDSM4(ah[1][0], ah[1][1], ah[1][2], ah[1][3], aAh + 16 * 80 + kb);
            if (SPLITA) {
                LDSM4(al[0][0], al[0][1], al[0][2], al[0][3], aAl + kb);
                LDSM4(al[1][0], al[1][1], al[1][2], al[1][3], aAl + 16 * 80 + kb);
            }
#pragma unroll
            for (int np = 0; np < 4; ++np) {
                uint32_t h0, h1, h2, h3;
                LDSM4(h0, h1, h2, h3, aB + (uint32_t)(np * 16) * 80 + kb);
                uint32_t be[2] = { h0, h2 }, bo[2] = { h1, h3 };
#pragma unroll
                for (int mf = 0; mf < 2; ++mf) {
                    mma16816(acc[mf][2 * np],     ah[mf], be);
                    mma16816(acc[mf][2 * np + 1], ah[mf], bo);
                    if (SPLITA) {
                        mma16816(acc[mf][2 * np],     al[mf], be);
                        mma16816(acc[mf][2 * np + 1], al[mf], bo);
                    }
                }
            }
        }
        __syncthreads();
    }

    // ---- epilogue ----
#pragma unroll
    for (int mf = 0; mf < 2; ++mf) {
        const int r0 = bm + wm + mf * 16 + qr;
        const int r1 = r0 + 8;
#pragma unroll
        for (int nf = 0; nf < 8; ++nf) {
            const int col = bn + wn + nf * 8 + qc * 2;
            float a0 = acc[mf][nf][0], a1 = acc[mf][nf][1];
            float a2 = acc[mf][nf][2], a3 = acc[mf][nf][3];
            if (MODE == 0) {
                *(float2*)&Cf[(size_t)r0 * N + col] = make_float2(a0, a1);
                *(float2*)&Cf[(size_t)r1 * N + col] = make_float2(a2, a3);
            } else if (MODE == 1) {
                if (col < 2048) {
                    a0 *= sc; a1 *= sc; a2 *= sc; a3 *= sc;
                    __half2 h, l;
                    split2(a0, a1, h, l);
                    *(__half2*)&Oh[(size_t)r0 * 2048 + col] = h;
                    *(__half2*)&Ol[(size_t)r0 * 2048 + col] = l;
                    split2(a2, a3, h, l);
                    *(__half2*)&Oh[(size_t)r1 * 2048 + col] = h;
                    *(__half2*)&Ol[(size_t)r1 * 2048 + col] = l;
                } else {
                    const int cl = col - 2048;
                    *(float2*)&Cf[(size_t)r0 * KV_RANK + cl] = make_float2(a0, a1);
                    *(float2*)&Cf[(size_t)r1 * KV_RANK + cl] = make_float2(a2, a3);
                }
            } else {   // MODE 2
                if (col < 2048) {
                    *(__half2*)&Oh[(size_t)r0 * 2048 + col] = __floats2half2_rn(a0, a1);
                    *(__half2*)&Oh[(size_t)r1 * 2048 + col] = __floats2half2_rn(a2, a3);
                } else {
                    const int cl = col - 2048;
                    *(__half2*)&O2[(size_t)r0 * 2048 + cl] = __floats2half2_rn(a0, a1);
                    *(__half2*)&O2[(size_t)r1 * 2048 + cl] = __floats2half2_rn(a2, a3);
                }
            }
        }
    }
}

// ---------------- RMSNorm over last dim (256) -> fp16 single ---------------
__global__ __launch_bounds__(256) void rmsnorm_kernel(
    const float* __restrict__ lat, const float* __restrict__ w,
    __half* __restrict__ lh)
{
    const int row = blockIdx.x;
    const int tid = threadIdx.x;
    float v = lat[(size_t)row * KV_RANK + tid];
    float ss = v * v;
#pragma unroll
    for (int o = 16; o; o >>= 1) ss += __shfl_xor_sync(0xffffffffu, ss, o);
    __shared__ float red[8];
    if ((tid & 31) == 0) red[tid >> 5] = ss;
    __syncthreads();
    float tot = red[0] + red[1] + red[2] + red[3] + red[4] + red[5] + red[6] + red[7];
    float r = rsqrtf(tot * (1.0f / KV_RANK) + 1e-6f);
    lh[(size_t)row * KV_RANK + tid] = __float2half_rn(w[tid] * v * r);
}

// ============ tensor-core flash attention (Q-tile 64, 2 CTAs/SM) ===========
// 128 threads, 4 warps (warp w: rows w*16..+15). K tile 64.
// smem: Qh@0 Ql@17408 (272B rows, 64 rows), 2 stages @34816/+35840:
//   {K(17408, 272B rows), VT(18432, 144B rows)}.  Total 106496 -> 2 CTAs/SM.
#define ATT_SMEM 106496
__global__ __launch_bounds__(128, 2) void attn_mma(
    const __half* __restrict__ Qh, const __half* __restrict__ Ql,
    const __half* __restrict__ Kg, const __half* __restrict__ VT,
    __half* __restrict__ Ohg)
{
    extern __shared__ char smA[];
    const uint32_t sb = smem_u32(smA);
    const int tid = threadIdx.x;
    const int w = tid >> 5, lane = tid & 31;
    const int qr = lane >> 2, qc = lane & 3;
    // heaviest-first: high qb = most k-tiles, launch first
    const int qb = (int)gridDim.x - 1 - (int)blockIdx.x;
    const int h = blockIdx.y, b = blockIdx.z;
    const int q0 = qb * 64;

    const uint32_t oQl = 17408, oStage = 34816, stSz = 35840;

    const uint32_t lmK = (uint32_t)(lane & 15) * 272 + (uint32_t)(lane >> 4) * 16;
    const uint32_t lmV = (uint32_t)(lane & 15) * 144 + (uint32_t)(lane >> 4) * 16;
    const uint32_t lmQ = (uint32_t)(w * 16) * 272 + lmK;

    // ---- Q tile load (hi/lo): 64 rows x 16 vecs x 2 mats / 128 thr ----
#pragma unroll
    for (int i = 0; i < 16; ++i) {
        int idx = tid + i * 128;
        int mat = idx >> 10, r = (idx >> 4) & 63, v = idx & 15;
        const __half* g = (mat ? Ql : Qh) +
            (size_t)(b * SEQ + q0 + r) * 2048 + h * HEAD_DIM + v * 8;
        CP_ASYNC16(sb + (mat ? oQl : 0u) + r * 272 + v * 16, g);
    }
    CP_COMMIT();

    auto issue = [&](int kt) {
        const int k0 = kt * 64;
        const uint32_t st = sb + oStage + (kt & 1) * stSz;
#pragma unroll
        for (int i = 0; i < 8; ++i) {
            int idx = tid + i * 128;
            int r = idx >> 4, v = idx & 15;
            const __half* g = Kg + (size_t)(b * SEQ + k0 + r) * 2048 + h * HEAD_DIM + v * 8;
            CP_ASYNC16(st + r * 272 + v * 16, g);
        }
#pragma unroll
        for (int i = 0; i < 8; ++i) {
            int idx = tid + i * 128;
            int d = idx >> 3, v = idx & 7;
            const __half* g = VT + (size_t)((b * HEADS + h) * HEAD_DIM + d) * 2048 + k0 + v * 8;
            CP_ASYNC16(st + 17408 + d * 144 + v * 16, g);
        }
        CP_COMMIT();
    };

    float m0 = -1e30f, m1 = -1e30f, l0 = 0.f, l1 = 0.f;
    float acc[16][4];
#pragma unroll
    for (int nt = 0; nt < 16; ++nt)
#pragma unroll
        for (int e = 0; e < 4; ++e) acc[nt][e] = 0.f;

    const int ntk = qb + 1;
    issue(0);

    for (int kt = 0; kt < ntk; ++kt) {
        if (kt + 1 < ntk) { issue(kt + 1); CP_WAIT(1); }
        else              { CP_WAIT(0); }
        __syncthreads();

        const uint32_t st  = sb + oStage + (kt & 1) * stSz;
        const uint32_t aK  = st + lmK;
        const uint32_t aV  = st + 17408 + lmV;
        const uint32_t aQh = sb + lmQ;
        const uint32_t aQl = sb + oQl + lmQ;

        // ---- S = Q K^T (2 terms) ----
        float sfr[8][4];
#pragma unroll
        for (int nt = 0; nt < 8; ++nt)
#pragma unroll
            for (int e = 0; e < 4; ++e) sfr[nt][e] = 0.f;

#pragma unroll
        for (int ks = 0; ks < 8; ++ks) {
            const uint32_t kb = ks * 32;
            uint32_t ah[4], al[4];
            LDSM4(ah[0], ah[1], ah[2], ah[3], aQh + kb);
            LDSM4(al[0], al[1], al[2], al[3], aQl + kb);
#pragma unroll
            for (int np = 0; np < 4; ++np) {
                uint32_t h0, h1, h2, h3;
                LDSM4(h0, h1, h2, h3, aK + (uint32_t)(np * 16) * 272 + kb);
                uint32_t be[2] = { h0, h2 }, bo[2] = { h1, h3 };
                mma16816(sfr[2 * np],     ah, be);
                mma16816(sfr[2 * np],     al, be);
                mma16816(sfr[2 * np + 1], ah, bo);
                mma16816(sfr[2 * np + 1], al, bo);
            }
        }

        // ---- mask + online softmax ----
        const int i0 = q0 + w * 16 + qr;
        const int i1 = i0 + 8;
        const int k0 = kt * 64;
#pragma unroll
        for (int nt = 0; nt < 8; ++nt) {
            const int j = k0 + nt * 8 + 2 * qc;
            if (j     > i0) sfr[nt][0] = -1e30f;
            if (j + 1 > i0) sfr[nt][1] = -1e30f;
            if (j     > i1) sfr[nt][2] = -1e30f;
            if (j + 1 > i1) sfr[nt][3] = -1e30f;
        }
        float mx0 = -1e30f, mx1 = -1e30f;
#pragma unroll
        for (int nt = 0; nt < 8; ++nt) {
            mx0 = fmaxf(mx0, fmaxf(sfr[nt][0], sfr[nt][1]));
            mx1 = fmaxf(mx1, fmaxf(sfr[nt][2], sfr[nt][3]));
        }
        mx0 = fmaxf(mx0, __shfl_xor_sync(0xffffffffu, mx0, 1));
        mx0 = fmaxf(mx0, __shfl_xor_sync(0xffffffffu, mx0, 2));
        mx1 = fmaxf(mx1, __shfl_xor_sync(0xffffffffu, mx1, 1));
        mx1 = fmaxf(mx1, __shfl_xor_sync(0xffffffffu, mx1, 2));
        const float mn0 = fmaxf(m0, mx0), mn1 = fmaxf(m1, mx1);
        const float c0 = __expf(m0 - mn0), c1 = __expf(m1 - mn1);
        m0 = mn0; m1 = mn1;
        l0 *= c0;  l1 *= c1;

        uint32_t pa[4][4], pl[4][4];
        float rs0 = 0.f, rs1 = 0.f;
#pragma unroll
        for (int nt = 0; nt < 8; ++nt) {
            float p0 = __expf(sfr[nt][0] - mn0);
            float p1 = __expf(sfr[nt][1] - mn0);
            float p2 = __expf(sfr[nt][2] - mn1);
            float p3 = __expf(sfr[nt][3] - mn1);
            rs0 += p0 + p1; rs1 += p2 + p3;
            uint32_t h01 = pack_hf2(p0, p1);
            uint32_t h23 = pack_hf2(p2, p3);
            __half2 hb01 = *(__half2*)&h01;
            __half2 hb23 = *(__half2*)&h23;
            uint32_t r01 = pack_hf2(p0 - __half2float(__low2half(hb01)),
                                    p1 - __half2float(__high2half(hb01)));
            uint32_t r23 = pack_hf2(p2 - __half2float(__low2half(hb23)),
                                    p3 - __half2float(__high2half(hb23)));
            const int ks = nt >> 1, half = nt & 1;
            if (half == 0) { pa[ks][0] = h01; pa[ks][1] = h23; pl[ks][0] = r01; pl[ks][1] = r23; }
            else           { pa[ks][2] = h01; pa[ks][3] = h23; pl[ks][2] = r01; pl[ks][3] = r23; }
        }
        rs0 += __shfl_xor_sync(0xffffffffu, rs0, 1);
        rs0 += __shfl_xor_sync(0xffffffffu, rs0, 2);
        rs1 += __shfl_xor_sync(0xffffffffu, rs1, 1);
        rs1 += __shfl_xor_sync(0xffffffffu, rs1, 2);
        l0 += rs0; l1 += rs1;

#pragma unroll
        for (int nt = 0; nt < 16; ++nt) {
            acc[nt][0] *= c0; acc[nt][1] *= c0;
            acc[nt][2] *= c1; acc[nt][3] *= c1;
        }

        // ---- O += P V (2 terms) ----
#pragma unroll
        for (int ks = 0; ks < 4; ++ks) {
            const uint32_t kb = ks * 32;
#pragma unroll
            for (int dp = 0; dp < 8; ++dp) {
                uint32_t h0, h1, h2, h3;
                LDSM4(h0, h1, h2, h3, aV + (uint32_t)(dp * 16) * 144 + kb);
                uint32_t be[2] = { h0, h2 }, bo[2] = { h1, h3 };
                mma16816(acc[2 * dp],     pa[ks], be);
                mma16816(acc[2 * dp],     pl[ks], be);
                mma16816(acc[2 * dp + 1], pa[ks], bo);
                mma16816(acc[2 * dp + 1], pl[ks], bo);
            }
        }
        __syncthreads();
    }

    // ---- epilogue: write fp16 single (consumed by single-A Wo GEMM) ----
    const float inv0 = 1.0f / l0, inv1 = 1.0f / l1;
    const size_t r0 = (size_t)(b * SEQ + q0 + w * 16 + qr);
    const size_t r1 = r0 + 8;
#pragma unroll
    for (int nt = 0; nt < 16; ++nt) {
        const int col = h * HEAD_DIM + nt * 8 + 2 * qc;
        *(__half2*)&Ohg[r0 * 2048 + col] =
            __floats2half2_rn(acc[nt][0] * inv0, acc[nt][1] * inv0);
        *(__half2*)&Ohg[r1 * 2048 + col] =
            __floats2half2_rn(acc[nt][2] * inv1, acc[nt][3] * inv1);
    }
}

// ---------------------------------------------------------------------------
extern "C" void kernel_launch(void* const* d_in, const int* in_sizes, int n_in,
                              void* d_out, int out_size)
{
    const float* x    = (const float*)d_in[0];
    const float* Wq   = (const float*)d_in[1];
    const float* Wkvd = (const float*)d_in[2];
    const float* knw  = (const float*)d_in[3];
    const float* Wkvu = (const float*)d_in[4];
    const float* Wo   = (const float*)d_in[5];
    float* out = (float*)d_out;

    float* lat;
    cudaGetSymbolAddress((void**)&lat, g_lat);
    __half *xh,*lath,*aoh,*qh,*ql,*k1,*vrm,*vt;
    __half *WT1,*WkuT,*WoT;
    cudaGetSymbolAddress((void**)&xh, g_xh);
    cudaGetSymbolAddress((void**)&lath, g_lath);
    cudaGetSymbolAddress((void**)&aoh, g_aoh);
    cudaGetSymbolAddress((void**)&qh, g_qh);     cudaGetSymbolAddress((void**)&ql, g_ql);
    cudaGetSymbolAddress((void**)&k1, g_k1);     cudaGetSymbolAddress((void**)&vrm, g_vrm);
    cudaGetSymbolAddress((void**)&vt, g_vt);
    cudaGetSymbolAddress((void**)&WT1, g_WT1);
    cudaGetSymbolAddress((void**)&WkuT, g_WkuT); cudaGetSymbolAddress((void**)&WoT, g_WoT);

    cudaFuncSetAttribute(gemm_mma<1, false>, cudaFuncAttributeMaxDynamicSharedMemorySize, 40960);
    cudaFuncSetAttribute(gemm_mma<2, false>, cudaFuncAttributeMaxDynamicSharedMemorySize, 40960);
    cudaFuncSetAttribute(gemm_mma<0, false>, cudaFuncAttributeMaxDynamicSharedMemorySize, 40960);
    cudaFuncSetAttribute(attn_mma, cudaFuncAttributeMaxDynamicSharedMemorySize, ATT_SMEM);

    // weight conversions: WT1 = [WqT rows 0..2047 ; WkdT rows 2048..2303]
    conv_wt_T<<<dim3(ATTN_DIM / 128, HIDDEN / 32), 256>>>(Wq, WT1, HIDDEN, ATTN_DIM);
    conv_wt_T<<<dim3(KV_RANK / 128, HIDDEN / 32), 256>>>(
        Wkvd, WT1 + (size_t)ATTN_DIM * HIDDEN, HIDDEN, KV_RANK);
    conv_wt_T<<<dim3(2 * ATTN_DIM / 128, KV_RANK / 32), 256>>>(Wkvu, WkuT, KV_RANK, 2 * ATTN_DIM);
    conv_wt_T<<<dim3(HIDDEN / 128, ATTN_DIM / 32), 256>>>(Wo, WoT, ATTN_DIM, HIDDEN);

    // x -> fp16 single
    {
        int n4 = M_ROWS * HIDDEN / 4;
        conv_h<<<(n4 + 255) / 256, 256>>>((const float4*)x, xh, n4);
    }

    // fused q+lat GEMM (single-A): q cols -> qh/ql (scaled), lat cols -> fp32
    gemm_mma<1, false><<<dim3((ATTN_DIM + KV_RANK) / 128, M_ROWS / 128), 256, 40960>>>(
        xh, nullptr, WT1, lat, qh, ql, nullptr,
        M_ROWS, ATTN_DIM + KV_RANK, HIDDEN, 0.08838834764831845f);

    // rmsnorm -> fp16 single
    rmsnorm_kernel<<<M_ROWS, KV_RANK>>>(lat, knw, lath);

    // kv GEMM (single-A): K half -> k1 fp16, V half -> vrm fp16
    gemm_mma<2, false><<<dim3(2 * ATTN_DIM / 128, M_ROWS / 128), 256, 40960>>>(
        lath, nullptr, WkuT, nullptr, k1, nullptr, vrm,
        M_ROWS, 2 * ATTN_DIM, KV_RANK, 1.0f);

    // V transpose (fp16 -> fp16)
    conv_vt_h<<<dim3(SEQ / 32, (HEADS * HEAD_DIM) / 32, BATCH), 256>>>(vrm, vt);

    // tensor-core attention (Q tile 64, 2 CTAs/SM, heaviest-first)
    attn_mma<<<dim3(SEQ / 64, HEADS, BATCH), 128, ATT_SMEM>>>(
        qh, ql, k1, vt, aoh);

    // out = ao @ Wo (fp32 out, single-A term)
    gemm_mma<0, false><<<dim3(HIDDEN / 128, M_ROWS / 128), 256, 40960>>>(
        aoh, nullptr, WoT, out, nullptr, nullptr, nullptr,
        M_ROWS, HIDDEN, ATTN_DIM, 1.0f);
}